// round 9
// baseline (speedup 1.0000x reference)
#include <cuda_runtime.h>
#include <math.h>
#include <stdint.h>

// ---------------- problem constants ----------------
namespace {
constexpr int BATCH = 2;
constexpr int SEQ   = 1024;
constexpr int DIM   = 768;
constexpr int NH    = 12;
constexpr int HD    = 64;
constexpr int FFD   = 3072;
constexpr int NE    = 4;
constexpr int NTOK  = BATCH * SEQ;     // 2048
constexpr int BHZ   = BATCH * NH;      // 24
constexpr int ROWS_TOT = BHZ * SEQ;    // 24576 attention rows
constexpr float EPSZ  = 1e-5f;
constexpr float EPSLN = 1e-5f;
}

// ---------------- scratch (static device memory) ----------------
__device__ __align__(16) float g_Q[NTOK * DIM];
__device__ __align__(16) float g_K[NTOK * DIM];
__device__ __align__(16) float g_Vt[BHZ * HD * SEQ];          // V^T: [b][h][d][t]
__device__ __align__(16) float g_P[(size_t)BHZ * SEQ * SEQ];  // raw scaled logits
__device__ __align__(16) float g_attn[NTOK * DIM];
__device__ __align__(16) float g_attno[NTOK * DIM];
__device__ __align__(16) float g_x[NTOK * DIM];
__device__ __align__(16) float g_H1[(size_t)NE * NTOK * FFD];
__device__ __align__(16) float g_Y[(size_t)NE * NTOK * DIM];
__device__ float g_rsum[ROWS_TOT];
__device__ float g_rsumsq[ROWS_TOT];
__device__ unsigned g_rmaxe[ROWS_TOT];
__device__ unsigned g_rmine[ROWS_TOT];
__device__ int   g_cnt[NE];
__device__ int   g_list[NE * NTOK];
__device__ int   g_tslot[2 * NTOK];
__device__ float g_tw[2 * NTOK];

// ---------------- primitives ----------------
__device__ __forceinline__ void mma_op(float* d, const uint32_t* a, uint32_t b0, uint32_t b1) {
    asm volatile(
        "mma.sync.aligned.m16n8k8.row.col.f32.tf32.tf32.f32 "
        "{%0,%1,%2,%3},{%4,%5,%6,%7},{%8,%9},{%0,%1,%2,%3};\n"
        : "+f"(d[0]), "+f"(d[1]), "+f"(d[2]), "+f"(d[3])
        : "r"(a[0]), "r"(a[1]), "r"(a[2]), "r"(a[3]), "r"(b0), "r"(b1));
}
__device__ __forceinline__ void cp_async16(float* dst, const float* src, int sz) {
    uint32_t s = (uint32_t)__cvta_generic_to_shared(dst);
    asm volatile("cp.async.cg.shared.global [%0], [%1], 16, %2;\n"
                 :: "r"(s), "l"(src), "r"(sz));
}
// swizzled float index in a (rows x 16f) tile (A operand / NT B operand)
__device__ __forceinline__ int swz(int row, int col) {
    return (row << 4) + (((((col >> 2) ^ ((row >> 1) & 3))) << 2) | (col & 3));
}
// swizzled index in a TN B tile (16 k-rows x 128 n floats)
__device__ __forceinline__ int swzt(int k, int n) {
    return (k << 7) + ((((n >> 2) ^ ((k & 3) << 1)) << 2) | (n & 3));
}
// ordered-uint encode for float atomic max/min
__device__ __forceinline__ unsigned fenc(float f) {
    unsigned u = __float_as_uint(f);
    return (u & 0x80000000u) ? ~u : (u | 0x80000000u);
}
__device__ __forceinline__ float fdec(unsigned u) {
    unsigned b = (u & 0x80000000u) ? (u ^ 0x80000000u) : ~u;
    return __uint_as_float(b);
}

// ---------------- cp.async 3-stage pipelined tf32 MMA core ----------------
// BM=128, BK=16, 256 threads. BN=128: warps 2x4, MT=4. BN=64: warps 4x2, MT=2.
// BT=0: pb1/pb2 per-thread B row pointers ([N,K] K-contig).
// BT=1: pb1 = B + n0 ([K,N] N-contig), stride ldbt.
template<int BN, int BT>
__device__ __forceinline__ void mma_core(
    const float* pa1, int sa1, const float* pa2, int sa2,
    const float* pb1, const float* pb2, int ldbt,
    int K, float* smem, float (&acc)[(BN == 128) ? 4 : 2][4][4])
{
    constexpr int MT  = (BN == 128) ? 4 : 2;
    constexpr int WN  = (BN == 128) ? 4 : 2;
    constexpr int ASZ = 128 * 16;
    constexpr int BSZ = BN * 16;
    constexpr int STG = ASZ + BSZ;
    const int tid = threadIdx.x;
    const int lane = tid & 31, wid = tid >> 5;
    const int wm = wid / WN, wn = wid % WN;
    const int gid = lane >> 2, tig = lane & 3;
    const int crow = tid >> 2, cq = tid & 3;
    const int coff  = (crow << 4) + ((cq ^ ((crow >> 1) & 3)) << 2);
    const int coff2 = ((crow + 64) << 4) + ((cq ^ ((crow >> 1) & 3)) << 2);
    const int q4 = 4 * cq;
    const int kk = tid >> 4, ng = tid & 15;           // BT mode
    const int bco1 = swzt(kk, 4 * ng);
    const int bco2 = swzt(kk, 4 * (ng + 16));

    auto issue = [&](int i) {
        float* As = smem + (i % 3) * STG;
        float* Bs = As + ASZ;
        const int kt = i << 4;
        cp_async16(As + coff,  pa1 + kt + q4, sa1);
        cp_async16(As + coff2, pa2 + kt + q4, sa2);
        if (BT) {
            const float* bp = pb1 + (size_t)(kt + kk) * ldbt;
            cp_async16(Bs + bco1, bp + 4 * ng, 16);
            cp_async16(Bs + bco2, bp + 4 * ng + 64, 16);
        } else {
            cp_async16(Bs + coff,  pb1 + kt + q4, 16);
            if (BN == 128) cp_async16(Bs + coff2, pb2 + kt + q4, 16);
        }
        asm volatile("cp.async.commit_group;\n" ::: "memory");
    };
    auto compute = [&](int s) {
        const float* As = smem + s * STG;
        const float* Bs = As + ASZ;
#pragma unroll
        for (int c = 0; c < 2; c++) {
            const int k0 = c * 8 + tig;
            uint32_t af[MT][4];
#pragma unroll
            for (int mt = 0; mt < MT; mt++) {
                const int ar = wm * (MT * 16) + mt * 16 + gid;
                af[mt][0] = __float_as_uint(As[swz(ar, k0)]);
                af[mt][1] = __float_as_uint(As[swz(ar + 8, k0)]);
                af[mt][2] = __float_as_uint(As[swz(ar, k0 + 4)]);
                af[mt][3] = __float_as_uint(As[swz(ar + 8, k0 + 4)]);
            }
#pragma unroll
            for (int nt = 0; nt < 4; nt++) {
                const int br = wn * 32 + nt * 8 + gid;
                uint32_t b0, b1;
                if (BT) {
                    b0 = __float_as_uint(Bs[swzt(k0, br)]);
                    b1 = __float_as_uint(Bs[swzt(k0 + 4, br)]);
                } else {
                    b0 = __float_as_uint(Bs[swz(br, k0)]);
                    b1 = __float_as_uint(Bs[swz(br, k0 + 4)]);
                }
#pragma unroll
                for (int mt = 0; mt < MT; mt++) mma_op(acc[mt][nt], af[mt], b0, b1);
            }
        }
    };

    const int nk = K >> 4;
    issue(0);
    if (nk > 1) issue(1);
    for (int i = 0; i < nk; i++) {
        if (i + 1 < nk) asm volatile("cp.async.wait_group 1;\n" ::: "memory");
        else            asm volatile("cp.async.wait_group 0;\n" ::: "memory");
        __syncthreads();
        if (i + 2 < nk) issue(i + 2);
        compute(i % 3);
    }
}

// ---------------- fused QKV projection (z: 0=Q,1=K,2=V-transposed) ----------------
__global__ __launch_bounds__(256, 2) void qkv_mma(
    const float* __restrict__ A,
    const float* __restrict__ Wq, const float* __restrict__ bq,
    const float* __restrict__ Wk, const float* __restrict__ bk,
    const float* __restrict__ Wv, const float* __restrict__ bv)
{
    __shared__ float smem[3 * (128 * 16 + 128 * 16)];
    const int tid = threadIdx.x;
    const int lane = tid & 31, wid = tid >> 5;
    const int wm = wid / 4, wn = wid % 4;
    const int gid = lane >> 2, tig = lane & 3;
    const int crow = tid >> 2;
    float acc[4][4][4] = {};
    const int which = blockIdx.z;
    const float* W = (which == 0) ? Wq : (which == 1) ? Wk : Wv;
    const float* bias = (which == 0) ? bq : (which == 1) ? bk : bv;
    const int m0 = blockIdx.y * 128, n0 = blockIdx.x * 128;
    mma_core<128, 0>(A + (size_t)(m0 + crow) * DIM, 16,
                     A + (size_t)(m0 + crow + 64) * DIM, 16,
                     W + (size_t)(n0 + crow) * DIM,
                     W + (size_t)(n0 + crow + 64) * DIM, 0,
                     DIM, smem, acc);
#pragma unroll
    for (int mt = 0; mt < 4; mt++) {
#pragma unroll
        for (int nt = 0; nt < 4; nt++) {
            int row = m0 + wm * 64 + mt * 16 + gid;
            int col = n0 + wn * 32 + nt * 8 + 2 * tig;
            float c0 = acc[mt][nt][0] + bias[col];
            float c1 = acc[mt][nt][1] + bias[col + 1];
            float c2 = acc[mt][nt][2] + bias[col];
            float c3 = acc[mt][nt][3] + bias[col + 1];
            if (which == 0) {
                *(float2*)(g_Q + (size_t)row * DIM + col) = make_float2(c0, c1);
                *(float2*)(g_Q + (size_t)(row + 8) * DIM + col) = make_float2(c2, c3);
            } else if (which == 1) {
                *(float2*)(g_K + (size_t)row * DIM + col) = make_float2(c0, c1);
                *(float2*)(g_K + (size_t)(row + 8) * DIM + col) = make_float2(c2, c3);
            } else {
                float vals[4] = {c0, c1, c2, c3};
#pragma unroll
                for (int q = 0; q < 4; q++) {
                    int rr = row + (q >> 1) * 8;
                    int cc = col + (q & 1);
                    int bb = rr >> 10, tt = rr & 1023;
                    int h = cc >> 6, d = cc & 63;
                    g_Vt[(((size_t)bb * NH + h) * HD + d) * SEQ + tt] = vals[q];
                }
            }
        }
    }
}

// ---------------- O projection ----------------
__global__ __launch_bounds__(256, 2) void oproj_mma(
    const float* __restrict__ A, const float* __restrict__ W,
    const float* __restrict__ bias, float* __restrict__ C)
{
    __shared__ float smem[3 * (128 * 16 + 128 * 16)];
    const int tid = threadIdx.x;
    const int lane = tid & 31, wid = tid >> 5;
    const int wm = wid / 4, wn = wid % 4;
    const int gid = lane >> 2, tig = lane & 3;
    const int crow = tid >> 2;
    float acc[4][4][4] = {};
    const int m0 = blockIdx.y * 128, n0 = blockIdx.x * 128;
    mma_core<128, 0>(A + (size_t)(m0 + crow) * DIM, 16,
                     A + (size_t)(m0 + crow + 64) * DIM, 16,
                     W + (size_t)(n0 + crow) * DIM,
                     W + (size_t)(n0 + crow + 64) * DIM, 0,
                     DIM, smem, acc);
#pragma unroll
    for (int mt = 0; mt < 4; mt++) {
#pragma unroll
        for (int nt = 0; nt < 4; nt++) {
            int row = m0 + wm * 64 + mt * 16 + gid;
            int col = n0 + wn * 32 + nt * 8 + 2 * tig;
            float b0 = bias[col], b1 = bias[col + 1];
            *(float2*)(C + (size_t)row * DIM + col) =
                make_float2(acc[mt][nt][0] + b0, acc[mt][nt][1] + b1);
            *(float2*)(C + (size_t)(row + 8) * DIM + col) =
                make_float2(acc[mt][nt][2] + b0, acc[mt][nt][3] + b1);
        }
    }
}

// ---------------- QK^T + per-row stats epilogue ----------------
__global__ __launch_bounds__(256, 2) void qk_mma(
    const float* __restrict__ Q, const float* __restrict__ Kt, float scale)
{
    __shared__ float smem[3 * (128 * 16 + 128 * 16)];
    const int tid = threadIdx.x;
    const int lane = tid & 31, wid = tid >> 5;
    const int wm = wid / 4, wn = wid % 4;
    const int gid = lane >> 2, tig = lane & 3;
    const int crow = tid >> 2;
    float acc[4][4][4] = {};
    const int z = blockIdx.z, b = z / NH, h = z % NH;
    const int m0 = blockIdx.y * 128, n0 = blockIdx.x * 128;
    const float* Ab = Q + (size_t)b * SEQ * DIM + h * HD;
    const float* Bb = Kt + (size_t)b * SEQ * DIM + h * HD;
    float* Cb = g_P + (size_t)z * SEQ * SEQ;
    mma_core<128, 0>(Ab + (size_t)(m0 + crow) * DIM, 16,
                     Ab + (size_t)(m0 + crow + 64) * DIM, 16,
                     Bb + (size_t)(n0 + crow) * DIM,
                     Bb + (size_t)(n0 + crow + 64) * DIM, 0,
                     HD, smem, acc);
    const size_t rowbase = (size_t)z * SEQ + m0;
#pragma unroll
    for (int mt = 0; mt < 4; mt++) {
        float s0 = 0.f, q0 = 0.f, s8 = 0.f, q8 = 0.f;
        float mx0 = -3e38f, mn0 = 3e38f, mx8 = -3e38f, mn8 = 3e38f;
#pragma unroll
        for (int nt = 0; nt < 4; nt++) {
            int row = m0 + wm * 64 + mt * 16 + gid;
            int col = n0 + wn * 32 + nt * 8 + 2 * tig;
            float v0 = acc[mt][nt][0] * scale, v1 = acc[mt][nt][1] * scale;
            float v2 = acc[mt][nt][2] * scale, v3 = acc[mt][nt][3] * scale;
            *(float2*)(Cb + (size_t)row * SEQ + col) = make_float2(v0, v1);
            *(float2*)(Cb + (size_t)(row + 8) * SEQ + col) = make_float2(v2, v3);
            s0 += v0 + v1; q0 += v0 * v0 + v1 * v1;
            mx0 = fmaxf(mx0, fmaxf(v0, v1)); mn0 = fminf(mn0, fminf(v0, v1));
            s8 += v2 + v3; q8 += v2 * v2 + v3 * v3;
            mx8 = fmaxf(mx8, fmaxf(v2, v3)); mn8 = fminf(mn8, fminf(v2, v3));
        }
#pragma unroll
        for (int o = 1; o < 4; o <<= 1) {
            s0 += __shfl_xor_sync(~0u, s0, o); q0 += __shfl_xor_sync(~0u, q0, o);
            s8 += __shfl_xor_sync(~0u, s8, o); q8 += __shfl_xor_sync(~0u, q8, o);
            mx0 = fmaxf(mx0, __shfl_xor_sync(~0u, mx0, o));
            mn0 = fminf(mn0, __shfl_xor_sync(~0u, mn0, o));
            mx8 = fmaxf(mx8, __shfl_xor_sync(~0u, mx8, o));
            mn8 = fminf(mn8, __shfl_xor_sync(~0u, mn8, o));
        }
        if (tig == 0) {
            size_t r0 = rowbase + wm * 64 + mt * 16 + gid;
            atomicAdd(&g_rsum[r0], s0);   atomicAdd(&g_rsumsq[r0], q0);
            atomicMax(&g_rmaxe[r0], fenc(mx0)); atomicMin(&g_rmine[r0], fenc(mn0));
            atomicAdd(&g_rsum[r0 + 8], s8); atomicAdd(&g_rsumsq[r0 + 8], q8);
            atomicMax(&g_rmaxe[r0 + 8], fenc(mx8)); atomicMin(&g_rmine[r0 + 8], fenc(mn8));
        }
    }
}

// ---------------- zero stats + routing counters ----------------
__global__ void zero_stats_kernel() {
    int i = blockIdx.x * 256 + threadIdx.x;
    if (i < ROWS_TOT) {
        g_rsum[i] = 0.f;
        g_rsumsq[i] = 0.f;
        g_rmaxe[i] = fenc(-3e38f);
        g_rmine[i] = fenc(3e38f);
    }
    if (i < NE) g_cnt[i] = 0;
}

// ---------------- fused zscore-softmax + P@V (BM=64, 384 CTAs) ----------------
__global__ __launch_bounds__(256, 2) void pv2_mma(const float* __restrict__ gamma)
{
    __shared__ float Asm[2][64 * 16];
    __shared__ float Bsm[3][64 * 16];
    __shared__ float denom_s[64];
    __shared__ float2 rowc_s[64];
    const int tid = threadIdx.x;
    const int lane = tid & 31, wid = tid >> 5;
    const int wm = wid >> 2, wn = wid & 3;      // 2 m-warps x 4 n-warps
    const int gid = lane >> 2, tig = lane & 3;
    const int crow = tid >> 2, cq = tid & 3;    // 64 rows x 4 quarters
    const int coff = (crow << 4) + ((cq ^ ((crow >> 1) & 3)) << 2);
    const int q4 = 4 * cq;
    float acc[2][2][4] = {};                    // warp tile 32m x 16n
    const int z = blockIdx.z, b = z / NH, h = z % NH;
    const int m0 = blockIdx.y * 64;
    const float* Arow = g_P + ((size_t)z * SEQ + m0 + crow) * SEQ;
    const float* Brow = g_Vt + (size_t)z * HD * SEQ + (size_t)crow * SEQ;
    float esum = 0.f;
    constexpr int nk = SEQ / 16;  // 64

    auto issueB = [&](int i) {
        cp_async16(Bsm[i % 3] + coff, Brow + (i << 4) + q4, 16);
        asm volatile("cp.async.commit_group;\n" ::: "memory");
    };
    auto compute = [&](const float* As, const float* Bs) {
#pragma unroll
        for (int c = 0; c < 2; c++) {
            const int k0 = c * 8 + tig;
            uint32_t af[2][4];
#pragma unroll
            for (int mt = 0; mt < 2; mt++) {
                const int ar = wm * 32 + mt * 16 + gid;
                af[mt][0] = __float_as_uint(As[swz(ar, k0)]);
                af[mt][1] = __float_as_uint(As[swz(ar + 8, k0)]);
                af[mt][2] = __float_as_uint(As[swz(ar, k0 + 4)]);
                af[mt][3] = __float_as_uint(As[swz(ar + 8, k0 + 4)]);
            }
#pragma unroll
            for (int nt = 0; nt < 2; nt++) {
                const int br = wn * 16 + nt * 8 + gid;
                uint32_t b0 = __float_as_uint(Bs[swz(br, k0)]);
                uint32_t b1 = __float_as_uint(Bs[swz(br, k0 + 4)]);
#pragma unroll
                for (int mt = 0; mt < 2; mt++) mma_op(acc[mt][nt], af[mt], b0, b1);
            }
        }
    };

    issueB(0);
    issueB(1);
    // per-row zscore coefficients computed locally (rows m0..m0+63)
    if (tid < 64) {
        size_t i = (size_t)z * SEQ + m0 + tid;
        float s = g_rsum[i], q = g_rsumsq[i];
        float mean = s * (1.f / SEQ);
        float var = fmaxf((q - s * s * (1.f / SEQ)) * (1.f / (SEQ - 1)), 0.f);
        float c1 = (*gamma) / (sqrtf(var) + EPSZ);
        float mx = fdec(g_rmaxe[i]), mn = fdec(g_rmine[i]);
        float zmax = fmaxf(c1 * (mx - mean), c1 * (mn - mean));
        rowc_s[tid] = make_float2(c1, -mean * c1 - zmax);
    }
    __syncthreads();
    const float2 rc = rowc_s[crow];
    float4 a0 = *(const float4*)(Arow + q4);
    for (int i = 0; i < nk; i++) {
        if (i + 1 < nk) asm volatile("cp.async.wait_group 1;\n" ::: "memory");
        else            asm volatile("cp.async.wait_group 0;\n" ::: "memory");
        __syncthreads();                       // B(i) visible; compute(i-1) done
        if (i + 2 < nk) issueB(i + 2);
        float4 e0;
        e0.x = __expf(fmaf(a0.x, rc.x, rc.y));
        e0.y = __expf(fmaf(a0.y, rc.x, rc.y));
        e0.z = __expf(fmaf(a0.z, rc.x, rc.y));
        e0.w = __expf(fmaf(a0.w, rc.x, rc.y));
        esum += e0.x + e0.y + e0.z + e0.w;
        *(float4*)(Asm[i & 1] + coff) = e0;
        if (i + 1 < nk) a0 = *(const float4*)(Arow + ((i + 1) << 4) + q4);
        __syncthreads();                       // A STS visible
        compute(Asm[i & 1], Bsm[i % 3]);
    }
    // row exp-sums -> denominators
#pragma unroll
    for (int o = 1; o < 4; o <<= 1) esum += __shfl_xor_sync(~0u, esum, o);
    if ((tid & 3) == 0) denom_s[crow] = esum;
    __syncthreads();
#pragma unroll
    for (int mt = 0; mt < 2; mt++) {
#pragma unroll
        for (int nt = 0; nt < 2; nt++) {
            int ro = wm * 32 + mt * 16 + gid;
            int col = wn * 16 + nt * 8 + 2 * tig;
            float r0 = 1.f / denom_s[ro];
            float r8 = 1.f / denom_s[ro + 8];
            int row = m0 + ro;
            float* c0 = g_attn + ((size_t)(b * SEQ + row)) * DIM + h * HD + col;
            float* c1 = g_attn + ((size_t)(b * SEQ + row + 8)) * DIM + h * HD + col;
            *(float2*)c0 = make_float2(acc[mt][nt][0] * r0, acc[mt][nt][1] * r0);
            *(float2*)c1 = make_float2(acc[mt][nt][2] * r8, acc[mt][nt][3] * r8);
        }
    }
}

// ---------------- FF1 (TN): H1 = relu(x[list] @ W1[e] + b1) ----------------
__global__ __launch_bounds__(256, 2) void ff1_mma(
    const float* __restrict__ x, const float* __restrict__ W1,
    const float* __restrict__ b1)
{
    const int e = blockIdx.z;
    const int cnt = g_cnt[e];
    const int m0 = blockIdx.y * 128;
    if (m0 >= cnt) return;
    __shared__ float smem[3 * (128 * 16 + 128 * 16)];
    const int tid = threadIdx.x;
    const int lane = tid & 31, wid = tid >> 5;
    const int wm = wid / 4, wn = wid % 4;
    const int gid = lane >> 2, tig = lane & 3;
    const int crow = tid >> 2;
    float acc[4][4][4] = {};
    const int n0 = blockIdx.x * 128;
    const int r1 = m0 + crow, r2 = m0 + crow + 64;
    const float* pa1 = x; int sa1 = 0;
    const float* pa2 = x; int sa2 = 0;
    if (r1 < cnt) { pa1 = x + (size_t)g_list[e * NTOK + r1] * DIM; sa1 = 16; }
    if (r2 < cnt) { pa2 = x + (size_t)g_list[e * NTOK + r2] * DIM; sa2 = 16; }
    const float* Bb = W1 + (size_t)e * DIM * FFD + n0;   // [K=DIM][N=FFD]
    const float* bb = b1 + e * FFD;
    float* Hout = g_H1 + (size_t)e * NTOK * FFD;
    mma_core<128, 1>(pa1, sa1, pa2, sa2, Bb, nullptr, FFD, DIM, smem, acc);
#pragma unroll
    for (int mt = 0; mt < 4; mt++) {
#pragma unroll
        for (int nt = 0; nt < 4; nt++) {
            int lm = m0 + wm * 64 + mt * 16 + gid;
            int col = n0 + wn * 32 + nt * 8 + 2 * tig;
            float b0 = bb[col], b1v = bb[col + 1];
            if (lm < cnt) {
                *(float2*)(Hout + (size_t)lm * FFD + col) =
                    make_float2(fmaxf(acc[mt][nt][0] + b0, 0.f), fmaxf(acc[mt][nt][1] + b1v, 0.f));
            }
            if (lm + 8 < cnt) {
                *(float2*)(Hout + (size_t)(lm + 8) * FFD + col) =
                    make_float2(fmaxf(acc[mt][nt][2] + b0, 0.f), fmaxf(acc[mt][nt][3] + b1v, 0.f));
            }
        }
    }
}

// ---------------- FF2 (TN): Y = H1 @ W2[e] + b2 ----------------
__global__ __launch_bounds__(256, 2) void ff2_mma(
    const float* __restrict__ W2, const float* __restrict__ b2)
{
    const int e = blockIdx.z;
    const int cnt = g_cnt[e];
    const int m0 = blockIdx.y * 128;
    if (m0 >= cnt) return;
    __shared__ float smem[3 * (128 * 16 + 128 * 16)];
    const int tid = threadIdx.x;
    const int lane = tid & 31, wid = tid >> 5;
    const int wm = wid / 4, wn = wid % 4;
    const int gid = lane >> 2, tig = lane & 3;
    const int crow = tid >> 2;
    float acc[4][4][4] = {};
    const int n0 = blockIdx.x * 128;
    const float* Ab = g_H1 + (size_t)e * NTOK * FFD;
    const int r1 = m0 + crow, r2 = m0 + crow + 64;
    const float* pa1 = Ab; int sa1 = 0;
    const float* pa2 = Ab; int sa2 = 0;
    if (r1 < cnt) { pa1 = Ab + (size_t)r1 * FFD; sa1 = 16; }
    if (r2 < cnt) { pa2 = Ab + (size_t)r2 * FFD; sa2 = 16; }
    const float* Bb = W2 + (size_t)e * FFD * DIM + n0;   // [K=FFD][N=DIM]
    const float* bb = b2 + e * DIM;
    float* Yout = g_Y + (size_t)e * NTOK * DIM;
    mma_core<128, 1>(pa1, sa1, pa2, sa2, Bb, nullptr, DIM, FFD, smem, acc);
#pragma unroll
    for (int mt = 0; mt < 4; mt++) {
#pragma unroll
        for (int nt = 0; nt < 4; nt++) {
            int lm = m0 + wm * 64 + mt * 16 + gid;
            int col = n0 + wn * 32 + nt * 8 + 2 * tig;
            float b0 = bb[col], b1v = bb[col + 1];
            if (lm < cnt) {
                *(float2*)(Yout + (size_t)lm * DIM + col) =
                    make_float2(acc[mt][nt][0] + b0, acc[mt][nt][1] + b1v);
            }
            if (lm + 8 < cnt) {
                *(float2*)(Yout + (size_t)(lm + 8) * DIM + col) =
                    make_float2(acc[mt][nt][2] + b0, acc[mt][nt][3] + b1v);
            }
        }
    }
}

// ---------------- reductions ----------------
__device__ __forceinline__ float blockReduceSum(float v) {
    __shared__ float red[8];
    int lane = threadIdx.x & 31, wid = threadIdx.x >> 5;
#pragma unroll
    for (int o = 16; o > 0; o >>= 1) v += __shfl_xor_sync(0xffffffffu, v, o);
    __syncthreads();
    if (lane == 0) red[wid] = v;
    __syncthreads();
    float r = (lane < 8) ? red[lane] : 0.f;
#pragma unroll
    for (int o = 16; o > 0; o >>= 1) r += __shfl_xor_sync(0xffffffffu, r, o);
    return r;
}

// ---------------- LN1 + fused gating ----------------
__global__ void add_ln1_gate_kernel(const float* __restrict__ a, const float* __restrict__ b,
                                    const float* __restrict__ g, const float* __restrict__ be,
                                    const float* __restrict__ Wg, const float* __restrict__ bg,
                                    float* __restrict__ out) {
    int t = blockIdx.x, tid = threadIdx.x;
    const float* ar = a + (size_t)t * DIM;
    const float* br = b + (size_t)t * DIM;
    float v[3];
#pragma unroll
    for (int i = 0; i < 3; i++) v[i] = ar[tid + i * 256] + br[tid + i * 256];
    float mean = blockReduceSum(v[0] + v[1] + v[2]) * (1.f / DIM);
    float sq = 0.f;
#pragma unroll
    for (int i = 0; i < 3; i++) { v[i] -= mean; sq += v[i] * v[i]; }
    float var = blockReduceSum(sq) * (1.f / DIM);
    float r = rsqrtf(var + EPSLN);
    float xv[3];
    float gp0 = 0.f, gp1 = 0.f, gp2 = 0.f, gp3 = 0.f;
#pragma unroll
    for (int i = 0; i < 3; i++) {
        int c = tid + i * 256;
        xv[i] = v[i] * r * g[c] + be[c];
        out[(size_t)t * DIM + c] = xv[i];
        gp0 += xv[i] * Wg[c];
        gp1 += xv[i] * Wg[DIM + c];
        gp2 += xv[i] * Wg[2 * DIM + c];
        gp3 += xv[i] * Wg[3 * DIM + c];
    }
    float s0 = blockReduceSum(gp0);
    float s1 = blockReduceSum(gp1);
    float s2 = blockReduceSum(gp2);
    float s3 = blockReduceSum(gp3);
    if (tid == 0) {
        float s[4] = {s0 + bg[0], s1 + bg[1], s2 + bg[2], s3 + bg[3]};
        float mx = fmaxf(fmaxf(s[0], s[1]), fmaxf(s[2], s[3]));
        float p[4], sum = 0.f;
#pragma unroll
        for (int e = 0; e < 4; e++) { p[e] = expf(s[e] - mx); sum += p[e]; }
        float ri = 1.f / sum;
#pragma unroll
        for (int e = 0; e < 4; e++) p[e] *= ri;
        int i1 = 0;
#pragma unroll
        for (int e = 1; e < 4; e++) if (p[e] > p[i1]) i1 = e;
        int i2 = (i1 == 0) ? 1 : 0;
#pragma unroll
        for (int e = 0; e < 4; e++) if (e != i1 && p[e] > p[i2]) i2 = e;
        int slot = atomicAdd(&g_cnt[i1], 1);
        g_list[i1 * NTOK + slot] = t;
        g_tslot[t] = i1 * NTOK + slot;
        g_tw[t] = p[i1];
        slot = atomicAdd(&g_cnt[i2], 1);
        g_list[i2 * NTOK + slot] = t;
        g_tslot[NTOK + t] = i2 * NTOK + slot;
        g_tw[NTOK + t] = p[i2];
    }
}

// ---------------- LN2 + MoE combine ----------------
__global__ void add_ln2_moe_kernel(const float* __restrict__ x,
                                   const float* __restrict__ g, const float* __restrict__ be,
                                   float* __restrict__ out) {
    int t = blockIdx.x, tid = threadIdx.x;
    int s1 = g_tslot[t], s2 = g_tslot[NTOK + t];
    float w1 = g_tw[t], w2 = g_tw[NTOK + t];
    const float* y1 = g_Y + (size_t)s1 * DIM;
    const float* y2 = g_Y + (size_t)s2 * DIM;
    const float* xr = x + (size_t)t * DIM;
    float v[3];
#pragma unroll
    for (int i = 0; i < 3; i++) {
        int c = tid + i * 256;
        v[i] = xr[c] + w1 * y1[c] + w2 * y2[c];
    }
    float mean = blockReduceSum(v[0] + v[1] + v[2]) * (1.f / DIM);
    float sq = 0.f;
#pragma unroll
    for (int i = 0; i < 3; i++) { v[i] -= mean; sq += v[i] * v[i]; }
    float var = blockReduceSum(sq) * (1.f / DIM);
    float r = rsqrtf(var + EPSLN);
#pragma unroll
    for (int i = 0; i < 3; i++) {
        int c = tid + i * 256;
        out[(size_t)t * DIM + c] = v[i] * r * g[c] + be[c];
    }
}

// ---------------- launch ----------------
extern "C" void kernel_launch(void* const* d_in, const int* in_sizes, int n_in,
                              void* d_out, int out_size) {
    const float* src  = (const float*)d_in[0];
    const float* Wq = (const float*)d_in[2];
    const float* bq = (const float*)d_in[3];
    const float* Wk = (const float*)d_in[4];
    const float* bk = (const float*)d_in[5];
    const float* Wv = (const float*)d_in[6];
    const float* bv = (const float*)d_in[7];
    const float* Wo = (const float*)d_in[8];
    const float* bo = (const float*)d_in[9];
    const float* gamma = (const float*)d_in[10];
    const float* ln1g = (const float*)d_in[11];
    const float* ln1b = (const float*)d_in[12];
    const float* ln2g = (const float*)d_in[13];
    const float* ln2b = (const float*)d_in[14];
    const float* Wg = (const float*)d_in[15];
    const float* bg = (const float*)d_in[16];
    const float* W1 = (const float*)d_in[17];
    const float* b1 = (const float*)d_in[18];
    const float* W2 = (const float*)d_in[19];
    const float* b2 = (const float*)d_in[20];
    float* out = (float*)d_out;

    float *Qp, *Kp, *attnp, *attnop, *xp;
    cudaGetSymbolAddress((void**)&Qp, g_Q);
    cudaGetSymbolAddress((void**)&Kp, g_K);
    cudaGetSymbolAddress((void**)&attnp, g_attn);
    cudaGetSymbolAddress((void**)&attnop, g_attno);
    cudaGetSymbolAddress((void**)&xp, g_x);

    // zero stats + routing counters
    zero_stats_kernel<<<(ROWS_TOT + 255) / 256, 256>>>();

    // fused QKV projections (V written transposed)
    qkv_mma<<<dim3(DIM / 128, NTOK / 128, 3), 256>>>(src, Wq, bq, Wk, bk, Wv, bv);

    // logits = scale * Q K^T  (+ per-row stats)
    qk_mma<<<dim3(SEQ / 128, SEQ / 128, BHZ), 256>>>(Qp, Kp, 0.125f);

    // fused zscore+softmax+PV (BM=64, full-machine grid)
    pv2_mma<<<dim3(1, SEQ / 64, BHZ), 256>>>(gamma);

    // O projection
    oproj_mma<<<dim3(DIM / 128, NTOK / 128), 256>>>(attnp, Wo, bo, attnop);

    // x = LN1(src + attn_out), fused gating + routing
    add_ln1_gate_kernel<<<NTOK, 256>>>(src, attnop, ln1g, ln1b, Wg, bg, xp);

    // expert FFN (sparse top-2, TN weights)
    ff1_mma<<<dim3(FFD / 128, NTOK / 128, NE), 256>>>(xp, W1, b1);
    ff2_mma<<<dim3(DIM / 128, NTOK / 128, NE), 256>>>(W2, b2);

    // out = LN2(x + combine(Y))
    add_ln2_moe_kernel<<<NTOK, 256>>>(xp, ln2g, ln2b, out);
}

// round 10
// speedup vs baseline: 1.0462x; 1.0462x over previous
#include <cuda_runtime.h>
#include <cuda_fp16.h>
#include <math.h>
#include <stdint.h>

// ---------------- problem constants ----------------
namespace {
constexpr int BATCH = 2;
constexpr int SEQ   = 1024;
constexpr int DIM   = 768;
constexpr int NH    = 12;
constexpr int HD    = 64;
constexpr int FFD   = 3072;
constexpr int NE    = 4;
constexpr int NTOK  = BATCH * SEQ;     // 2048
constexpr int BHZ   = BATCH * NH;      // 24
constexpr int ROWS_TOT = BHZ * SEQ;    // 24576 attention rows
constexpr float EPSZ  = 1e-5f;
constexpr float EPSLN = 1e-5f;
}

// ---------------- scratch (static device memory) ----------------
__device__ __align__(16) float g_Q[NTOK * DIM];
__device__ __align__(16) float g_K[NTOK * DIM];
__device__ __align__(16) float g_Vt[BHZ * HD * SEQ];           // V^T: [b][h][d][t]
__device__ __align__(16) __half g_P[(size_t)BHZ * SEQ * SEQ];  // raw scaled logits (fp16)
__device__ __align__(16) float g_attn[NTOK * DIM];
__device__ __align__(16) float g_attno[NTOK * DIM];
__device__ __align__(16) float g_x[NTOK * DIM];
__device__ __align__(16) float g_H1[(size_t)NE * NTOK * FFD];
__device__ __align__(16) float g_Y[(size_t)NE * NTOK * DIM];
__device__ float g_rsum[ROWS_TOT];
__device__ float g_rsumsq[ROWS_TOT];
__device__ unsigned g_rmaxe[ROWS_TOT];
__device__ unsigned g_rmine[ROWS_TOT];
__device__ int   g_cnt[NE];
__device__ int   g_list[NE * NTOK];
__device__ int   g_tslot[2 * NTOK];
__device__ float g_tw[2 * NTOK];

// ---------------- primitives ----------------
__device__ __forceinline__ void mma_op(float* d, const uint32_t* a, uint32_t b0, uint32_t b1) {
    asm volatile(
        "mma.sync.aligned.m16n8k8.row.col.f32.tf32.tf32.f32 "
        "{%0,%1,%2,%3},{%4,%5,%6,%7},{%8,%9},{%0,%1,%2,%3};\n"
        : "+f"(d[0]), "+f"(d[1]), "+f"(d[2]), "+f"(d[3])
        : "r"(a[0]), "r"(a[1]), "r"(a[2]), "r"(a[3]), "r"(b0), "r"(b1));
}
__device__ __forceinline__ void cp_async16(float* dst, const float* src, int sz) {
    uint32_t s = (uint32_t)__cvta_generic_to_shared(dst);
    asm volatile("cp.async.cg.shared.global [%0], [%1], 16, %2;\n"
                 :: "r"(s), "l"(src), "r"(sz));
}
// swizzled float index in a (rows x 16f) tile (A operand / NT B operand)
__device__ __forceinline__ int swz(int row, int col) {
    return (row << 4) + (((((col >> 2) ^ ((row >> 1) & 3))) << 2) | (col & 3));
}
// swizzled index in a TN B tile (16 k-rows x 128 n floats)
__device__ __forceinline__ int swzt(int k, int n) {
    return (k << 7) + ((((n >> 2) ^ ((k & 3) << 1)) << 2) | (n & 3));
}
// ordered-uint encode for float atomic max/min
__device__ __forceinline__ unsigned fenc(float f) {
    unsigned u = __float_as_uint(f);
    return (u & 0x80000000u) ? ~u : (u | 0x80000000u);
}
__device__ __forceinline__ float fdec(unsigned u) {
    unsigned b = (u & 0x80000000u) ? (u ^ 0x80000000u) : ~u;
    return __uint_as_float(b);
}

// ---------------- cp.async 3-stage pipelined tf32 MMA core ----------------
// BM=128, BK=16, 256 threads. BN=128: warps 2x4, MT=4.
// BT=0: pb1/pb2 per-thread B row pointers ([N,K] K-contig).
// BT=1: pb1 = B + n0 ([K,N] N-contig), stride ldbt.
template<int BN, int BT>
__device__ __forceinline__ void mma_core(
    const float* pa1, int sa1, const float* pa2, int sa2,
    const float* pb1, const float* pb2, int ldbt,
    int K, float* smem, float (&acc)[(BN == 128) ? 4 : 2][4][4])
{
    constexpr int MT  = (BN == 128) ? 4 : 2;
    constexpr int WN  = (BN == 128) ? 4 : 2;
    constexpr int ASZ = 128 * 16;
    constexpr int BSZ = BN * 16;
    constexpr int STG = ASZ + BSZ;
    const int tid = threadIdx.x;
    const int lane = tid & 31, wid = tid >> 5;
    const int wm = wid / WN, wn = wid % WN;
    const int gid = lane >> 2, tig = lane & 3;
    const int crow = tid >> 2, cq = tid & 3;
    const int coff  = (crow << 4) + ((cq ^ ((crow >> 1) & 3)) << 2);
    const int coff2 = ((crow + 64) << 4) + ((cq ^ ((crow >> 1) & 3)) << 2);
    const int q4 = 4 * cq;
    const int kk = tid >> 4, ng = tid & 15;           // BT mode
    const int bco1 = swzt(kk, 4 * ng);
    const int bco2 = swzt(kk, 4 * (ng + 16));

    auto issue = [&](int i) {
        float* As = smem + (i % 3) * STG;
        float* Bs = As + ASZ;
        const int kt = i << 4;
        cp_async16(As + coff,  pa1 + kt + q4, sa1);
        cp_async16(As + coff2, pa2 + kt + q4, sa2);
        if (BT) {
            const float* bp = pb1 + (size_t)(kt + kk) * ldbt;
            cp_async16(Bs + bco1, bp + 4 * ng, 16);
            cp_async16(Bs + bco2, bp + 4 * ng + 64, 16);
        } else {
            cp_async16(Bs + coff,  pb1 + kt + q4, 16);
            if (BN == 128) cp_async16(Bs + coff2, pb2 + kt + q4, 16);
        }
        asm volatile("cp.async.commit_group;\n" ::: "memory");
    };
    auto compute = [&](int s) {
        const float* As = smem + s * STG;
        const float* Bs = As + ASZ;
#pragma unroll
        for (int c = 0; c < 2; c++) {
            const int k0 = c * 8 + tig;
            uint32_t af[MT][4];
#pragma unroll
            for (int mt = 0; mt < MT; mt++) {
                const int ar = wm * (MT * 16) + mt * 16 + gid;
                af[mt][0] = __float_as_uint(As[swz(ar, k0)]);
                af[mt][1] = __float_as_uint(As[swz(ar + 8, k0)]);
                af[mt][2] = __float_as_uint(As[swz(ar, k0 + 4)]);
                af[mt][3] = __float_as_uint(As[swz(ar + 8, k0 + 4)]);
            }
#pragma unroll
            for (int nt = 0; nt < 4; nt++) {
                const int br = wn * 32 + nt * 8 + gid;
                uint32_t b0, b1;
                if (BT) {
                    b0 = __float_as_uint(Bs[swzt(k0, br)]);
                    b1 = __float_as_uint(Bs[swzt(k0 + 4, br)]);
                } else {
                    b0 = __float_as_uint(Bs[swz(br, k0)]);
                    b1 = __float_as_uint(Bs[swz(br, k0 + 4)]);
                }
#pragma unroll
                for (int mt = 0; mt < MT; mt++) mma_op(acc[mt][nt], af[mt], b0, b1);
            }
        }
    };

    const int nk = K >> 4;
    issue(0);
    if (nk > 1) issue(1);
    for (int i = 0; i < nk; i++) {
        if (i + 1 < nk) asm volatile("cp.async.wait_group 1;\n" ::: "memory");
        else            asm volatile("cp.async.wait_group 0;\n" ::: "memory");
        __syncthreads();
        if (i + 2 < nk) issue(i + 2);
        compute(i % 3);
    }
}

// ---------------- fused QKV projection (z: 0=Q,1=K,2=V-transposed) ----------------
// Also zeroes the attention row-stats + routing counters (read only after qk).
__global__ __launch_bounds__(256, 2) void qkv_mma(
    const float* __restrict__ A,
    const float* __restrict__ Wq, const float* __restrict__ bq,
    const float* __restrict__ Wk, const float* __restrict__ bk,
    const float* __restrict__ Wv, const float* __restrict__ bv)
{
    __shared__ float smem[3 * (128 * 16 + 128 * 16)];
    const int tid = threadIdx.x;
    // fold zero_stats: 288 CTAs x 256 threads cover ROWS_TOT
    {
        int gbid = (blockIdx.z * gridDim.y + blockIdx.y) * gridDim.x + blockIdx.x;
        int gidx = gbid * 256 + tid;
        if (gidx < ROWS_TOT) {
            g_rsum[gidx] = 0.f;
            g_rsumsq[gidx] = 0.f;
            g_rmaxe[gidx] = fenc(-3e38f);
            g_rmine[gidx] = fenc(3e38f);
        }
        if (gidx < NE) g_cnt[gidx] = 0;
    }
    const int lane = tid & 31, wid = tid >> 5;
    const int wm = wid / 4, wn = wid % 4;
    const int gid = lane >> 2, tig = lane & 3;
    const int crow = tid >> 2;
    float acc[4][4][4] = {};
    const int which = blockIdx.z;
    const float* W = (which == 0) ? Wq : (which == 1) ? Wk : Wv;
    const float* bias = (which == 0) ? bq : (which == 1) ? bk : bv;
    const int m0 = blockIdx.y * 128, n0 = blockIdx.x * 128;
    mma_core<128, 0>(A + (size_t)(m0 + crow) * DIM, 16,
                     A + (size_t)(m0 + crow + 64) * DIM, 16,
                     W + (size_t)(n0 + crow) * DIM,
                     W + (size_t)(n0 + crow + 64) * DIM, 0,
                     DIM, smem, acc);
#pragma unroll
    for (int mt = 0; mt < 4; mt++) {
#pragma unroll
        for (int nt = 0; nt < 4; nt++) {
            int row = m0 + wm * 64 + mt * 16 + gid;
            int col = n0 + wn * 32 + nt * 8 + 2 * tig;
            float c0 = acc[mt][nt][0] + bias[col];
            float c1 = acc[mt][nt][1] + bias[col + 1];
            float c2 = acc[mt][nt][2] + bias[col];
            float c3 = acc[mt][nt][3] + bias[col + 1];
            if (which == 0) {
                *(float2*)(g_Q + (size_t)row * DIM + col) = make_float2(c0, c1);
                *(float2*)(g_Q + (size_t)(row + 8) * DIM + col) = make_float2(c2, c3);
            } else if (which == 1) {
                *(float2*)(g_K + (size_t)row * DIM + col) = make_float2(c0, c1);
                *(float2*)(g_K + (size_t)(row + 8) * DIM + col) = make_float2(c2, c3);
            } else {
                float vals[4] = {c0, c1, c2, c3};
#pragma unroll
                for (int q = 0; q < 4; q++) {
                    int rr = row + (q >> 1) * 8;
                    int cc = col + (q & 1);
                    int bb = rr >> 10, tt = rr & 1023;
                    int h = cc >> 6, d = cc & 63;
                    g_Vt[(((size_t)bb * NH + h) * HD + d) * SEQ + tt] = vals[q];
                }
            }
        }
    }
}

// ---------------- O projection ----------------
__global__ __launch_bounds__(256, 2) void oproj_mma(
    const float* __restrict__ A, const float* __restrict__ W,
    const float* __restrict__ bias, float* __restrict__ C)
{
    __shared__ float smem[3 * (128 * 16 + 128 * 16)];
    const int tid = threadIdx.x;
    const int lane = tid & 31, wid = tid >> 5;
    const int wm = wid / 4, wn = wid % 4;
    const int gid = lane >> 2, tig = lane & 3;
    const int crow = tid >> 2;
    float acc[4][4][4] = {};
    const int m0 = blockIdx.y * 128, n0 = blockIdx.x * 128;
    mma_core<128, 0>(A + (size_t)(m0 + crow) * DIM, 16,
                     A + (size_t)(m0 + crow + 64) * DIM, 16,
                     W + (size_t)(n0 + crow) * DIM,
                     W + (size_t)(n0 + crow + 64) * DIM, 0,
                     DIM, smem, acc);
#pragma unroll
    for (int mt = 0; mt < 4; mt++) {
#pragma unroll
        for (int nt = 0; nt < 4; nt++) {
            int row = m0 + wm * 64 + mt * 16 + gid;
            int col = n0 + wn * 32 + nt * 8 + 2 * tig;
            float b0 = bias[col], b1 = bias[col + 1];
            *(float2*)(C + (size_t)row * DIM + col) =
                make_float2(acc[mt][nt][0] + b0, acc[mt][nt][1] + b1);
            *(float2*)(C + (size_t)(row + 8) * DIM + col) =
                make_float2(acc[mt][nt][2] + b0, acc[mt][nt][3] + b1);
        }
    }
}

// ---------------- QK^T + per-row stats epilogue (fp16 P store) ----------------
__global__ __launch_bounds__(256, 2) void qk_mma(
    const float* __restrict__ Q, const float* __restrict__ Kt, float scale)
{
    __shared__ float smem[3 * (128 * 16 + 128 * 16)];
    const int tid = threadIdx.x;
    const int lane = tid & 31, wid = tid >> 5;
    const int wm = wid / 4, wn = wid % 4;
    const int gid = lane >> 2, tig = lane & 3;
    const int crow = tid >> 2;
    float acc[4][4][4] = {};
    const int z = blockIdx.z, b = z / NH, h = z % NH;
    const int m0 = blockIdx.y * 128, n0 = blockIdx.x * 128;
    const float* Ab = Q + (size_t)b * SEQ * DIM + h * HD;
    const float* Bb = Kt + (size_t)b * SEQ * DIM + h * HD;
    __half* Cb = g_P + (size_t)z * SEQ * SEQ;
    mma_core<128, 0>(Ab + (size_t)(m0 + crow) * DIM, 16,
                     Ab + (size_t)(m0 + crow + 64) * DIM, 16,
                     Bb + (size_t)(n0 + crow) * DIM,
                     Bb + (size_t)(n0 + crow + 64) * DIM, 0,
                     HD, smem, acc);
    const size_t rowbase = (size_t)z * SEQ + m0;
#pragma unroll
    for (int mt = 0; mt < 4; mt++) {
        float s0 = 0.f, q0 = 0.f, s8 = 0.f, q8 = 0.f;
        float mx0 = -3e38f, mn0 = 3e38f, mx8 = -3e38f, mn8 = 3e38f;
#pragma unroll
        for (int nt = 0; nt < 4; nt++) {
            int row = m0 + wm * 64 + mt * 16 + gid;
            int col = n0 + wn * 32 + nt * 8 + 2 * tig;
            float v0 = acc[mt][nt][0] * scale, v1 = acc[mt][nt][1] * scale;
            float v2 = acc[mt][nt][2] * scale, v3 = acc[mt][nt][3] * scale;
            *(__half2*)(Cb + (size_t)row * SEQ + col) = __floats2half2_rn(v0, v1);
            *(__half2*)(Cb + (size_t)(row + 8) * SEQ + col) = __floats2half2_rn(v2, v3);
            s0 += v0 + v1; q0 += v0 * v0 + v1 * v1;
            mx0 = fmaxf(mx0, fmaxf(v0, v1)); mn0 = fminf(mn0, fminf(v0, v1));
            s8 += v2 + v3; q8 += v2 * v2 + v3 * v3;
            mx8 = fmaxf(mx8, fmaxf(v2, v3)); mn8 = fminf(mn8, fminf(v2, v3));
        }
#pragma unroll
        for (int o = 1; o < 4; o <<= 1) {
            s0 += __shfl_xor_sync(~0u, s0, o); q0 += __shfl_xor_sync(~0u, q0, o);
            s8 += __shfl_xor_sync(~0u, s8, o); q8 += __shfl_xor_sync(~0u, q8, o);
            mx0 = fmaxf(mx0, __shfl_xor_sync(~0u, mx0, o));
            mn0 = fminf(mn0, __shfl_xor_sync(~0u, mn0, o));
            mx8 = fmaxf(mx8, __shfl_xor_sync(~0u, mx8, o));
            mn8 = fminf(mn8, __shfl_xor_sync(~0u, mn8, o));
        }
        if (tig == 0) {
            size_t r0 = rowbase + wm * 64 + mt * 16 + gid;
            atomicAdd(&g_rsum[r0], s0);   atomicAdd(&g_rsumsq[r0], q0);
            atomicMax(&g_rmaxe[r0], fenc(mx0)); atomicMin(&g_rmine[r0], fenc(mn0));
            atomicAdd(&g_rsum[r0 + 8], s8); atomicAdd(&g_rsumsq[r0 + 8], q8);
            atomicMax(&g_rmaxe[r0 + 8], fenc(mx8)); atomicMin(&g_rmine[r0 + 8], fenc(mn8));
        }
    }
}

// ---------------- fused zscore-softmax + P@V (BM=128, fp16 P reads) ----------------
__global__ __launch_bounds__(256, 2) void pv2_mma(const float* __restrict__ gamma)
{
    __shared__ float Asm[2][128 * 16];
    __shared__ float Bsm[3][64 * 16];
    __shared__ float denom_s[128];
    __shared__ float2 rowc_s[128];
    const int tid = threadIdx.x;
    const int lane = tid & 31, wid = tid >> 5;
    const int wm = wid / 2, wn = wid % 2;
    const int gid = lane >> 2, tig = lane & 3;
    // B-side indexing (64 rows x 4 quarters)
    const int browc = tid >> 2, bq = tid & 3;
    const int bcoff = (browc << 4) + ((bq ^ ((browc >> 1) & 3)) << 2);
    // A-side indexing (128 rows x 2 half-chunks of 8 halves)
    const int arow = tid >> 1, acq = tid & 1;
    const int axor = (arow >> 1) & 3;
    const int asoff0 = (arow << 4) + (((2 * acq)     ^ axor) << 2);
    const int asoff1 = (arow << 4) + (((2 * acq + 1) ^ axor) << 2);
    float acc[2][4][4] = {};
    const int z = blockIdx.z, b = z / NH, h = z % NH;
    const int m0 = blockIdx.y * 128;
    const __half* Arow = g_P + ((size_t)z * SEQ + m0 + arow) * SEQ + 8 * acq;
    const float* Brow = g_Vt + (size_t)z * HD * SEQ + (size_t)browc * SEQ;
    float esum = 0.f;
    constexpr int nk = SEQ / 16;  // 64

    auto issueB = [&](int i) {
        cp_async16(Bsm[i % 3] + bcoff, Brow + (i << 4) + 4 * bq, 16);
        asm volatile("cp.async.commit_group;\n" ::: "memory");
    };
    auto compute = [&](const float* As, const float* Bs) {
#pragma unroll
        for (int c = 0; c < 2; c++) {
            const int k0 = c * 8 + tig;
            uint32_t af[2][4];
#pragma unroll
            for (int mt = 0; mt < 2; mt++) {
                const int ar = wm * 32 + mt * 16 + gid;
                af[mt][0] = __float_as_uint(As[swz(ar, k0)]);
                af[mt][1] = __float_as_uint(As[swz(ar + 8, k0)]);
                af[mt][2] = __float_as_uint(As[swz(ar, k0 + 4)]);
                af[mt][3] = __float_as_uint(As[swz(ar + 8, k0 + 4)]);
            }
#pragma unroll
            for (int nt = 0; nt < 4; nt++) {
                const int br = wn * 32 + nt * 8 + gid;
                uint32_t b0 = __float_as_uint(Bs[swz(br, k0)]);
                uint32_t b1 = __float_as_uint(Bs[swz(br, k0 + 4)]);
#pragma unroll
                for (int mt = 0; mt < 2; mt++) mma_op(acc[mt][nt], af[mt], b0, b1);
            }
        }
    };

    issueB(0);
    issueB(1);
    // per-row zscore coefficients computed locally (rows m0..m0+127)
    if (tid < 128) {
        size_t i = (size_t)z * SEQ + m0 + tid;
        float s = g_rsum[i], q = g_rsumsq[i];
        float mean = s * (1.f / SEQ);
        float var = fmaxf((q - s * s * (1.f / SEQ)) * (1.f / (SEQ - 1)), 0.f);
        float c1 = (*gamma) / (sqrtf(var) + EPSZ);
        float mx = fdec(g_rmaxe[i]), mn = fdec(g_rmine[i]);
        float zmax = fmaxf(c1 * (mx - mean), c1 * (mn - mean));
        rowc_s[tid] = make_float2(c1, -mean * c1 - zmax);
    }
    __syncthreads();
    const float2 rc = rowc_s[arow];
    uint4 a0 = *(const uint4*)(Arow);   // 8 halves
    for (int i = 0; i < nk; i++) {
        if (i + 1 < nk) asm volatile("cp.async.wait_group 1;\n" ::: "memory");
        else            asm volatile("cp.async.wait_group 0;\n" ::: "memory");
        __syncthreads();                       // B(i) visible; compute(i-1) done
        if (i + 2 < nk) issueB(i + 2);
        // convert 8 halves -> exp
        float2 f0 = __half22float2(*(__half2*)&a0.x);
        float2 f1 = __half22float2(*(__half2*)&a0.y);
        float2 f2 = __half22float2(*(__half2*)&a0.z);
        float2 f3 = __half22float2(*(__half2*)&a0.w);
        float4 e0, e1;
        e0.x = __expf(fmaf(f0.x, rc.x, rc.y));
        e0.y = __expf(fmaf(f0.y, rc.x, rc.y));
        e0.z = __expf(fmaf(f1.x, rc.x, rc.y));
        e0.w = __expf(fmaf(f1.y, rc.x, rc.y));
        e1.x = __expf(fmaf(f2.x, rc.x, rc.y));
        e1.y = __expf(fmaf(f2.y, rc.x, rc.y));
        e1.z = __expf(fmaf(f3.x, rc.x, rc.y));
        e1.w = __expf(fmaf(f3.y, rc.x, rc.y));
        esum += e0.x + e0.y + e0.z + e0.w + e1.x + e1.y + e1.z + e1.w;
        *(float4*)(Asm[i & 1] + asoff0) = e0;
        *(float4*)(Asm[i & 1] + asoff1) = e1;
        if (i + 1 < nk) a0 = *(const uint4*)(Arow + ((i + 1) << 4));
        __syncthreads();                       // A STS visible
        compute(Asm[i & 1], Bsm[i % 3]);
    }
    // row exp-sums -> denominators (2 threads per row)
    esum += __shfl_xor_sync(~0u, esum, 1);
    if (acq == 0) denom_s[arow] = esum;
    __syncthreads();
#pragma unroll
    for (int mt = 0; mt < 2; mt++) {
#pragma unroll
        for (int nt = 0; nt < 4; nt++) {
            int ro = wm * 32 + mt * 16 + gid;
            int col = wn * 32 + nt * 8 + 2 * tig;
            float r0 = 1.f / denom_s[ro];
            float r8 = 1.f / denom_s[ro + 8];
            int row = m0 + ro;
            float* c0 = g_attn + ((size_t)(b * SEQ + row)) * DIM + h * HD + col;
            float* c1 = g_attn + ((size_t)(b * SEQ + row + 8)) * DIM + h * HD + col;
            *(float2*)c0 = make_float2(acc[mt][nt][0] * r0, acc[mt][nt][1] * r0);
            *(float2*)c1 = make_float2(acc[mt][nt][2] * r8, acc[mt][nt][3] * r8);
        }
    }
}

// ---------------- FF1 (TN): H1 = relu(x[list] @ W1[e] + b1) ----------------
__global__ __launch_bounds__(256, 2) void ff1_mma(
    const float* __restrict__ x, const float* __restrict__ W1,
    const float* __restrict__ b1)
{
    const int e = blockIdx.z;
    const int cnt = g_cnt[e];
    const int m0 = blockIdx.y * 128;
    if (m0 >= cnt) return;
    __shared__ float smem[3 * (128 * 16 + 128 * 16)];
    const int tid = threadIdx.x;
    const int lane = tid & 31, wid = tid >> 5;
    const int wm = wid / 4, wn = wid % 4;
    const int gid = lane >> 2, tig = lane & 3;
    const int crow = tid >> 2;
    float acc[4][4][4] = {};
    const int n0 = blockIdx.x * 128;
    const int r1 = m0 + crow, r2 = m0 + crow + 64;
    const float* pa1 = x; int sa1 = 0;
    const float* pa2 = x; int sa2 = 0;
    if (r1 < cnt) { pa1 = x + (size_t)g_list[e * NTOK + r1] * DIM; sa1 = 16; }
    if (r2 < cnt) { pa2 = x + (size_t)g_list[e * NTOK + r2] * DIM; sa2 = 16; }
    const float* Bb = W1 + (size_t)e * DIM * FFD + n0;   // [K=DIM][N=FFD]
    const float* bb = b1 + e * FFD;
    float* Hout = g_H1 + (size_t)e * NTOK * FFD;
    mma_core<128, 1>(pa1, sa1, pa2, sa2, Bb, nullptr, FFD, DIM, smem, acc);
#pragma unroll
    for (int mt = 0; mt < 4; mt++) {
#pragma unroll
        for (int nt = 0; nt < 4; nt++) {
            int lm = m0 + wm * 64 + mt * 16 + gid;
            int col = n0 + wn * 32 + nt * 8 + 2 * tig;
            float b0 = bb[col], b1v = bb[col + 1];
            if (lm < cnt) {
                *(float2*)(Hout + (size_t)lm * FFD + col) =
                    make_float2(fmaxf(acc[mt][nt][0] + b0, 0.f), fmaxf(acc[mt][nt][1] + b1v, 0.f));
            }
            if (lm + 8 < cnt) {
                *(float2*)(Hout + (size_t)(lm + 8) * FFD + col) =
                    make_float2(fmaxf(acc[mt][nt][2] + b0, 0.f), fmaxf(acc[mt][nt][3] + b1v, 0.f));
            }
        }
    }
}

// ---------------- FF2 (TN): Y = H1 @ W2[e] + b2 ----------------
__global__ __launch_bounds__(256, 2) void ff2_mma(
    const float* __restrict__ W2, const float* __restrict__ b2)
{
    const int e = blockIdx.z;
    const int cnt = g_cnt[e];
    const int m0 = blockIdx.y * 128;
    if (m0 >= cnt) return;
    __shared__ float smem[3 * (128 * 16 + 128 * 16)];
    const int tid = threadIdx.x;
    const int lane = tid & 31, wid = tid >> 5;
    const int wm = wid / 4, wn = wid % 4;
    const int gid = lane >> 2, tig = lane & 3;
    const int crow = tid >> 2;
    float acc[4][4][4] = {};
    const int n0 = blockIdx.x * 128;
    const float* Ab = g_H1 + (size_t)e * NTOK * FFD;
    const int r1 = m0 + crow, r2 = m0 + crow + 64;
    const float* pa1 = Ab; int sa1 = 0;
    const float* pa2 = Ab; int sa2 = 0;
    if (r1 < cnt) { pa1 = Ab + (size_t)r1 * FFD; sa1 = 16; }
    if (r2 < cnt) { pa2 = Ab + (size_t)r2 * FFD; sa2 = 16; }
    const float* Bb = W2 + (size_t)e * FFD * DIM + n0;   // [K=FFD][N=DIM]
    const float* bb = b2 + e * DIM;
    float* Yout = g_Y + (size_t)e * NTOK * DIM;
    mma_core<128, 1>(pa1, sa1, pa2, sa2, Bb, nullptr, DIM, FFD, smem, acc);
#pragma unroll
    for (int mt = 0; mt < 4; mt++) {
#pragma unroll
        for (int nt = 0; nt < 4; nt++) {
            int lm = m0 + wm * 64 + mt * 16 + gid;
            int col = n0 + wn * 32 + nt * 8 + 2 * tig;
            float b0 = bb[col], b1v = bb[col + 1];
            if (lm < cnt) {
                *(float2*)(Yout + (size_t)lm * DIM + col) =
                    make_float2(acc[mt][nt][0] + b0, acc[mt][nt][1] + b1v);
            }
            if (lm + 8 < cnt) {
                *(float2*)(Yout + (size_t)(lm + 8) * DIM + col) =
                    make_float2(acc[mt][nt][2] + b0, acc[mt][nt][3] + b1v);
            }
        }
    }
}

// ---------------- reductions ----------------
__device__ __forceinline__ float blockReduceSum(float v) {
    __shared__ float red[8];
    int lane = threadIdx.x & 31, wid = threadIdx.x >> 5;
#pragma unroll
    for (int o = 16; o > 0; o >>= 1) v += __shfl_xor_sync(0xffffffffu, v, o);
    __syncthreads();
    if (lane == 0) red[wid] = v;
    __syncthreads();
    float r = (lane < 8) ? red[lane] : 0.f;
#pragma unroll
    for (int o = 16; o > 0; o >>= 1) r += __shfl_xor_sync(0xffffffffu, r, o);
    return r;
}

// ---------------- LN1 + fused gating ----------------
__global__ void add_ln1_gate_kernel(const float* __restrict__ a, const float* __restrict__ b,
                                    const float* __restrict__ g, const float* __restrict__ be,
                                    const float* __restrict__ Wg, const float* __restrict__ bg,
                                    float* __restrict__ out) {
    int t = blockIdx.x, tid = threadIdx.x;
    const float* ar = a + (size_t)t * DIM;
    const float* br = b + (size_t)t * DIM;
    float v[3];
#pragma unroll
    for (int i = 0; i < 3; i++) v[i] = ar[tid + i * 256] + br[tid + i * 256];
    float mean = blockReduceSum(v[0] + v[1] + v[2]) * (1.f / DIM);
    float sq = 0.f;
#pragma unroll
    for (int i = 0; i < 3; i++) { v[i] -= mean; sq += v[i] * v[i]; }
    float var = blockReduceSum(sq) * (1.f / DIM);
    float r = rsqrtf(var + EPSLN);
    float xv[3];
    float gp0 = 0.f, gp1 = 0.f, gp2 = 0.f, gp3 = 0.f;
#pragma unroll
    for (int i = 0; i < 3; i++) {
        int c = tid + i * 256;
        xv[i] = v[i] * r * g[c] + be[c];
        out[(size_t)t * DIM + c] = xv[i];
        gp0 += xv[i] * Wg[c];
        gp1 += xv[i] * Wg[DIM + c];
        gp2 += xv[i] * Wg[2 * DIM + c];
        gp3 += xv[i] * Wg[3 * DIM + c];
    }
    float s0 = blockReduceSum(gp0);
    float s1 = blockReduceSum(gp1);
    float s2 = blockReduceSum(gp2);
    float s3 = blockReduceSum(gp3);
    if (tid == 0) {
        float s[4] = {s0 + bg[0], s1 + bg[1], s2 + bg[2], s3 + bg[3]};
        float mx = fmaxf(fmaxf(s[0], s[1]), fmaxf(s[2], s[3]));
        float p[4], sum = 0.f;
#pragma unroll
        for (int e = 0; e < 4; e++) { p[e] = expf(s[e] - mx); sum += p[e]; }
        float ri = 1.f / sum;
#pragma unroll
        for (int e = 0; e < 4; e++) p[e] *= ri;
        int i1 = 0;
#pragma unroll
        for (int e = 1; e < 4; e++) if (p[e] > p[i1]) i1 = e;
        int i2 = (i1 == 0) ? 1 : 0;
#pragma unroll
        for (int e = 0; e < 4; e++) if (e != i1 && p[e] > p[i2]) i2 = e;
        int slot = atomicAdd(&g_cnt[i1], 1);
        g_list[i1 * NTOK + slot] = t;
        g_tslot[t] = i1 * NTOK + slot;
        g_tw[t] = p[i1];
        slot = atomicAdd(&g_cnt[i2], 1);
        g_list[i2 * NTOK + slot] = t;
        g_tslot[NTOK + t] = i2 * NTOK + slot;
        g_tw[NTOK + t] = p[i2];
    }
}

// ---------------- LN2 + MoE combine ----------------
__global__ void add_ln2_moe_kernel(const float* __restrict__ x,
                                   const float* __restrict__ g, const float* __restrict__ be,
                                   float* __restrict__ out) {
    int t = blockIdx.x, tid = threadIdx.x;
    int s1 = g_tslot[t], s2 = g_tslot[NTOK + t];
    float w1 = g_tw[t], w2 = g_tw[NTOK + t];
    const float* y1 = g_Y + (size_t)s1 * DIM;
    const float* y2 = g_Y + (size_t)s2 * DIM;
    const float* xr = x + (size_t)t * DIM;
    float v[3];
#pragma unroll
    for (int i = 0; i < 3; i++) {
        int c = tid + i * 256;
        v[i] = xr[c] + w1 * y1[c] + w2 * y2[c];
    }
    float mean = blockReduceSum(v[0] + v[1] + v[2]) * (1.f / DIM);
    float sq = 0.f;
#pragma unroll
    for (int i = 0; i < 3; i++) { v[i] -= mean; sq += v[i] * v[i]; }
    float var = blockReduceSum(sq) * (1.f / DIM);
    float r = rsqrtf(var + EPSLN);
#pragma unroll
    for (int i = 0; i < 3; i++) {
        int c = tid + i * 256;
        out[(size_t)t * DIM + c] = v[i] * r * g[c] + be[c];
    }
}

// ---------------- launch ----------------
extern "C" void kernel_launch(void* const* d_in, const int* in_sizes, int n_in,
                              void* d_out, int out_size) {
    const float* src  = (const float*)d_in[0];
    const float* Wq = (const float*)d_in[2];
    const float* bq = (const float*)d_in[3];
    const float* Wk = (const float*)d_in[4];
    const float* bk = (const float*)d_in[5];
    const float* Wv = (const float*)d_in[6];
    const float* bv = (const float*)d_in[7];
    const float* Wo = (const float*)d_in[8];
    const float* bo = (const float*)d_in[9];
    const float* gamma = (const float*)d_in[10];
    const float* ln1g = (const float*)d_in[11];
    const float* ln1b = (const float*)d_in[12];
    const float* ln2g = (const float*)d_in[13];
    const float* ln2b = (const float*)d_in[14];
    const float* Wg = (const float*)d_in[15];
    const float* bg = (const float*)d_in[16];
    const float* W1 = (const float*)d_in[17];
    const float* b1 = (const float*)d_in[18];
    const float* W2 = (const float*)d_in[19];
    const float* b2 = (const float*)d_in[20];
    float* out = (float*)d_out;

    float *Qp, *Kp, *attnp, *attnop, *xp;
    cudaGetSymbolAddress((void**)&Qp, g_Q);
    cudaGetSymbolAddress((void**)&Kp, g_K);
    cudaGetSymbolAddress((void**)&attnp, g_attn);
    cudaGetSymbolAddress((void**)&attnop, g_attno);
    cudaGetSymbolAddress((void**)&xp, g_x);

    // fused QKV projections (V written transposed) + stats/counter zeroing
    qkv_mma<<<dim3(DIM / 128, NTOK / 128, 3), 256>>>(src, Wq, bq, Wk, bk, Wv, bv);

    // logits = scale * Q K^T  (+ per-row stats, fp16 P store)
    qk_mma<<<dim3(SEQ / 128, SEQ / 128, BHZ), 256>>>(Qp, Kp, 0.125f);

    // fused zscore+softmax+PV (rowc in prologue, fp16 P reads)
    pv2_mma<<<dim3(1, SEQ / 128, BHZ), 256>>>(gamma);

    // O projection
    oproj_mma<<<dim3(DIM / 128, NTOK / 128), 256>>>(attnp, Wo, bo, attnop);

    // x = LN1(src + attn_out), fused gating + routing
    add_ln1_gate_kernel<<<NTOK, 256>>>(src, attnop, ln1g, ln1b, Wg, bg, xp);

    // expert FFN (sparse top-2, TN weights)
    ff1_mma<<<dim3(FFD / 128, NTOK / 128, NE), 256>>>(xp, W1, b1);
    ff2_mma<<<dim3(DIM / 128, NTOK / 128, NE), 256>>>(W2, b2);

    // out = LN2(x + combine(Y))
    add_ln2_moe_kernel<<<NTOK, 256>>>(xp, ln2g, ln2b, out);
}

// round 11
// speedup vs baseline: 1.0583x; 1.0115x over previous
#include <cuda_runtime.h>
#include <cuda_fp16.h>
#include <math.h>
#include <stdint.h>

// ---------------- problem constants ----------------
namespace {
constexpr int BATCH = 2;
constexpr int SEQ   = 1024;
constexpr int DIM   = 768;
constexpr int NH    = 12;
constexpr int HD    = 64;
constexpr int FFD   = 3072;
constexpr int NE    = 4;
constexpr int NTOK  = BATCH * SEQ;     // 2048
constexpr int BHZ   = BATCH * NH;      // 24
constexpr int ROWS_TOT = BHZ * SEQ;    // 24576 attention rows
constexpr float EPSZ  = 1e-5f;
constexpr float EPSLN = 1e-5f;
}

// ---------------- scratch (static device memory) ----------------
__device__ __align__(16) float g_Q[NTOK * DIM];
__device__ __align__(16) float g_K[NTOK * DIM];
__device__ __align__(16) float g_Vt[BHZ * HD * SEQ];           // V^T: [b][h][d][t]
__device__ __align__(16) __half g_P[(size_t)BHZ * SEQ * SEQ];  // raw scaled logits (fp16)
__device__ __align__(16) float g_attn[NTOK * DIM];
__device__ __align__(16) float g_attno[NTOK * DIM];
__device__ __align__(16) float g_x[NTOK * DIM];
__device__ __align__(16) float g_H1[(size_t)NE * NTOK * FFD];
__device__ __align__(16) float g_Y[(size_t)NE * NTOK * DIM];
__device__ float g_rsum[ROWS_TOT];
__device__ float g_rsumsq[ROWS_TOT];
__device__ unsigned g_rmaxe[ROWS_TOT];
__device__ unsigned g_rmine[ROWS_TOT];
__device__ int   g_cnt[NE];
__device__ int   g_list[NE * NTOK];
__device__ int   g_tslot[2 * NTOK];
__device__ float g_tw[2 * NTOK];

// ---------------- primitives ----------------
__device__ __forceinline__ void mma_op(float* d, const uint32_t* a, uint32_t b0, uint32_t b1) {
    asm volatile(
        "mma.sync.aligned.m16n8k8.row.col.f32.tf32.tf32.f32 "
        "{%0,%1,%2,%3},{%4,%5,%6,%7},{%8,%9},{%0,%1,%2,%3};\n"
        : "+f"(d[0]), "+f"(d[1]), "+f"(d[2]), "+f"(d[3])
        : "r"(a[0]), "r"(a[1]), "r"(a[2]), "r"(a[3]), "r"(b0), "r"(b1));
}
__device__ __forceinline__ void cp_async16(float* dst, const float* src, int sz) {
    uint32_t s = (uint32_t)__cvta_generic_to_shared(dst);
    asm volatile("cp.async.cg.shared.global [%0], [%1], 16, %2;\n"
                 :: "r"(s), "l"(src), "r"(sz));
}
// swizzled float index in a (rows x 16f) tile (A operand / NT B operand)
__device__ __forceinline__ int swz(int row, int col) {
    return (row << 4) + (((((col >> 2) ^ ((row >> 1) & 3))) << 2) | (col & 3));
}
// swizzled index in a TN B tile (16 k-rows x 128 n floats)
__device__ __forceinline__ int swzt(int k, int n) {
    return (k << 7) + ((((n >> 2) ^ ((k & 3) << 1)) << 2) | (n & 3));
}
// ordered-uint encode for float atomic max/min
__device__ __forceinline__ unsigned fenc(float f) {
    unsigned u = __float_as_uint(f);
    return (u & 0x80000000u) ? ~u : (u | 0x80000000u);
}
__device__ __forceinline__ float fdec(unsigned u) {
    unsigned b = (u & 0x80000000u) ? (u ^ 0x80000000u) : ~u;
    return __uint_as_float(b);
}

// ---------------- cp.async 3-stage pipelined tf32 MMA core ----------------
// BM=128, BK=16, 256 threads. BN=128: warps 2x4, MT=4. BN=64: warps 4x2, MT=2.
// BT=0: pb1/pb2 per-thread B row pointers ([N,K] K-contig).
// BT=1: pb1 = B + n0 ([K,N] N-contig), stride ldbt (B stage kept 128-wide).
template<int BN, int BT>
__device__ __forceinline__ void mma_core(
    const float* pa1, int sa1, const float* pa2, int sa2,
    const float* pb1, const float* pb2, int ldbt,
    int K, float* smem, float (&acc)[(BN == 128) ? 4 : 2][4][4])
{
    constexpr int MT  = (BN == 128) ? 4 : 2;
    constexpr int WN  = (BN == 128) ? 4 : 2;
    constexpr int ASZ = 128 * 16;
    constexpr int BSZ = (BT == 1) ? 128 * 16 : BN * 16;
    constexpr int STG = ASZ + BSZ;
    const int tid = threadIdx.x;
    const int lane = tid & 31, wid = tid >> 5;
    const int wm = wid / WN, wn = wid % WN;
    const int gid = lane >> 2, tig = lane & 3;
    const int crow = tid >> 2, cq = tid & 3;
    const int coff  = (crow << 4) + ((cq ^ ((crow >> 1) & 3)) << 2);
    const int coff2 = ((crow + 64) << 4) + ((cq ^ ((crow >> 1) & 3)) << 2);
    const int q4 = 4 * cq;
    const int kk = tid >> 4, ng = tid & 15;           // BT mode
    const int bco1 = swzt(kk, 4 * ng);
    const int bco2 = swzt(kk, 4 * (ng + 16));

    auto issue = [&](int i) {
        float* As = smem + (i % 3) * STG;
        float* Bs = As + ASZ;
        const int kt = i << 4;
        cp_async16(As + coff,  pa1 + kt + q4, sa1);
        cp_async16(As + coff2, pa2 + kt + q4, sa2);
        if (BT) {
            const float* bp = pb1 + (size_t)(kt + kk) * ldbt;
            cp_async16(Bs + bco1, bp + 4 * ng, 16);
            if (BN == 128) cp_async16(Bs + bco2, bp + 4 * ng + 64, 16);
        } else {
            cp_async16(Bs + coff,  pb1 + kt + q4, 16);
            if (BN == 128) cp_async16(Bs + coff2, pb2 + kt + q4, 16);
        }
        asm volatile("cp.async.commit_group;\n" ::: "memory");
    };
    auto compute = [&](int s) {
        const float* As = smem + s * STG;
        const float* Bs = As + ASZ;
#pragma unroll
        for (int c = 0; c < 2; c++) {
            const int k0 = c * 8 + tig;
            uint32_t af[MT][4];
#pragma unroll
            for (int mt = 0; mt < MT; mt++) {
                const int ar = wm * (MT * 16) + mt * 16 + gid;
                af[mt][0] = __float_as_uint(As[swz(ar, k0)]);
                af[mt][1] = __float_as_uint(As[swz(ar + 8, k0)]);
                af[mt][2] = __float_as_uint(As[swz(ar, k0 + 4)]);
                af[mt][3] = __float_as_uint(As[swz(ar + 8, k0 + 4)]);
            }
#pragma unroll
            for (int nt = 0; nt < 4; nt++) {
                const int br = wn * 32 + nt * 8 + gid;
                uint32_t b0, b1;
                if (BT) {
                    b0 = __float_as_uint(Bs[swzt(k0, br)]);
                    b1 = __float_as_uint(Bs[swzt(k0 + 4, br)]);
                } else {
                    b0 = __float_as_uint(Bs[swz(br, k0)]);
                    b1 = __float_as_uint(Bs[swz(br, k0 + 4)]);
                }
#pragma unroll
                for (int mt = 0; mt < MT; mt++) mma_op(acc[mt][nt], af[mt], b0, b1);
            }
        }
    };

    const int nk = K >> 4;
    issue(0);
    if (nk > 1) issue(1);
    for (int i = 0; i < nk; i++) {
        if (i + 1 < nk) asm volatile("cp.async.wait_group 1;\n" ::: "memory");
        else            asm volatile("cp.async.wait_group 0;\n" ::: "memory");
        __syncthreads();
        if (i + 2 < nk) issue(i + 2);
        compute(i % 3);
    }
}

// ---------------- fused QKV projection (z: 0=Q,1=K,2=V-transposed) ----------------
// Also zeroes the attention row-stats + routing counters (read only after qk).
__global__ __launch_bounds__(256, 2) void qkv_mma(
    const float* __restrict__ A,
    const float* __restrict__ Wq, const float* __restrict__ bq,
    const float* __restrict__ Wk, const float* __restrict__ bk,
    const float* __restrict__ Wv, const float* __restrict__ bv)
{
    __shared__ float smem[3 * (128 * 16 + 128 * 16)];
    const int tid = threadIdx.x;
    // fold zero_stats: 288 CTAs x 256 threads cover ROWS_TOT
    {
        int gbid = (blockIdx.z * gridDim.y + blockIdx.y) * gridDim.x + blockIdx.x;
        int gidx = gbid * 256 + tid;
        if (gidx < ROWS_TOT) {
            g_rsum[gidx] = 0.f;
            g_rsumsq[gidx] = 0.f;
            g_rmaxe[gidx] = fenc(-3e38f);
            g_rmine[gidx] = fenc(3e38f);
        }
        if (gidx < NE) g_cnt[gidx] = 0;
    }
    const int lane = tid & 31, wid = tid >> 5;
    const int wm = wid / 4, wn = wid % 4;
    const int gid = lane >> 2, tig = lane & 3;
    const int crow = tid >> 2;
    float acc[4][4][4] = {};
    const int which = blockIdx.z;
    const float* W = (which == 0) ? Wq : (which == 1) ? Wk : Wv;
    const float* bias = (which == 0) ? bq : (which == 1) ? bk : bv;
    const int m0 = blockIdx.y * 128, n0 = blockIdx.x * 128;
    mma_core<128, 0>(A + (size_t)(m0 + crow) * DIM, 16,
                     A + (size_t)(m0 + crow + 64) * DIM, 16,
                     W + (size_t)(n0 + crow) * DIM,
                     W + (size_t)(n0 + crow + 64) * DIM, 0,
                     DIM, smem, acc);
#pragma unroll
    for (int mt = 0; mt < 4; mt++) {
#pragma unroll
        for (int nt = 0; nt < 4; nt++) {
            int row = m0 + wm * 64 + mt * 16 + gid;
            int col = n0 + wn * 32 + nt * 8 + 2 * tig;
            float c0 = acc[mt][nt][0] + bias[col];
            float c1 = acc[mt][nt][1] + bias[col + 1];
            float c2 = acc[mt][nt][2] + bias[col];
            float c3 = acc[mt][nt][3] + bias[col + 1];
            if (which == 0) {
                *(float2*)(g_Q + (size_t)row * DIM + col) = make_float2(c0, c1);
                *(float2*)(g_Q + (size_t)(row + 8) * DIM + col) = make_float2(c2, c3);
            } else if (which == 1) {
                *(float2*)(g_K + (size_t)row * DIM + col) = make_float2(c0, c1);
                *(float2*)(g_K + (size_t)(row + 8) * DIM + col) = make_float2(c2, c3);
            } else {
                float vals[4] = {c0, c1, c2, c3};
#pragma unroll
                for (int q = 0; q < 4; q++) {
                    int rr = row + (q >> 1) * 8;
                    int cc = col + (q & 1);
                    int bb = rr >> 10, tt = rr & 1023;
                    int h = cc >> 6, d = cc & 63;
                    g_Vt[(((size_t)bb * NH + h) * HD + d) * SEQ + tt] = vals[q];
                }
            }
        }
    }
}

// ---------------- O projection (BN=64: 192 CTAs) ----------------
__global__ __launch_bounds__(256, 2) void oproj_mma(
    const float* __restrict__ A, const float* __restrict__ W,
    const float* __restrict__ bias, float* __restrict__ C)
{
    __shared__ float smem[3 * (128 * 16 + 64 * 16)];
    const int tid = threadIdx.x;
    const int lane = tid & 31, wid = tid >> 5;
    const int wm = wid / 2, wn = wid % 2;
    const int gid = lane >> 2, tig = lane & 3;
    const int crow = tid >> 2;
    float acc[2][4][4] = {};
    const int m0 = blockIdx.y * 128, n0 = blockIdx.x * 64;
    mma_core<64, 0>(A + (size_t)(m0 + crow) * DIM, 16,
                    A + (size_t)(m0 + crow + 64) * DIM, 16,
                    W + (size_t)(n0 + crow) * DIM, nullptr, 0,
                    DIM, smem, acc);
#pragma unroll
    for (int mt = 0; mt < 2; mt++) {
#pragma unroll
        for (int nt = 0; nt < 4; nt++) {
            int row = m0 + wm * 32 + mt * 16 + gid;
            int col = n0 + wn * 32 + nt * 8 + 2 * tig;
            float b0 = bias[col], b1 = bias[col + 1];
            *(float2*)(C + (size_t)row * DIM + col) =
                make_float2(acc[mt][nt][0] + b0, acc[mt][nt][1] + b1);
            *(float2*)(C + (size_t)(row + 8) * DIM + col) =
                make_float2(acc[mt][nt][2] + b0, acc[mt][nt][3] + b1);
        }
    }
}

// ---------------- QK^T + per-row stats epilogue (fp16 P store) ----------------
__global__ __launch_bounds__(256, 2) void qk_mma(
    const float* __restrict__ Q, const float* __restrict__ Kt, float scale)
{
    __shared__ float smem[3 * (128 * 16 + 128 * 16)];
    const int tid = threadIdx.x;
    const int lane = tid & 31, wid = tid >> 5;
    const int wm = wid / 4, wn = wid % 4;
    const int gid = lane >> 2, tig = lane & 3;
    const int crow = tid >> 2;
    float acc[4][4][4] = {};
    const int z = blockIdx.z, b = z / NH, h = z % NH;
    const int m0 = blockIdx.y * 128, n0 = blockIdx.x * 128;
    const float* Ab = Q + (size_t)b * SEQ * DIM + h * HD;
    const float* Bb = Kt + (size_t)b * SEQ * DIM + h * HD;
    __half* Cb = g_P + (size_t)z * SEQ * SEQ;
    mma_core<128, 0>(Ab + (size_t)(m0 + crow) * DIM, 16,
                     Ab + (size_t)(m0 + crow + 64) * DIM, 16,
                     Bb + (size_t)(n0 + crow) * DIM,
                     Bb + (size_t)(n0 + crow + 64) * DIM, 0,
                     HD, smem, acc);
    const size_t rowbase = (size_t)z * SEQ + m0;
#pragma unroll
    for (int mt = 0; mt < 4; mt++) {
        float s0 = 0.f, q0 = 0.f, s8 = 0.f, q8 = 0.f;
        float mx0 = -3e38f, mn0 = 3e38f, mx8 = -3e38f, mn8 = 3e38f;
#pragma unroll
        for (int nt = 0; nt < 4; nt++) {
            int row = m0 + wm * 64 + mt * 16 + gid;
            int col = n0 + wn * 32 + nt * 8 + 2 * tig;
            float v0 = acc[mt][nt][0] * scale, v1 = acc[mt][nt][1] * scale;
            float v2 = acc[mt][nt][2] * scale, v3 = acc[mt][nt][3] * scale;
            *(__half2*)(Cb + (size_t)row * SEQ + col) = __floats2half2_rn(v0, v1);
            *(__half2*)(Cb + (size_t)(row + 8) * SEQ + col) = __floats2half2_rn(v2, v3);
            s0 += v0 + v1; q0 += v0 * v0 + v1 * v1;
            mx0 = fmaxf(mx0, fmaxf(v0, v1)); mn0 = fminf(mn0, fminf(v0, v1));
            s8 += v2 + v3; q8 += v2 * v2 + v3 * v3;
            mx8 = fmaxf(mx8, fmaxf(v2, v3)); mn8 = fminf(mn8, fminf(v2, v3));
        }
#pragma unroll
        for (int o = 1; o < 4; o <<= 1) {
            s0 += __shfl_xor_sync(~0u, s0, o); q0 += __shfl_xor_sync(~0u, q0, o);
            s8 += __shfl_xor_sync(~0u, s8, o); q8 += __shfl_xor_sync(~0u, q8, o);
            mx0 = fmaxf(mx0, __shfl_xor_sync(~0u, mx0, o));
            mn0 = fminf(mn0, __shfl_xor_sync(~0u, mn0, o));
            mx8 = fmaxf(mx8, __shfl_xor_sync(~0u, mx8, o));
            mn8 = fminf(mn8, __shfl_xor_sync(~0u, mn8, o));
        }
        if (tig == 0) {
            size_t r0 = rowbase + wm * 64 + mt * 16 + gid;
            atomicAdd(&g_rsum[r0], s0);   atomicAdd(&g_rsumsq[r0], q0);
            atomicMax(&g_rmaxe[r0], fenc(mx0)); atomicMin(&g_rmine[r0], fenc(mn0));
            atomicAdd(&g_rsum[r0 + 8], s8); atomicAdd(&g_rsumsq[r0 + 8], q8);
            atomicMax(&g_rmaxe[r0 + 8], fenc(mx8)); atomicMin(&g_rmine[r0 + 8], fenc(mn8));
        }
    }
}

// ---------------- fused zscore-softmax + P@V (BM=128, fp16 P reads) ----------------
__global__ __launch_bounds__(256, 2) void pv2_mma(const float* __restrict__ gamma)
{
    __shared__ float Asm[2][128 * 16];
    __shared__ float Bsm[3][64 * 16];
    __shared__ float denom_s[128];
    __shared__ float2 rowc_s[128];
    const int tid = threadIdx.x;
    const int lane = tid & 31, wid = tid >> 5;
    const int wm = wid / 2, wn = wid % 2;
    const int gid = lane >> 2, tig = lane & 3;
    // B-side indexing (64 rows x 4 quarters)
    const int browc = tid >> 2, bq = tid & 3;
    const int bcoff = (browc << 4) + ((bq ^ ((browc >> 1) & 3)) << 2);
    // A-side indexing (128 rows x 2 half-chunks of 8 halves)
    const int arow = tid >> 1, acq = tid & 1;
    const int axor = (arow >> 1) & 3;
    const int asoff0 = (arow << 4) + (((2 * acq)     ^ axor) << 2);
    const int asoff1 = (arow << 4) + (((2 * acq + 1) ^ axor) << 2);
    float acc[2][4][4] = {};
    const int z = blockIdx.z, b = z / NH, h = z % NH;
    const int m0 = blockIdx.y * 128;
    const __half* Arow = g_P + ((size_t)z * SEQ + m0 + arow) * SEQ + 8 * acq;
    const float* Brow = g_Vt + (size_t)z * HD * SEQ + (size_t)browc * SEQ;
    float esum = 0.f;
    constexpr int nk = SEQ / 16;  // 64

    auto issueB = [&](int i) {
        cp_async16(Bsm[i % 3] + bcoff, Brow + (i << 4) + 4 * bq, 16);
        asm volatile("cp.async.commit_group;\n" ::: "memory");
    };
    auto compute = [&](const float* As, const float* Bs) {
#pragma unroll
        for (int c = 0; c < 2; c++) {
            const int k0 = c * 8 + tig;
            uint32_t af[2][4];
#pragma unroll
            for (int mt = 0; mt < 2; mt++) {
                const int ar = wm * 32 + mt * 16 + gid;
                af[mt][0] = __float_as_uint(As[swz(ar, k0)]);
                af[mt][1] = __float_as_uint(As[swz(ar + 8, k0)]);
                af[mt][2] = __float_as_uint(As[swz(ar, k0 + 4)]);
                af[mt][3] = __float_as_uint(As[swz(ar + 8, k0 + 4)]);
            }
#pragma unroll
            for (int nt = 0; nt < 4; nt++) {
                const int br = wn * 32 + nt * 8 + gid;
                uint32_t b0 = __float_as_uint(Bs[swz(br, k0)]);
                uint32_t b1 = __float_as_uint(Bs[swz(br, k0 + 4)]);
#pragma unroll
                for (int mt = 0; mt < 2; mt++) mma_op(acc[mt][nt], af[mt], b0, b1);
            }
        }
    };

    issueB(0);
    issueB(1);
    // per-row zscore coefficients computed locally (rows m0..m0+127)
    if (tid < 128) {
        size_t i = (size_t)z * SEQ + m0 + tid;
        float s = g_rsum[i], q = g_rsumsq[i];
        float mean = s * (1.f / SEQ);
        float var = fmaxf((q - s * s * (1.f / SEQ)) * (1.f / (SEQ - 1)), 0.f);
        float c1 = (*gamma) / (sqrtf(var) + EPSZ);
        float mx = fdec(g_rmaxe[i]), mn = fdec(g_rmine[i]);
        float zmax = fmaxf(c1 * (mx - mean), c1 * (mn - mean));
        rowc_s[tid] = make_float2(c1, -mean * c1 - zmax);
    }
    __syncthreads();
    const float2 rc = rowc_s[arow];
    uint4 a0 = *(const uint4*)(Arow);   // 8 halves
    for (int i = 0; i < nk; i++) {
        if (i + 1 < nk) asm volatile("cp.async.wait_group 1;\n" ::: "memory");
        else            asm volatile("cp.async.wait_group 0;\n" ::: "memory");
        __syncthreads();                       // B(i) visible; compute(i-1) done
        if (i + 2 < nk) issueB(i + 2);
        // convert 8 halves -> exp
        float2 f0 = __half22float2(*(__half2*)&a0.x);
        float2 f1 = __half22float2(*(__half2*)&a0.y);
        float2 f2 = __half22float2(*(__half2*)&a0.z);
        float2 f3 = __half22float2(*(__half2*)&a0.w);
        float4 e0, e1;
        e0.x = __expf(fmaf(f0.x, rc.x, rc.y));
        e0.y = __expf(fmaf(f0.y, rc.x, rc.y));
        e0.z = __expf(fmaf(f1.x, rc.x, rc.y));
        e0.w = __expf(fmaf(f1.y, rc.x, rc.y));
        e1.x = __expf(fmaf(f2.x, rc.x, rc.y));
        e1.y = __expf(fmaf(f2.y, rc.x, rc.y));
        e1.z = __expf(fmaf(f3.x, rc.x, rc.y));
        e1.w = __expf(fmaf(f3.y, rc.x, rc.y));
        esum += e0.x + e0.y + e0.z + e0.w + e1.x + e1.y + e1.z + e1.w;
        *(float4*)(Asm[i & 1] + asoff0) = e0;
        *(float4*)(Asm[i & 1] + asoff1) = e1;
        if (i + 1 < nk) a0 = *(const uint4*)(Arow + ((i + 1) << 4));
        __syncthreads();                       // A STS visible
        compute(Asm[i & 1], Bsm[i % 3]);
    }
    // row exp-sums -> denominators (2 threads per row)
    esum += __shfl_xor_sync(~0u, esum, 1);
    if (acq == 0) denom_s[arow] = esum;
    __syncthreads();
#pragma unroll
    for (int mt = 0; mt < 2; mt++) {
#pragma unroll
        for (int nt = 0; nt < 4; nt++) {
            int ro = wm * 32 + mt * 16 + gid;
            int col = wn * 32 + nt * 8 + 2 * tig;
            float r0 = 1.f / denom_s[ro];
            float r8 = 1.f / denom_s[ro + 8];
            int row = m0 + ro;
            float* c0 = g_attn + ((size_t)(b * SEQ + row)) * DIM + h * HD + col;
            float* c1 = g_attn + ((size_t)(b * SEQ + row + 8)) * DIM + h * HD + col;
            *(float2*)c0 = make_float2(acc[mt][nt][0] * r0, acc[mt][nt][1] * r0);
            *(float2*)c1 = make_float2(acc[mt][nt][2] * r8, acc[mt][nt][3] * r8);
        }
    }
}

// ---------------- FF1 (TN): H1 = relu(x[list] @ W1[e] + b1) ----------------
__global__ __launch_bounds__(256, 2) void ff1_mma(
    const float* __restrict__ x, const float* __restrict__ W1,
    const float* __restrict__ b1)
{
    const int e = blockIdx.z;
    const int cnt = g_cnt[e];
    const int m0 = blockIdx.y * 128;
    if (m0 >= cnt) return;
    __shared__ float smem[3 * (128 * 16 + 128 * 16)];
    const int tid = threadIdx.x;
    const int lane = tid & 31, wid = tid >> 5;
    const int wm = wid / 4, wn = wid % 4;
    const int gid = lane >> 2, tig = lane & 3;
    const int crow = tid >> 2;
    float acc[4][4][4] = {};
    const int n0 = blockIdx.x * 128;
    const int r1 = m0 + crow, r2 = m0 + crow + 64;
    const float* pa1 = x; int sa1 = 0;
    const float* pa2 = x; int sa2 = 0;
    if (r1 < cnt) { pa1 = x + (size_t)g_list[e * NTOK + r1] * DIM; sa1 = 16; }
    if (r2 < cnt) { pa2 = x + (size_t)g_list[e * NTOK + r2] * DIM; sa2 = 16; }
    const float* Bb = W1 + (size_t)e * DIM * FFD + n0;   // [K=DIM][N=FFD]
    const float* bb = b1 + e * FFD;
    float* Hout = g_H1 + (size_t)e * NTOK * FFD;
    mma_core<128, 1>(pa1, sa1, pa2, sa2, Bb, nullptr, FFD, DIM, smem, acc);
#pragma unroll
    for (int mt = 0; mt < 4; mt++) {
#pragma unroll
        for (int nt = 0; nt < 4; nt++) {
            int lm = m0 + wm * 64 + mt * 16 + gid;
            int col = n0 + wn * 32 + nt * 8 + 2 * tig;
            float b0 = bb[col], b1v = bb[col + 1];
            if (lm < cnt) {
                *(float2*)(Hout + (size_t)lm * FFD + col) =
                    make_float2(fmaxf(acc[mt][nt][0] + b0, 0.f), fmaxf(acc[mt][nt][1] + b1v, 0.f));
            }
            if (lm + 8 < cnt) {
                *(float2*)(Hout + (size_t)(lm + 8) * FFD + col) =
                    make_float2(fmaxf(acc[mt][nt][2] + b0, 0.f), fmaxf(acc[mt][nt][3] + b1v, 0.f));
            }
        }
    }
}

// ---------------- FF2 (TN, BN=64): Y = H1 @ W2[e] + b2 ----------------
__global__ __launch_bounds__(256, 2) void ff2_mma(
    const float* __restrict__ W2, const float* __restrict__ b2)
{
    const int e = blockIdx.z;
    const int cnt = g_cnt[e];
    const int m0 = blockIdx.y * 128;
    if (m0 >= cnt) return;
    __shared__ float smem[3 * (128 * 16 + 128 * 16)];
    const int tid = threadIdx.x;
    const int lane = tid & 31, wid = tid >> 5;
    const int wm = wid / 2, wn = wid % 2;
    const int gid = lane >> 2, tig = lane & 3;
    const int crow = tid >> 2;
    float acc[2][4][4] = {};
    const int n0 = blockIdx.x * 64;
    const float* Ab = g_H1 + (size_t)e * NTOK * FFD;
    const int r1 = m0 + crow, r2 = m0 + crow + 64;
    const float* pa1 = Ab; int sa1 = 0;
    const float* pa2 = Ab; int sa2 = 0;
    if (r1 < cnt) { pa1 = Ab + (size_t)r1 * FFD; sa1 = 16; }
    if (r2 < cnt) { pa2 = Ab + (size_t)r2 * FFD; sa2 = 16; }
    const float* Bb = W2 + (size_t)e * FFD * DIM + n0;   // [K=FFD][N=DIM]
    const float* bb = b2 + e * DIM;
    float* Yout = g_Y + (size_t)e * NTOK * DIM;
    mma_core<64, 1>(pa1, sa1, pa2, sa2, Bb, nullptr, DIM, FFD, smem, acc);
#pragma unroll
    for (int mt = 0; mt < 2; mt++) {
#pragma unroll
        for (int nt = 0; nt < 4; nt++) {
            int lm = m0 + wm * 32 + mt * 16 + gid;
            int col = n0 + wn * 32 + nt * 8 + 2 * tig;
            float b0 = bb[col], b1v = bb[col + 1];
            if (lm < cnt) {
                *(float2*)(Yout + (size_t)lm * DIM + col) =
                    make_float2(acc[mt][nt][0] + b0, acc[mt][nt][1] + b1v);
            }
            if (lm + 8 < cnt) {
                *(float2*)(Yout + (size_t)(lm + 8) * DIM + col) =
                    make_float2(acc[mt][nt][2] + b0, acc[mt][nt][3] + b1v);
            }
        }
    }
}

// ---------------- reductions ----------------
__device__ __forceinline__ float blockReduceSum(float v) {
    __shared__ float red[8];
    int lane = threadIdx.x & 31, wid = threadIdx.x >> 5;
#pragma unroll
    for (int o = 16; o > 0; o >>= 1) v += __shfl_xor_sync(0xffffffffu, v, o);
    __syncthreads();
    if (lane == 0) red[wid] = v;
    __syncthreads();
    float r = (lane < 8) ? red[lane] : 0.f;
#pragma unroll
    for (int o = 16; o > 0; o >>= 1) r += __shfl_xor_sync(0xffffffffu, r, o);
    return r;
}

// ---------------- LN1 + fused gating ----------------
__global__ void add_ln1_gate_kernel(const float* __restrict__ a, const float* __restrict__ b,
                                    const float* __restrict__ g, const float* __restrict__ be,
                                    const float* __restrict__ Wg, const float* __restrict__ bg,
                                    float* __restrict__ out) {
    int t = blockIdx.x, tid = threadIdx.x;
    const float* ar = a + (size_t)t * DIM;
    const float* br = b + (size_t)t * DIM;
    float v[3];
#pragma unroll
    for (int i = 0; i < 3; i++) v[i] = ar[tid + i * 256] + br[tid + i * 256];
    float mean = blockReduceSum(v[0] + v[1] + v[2]) * (1.f / DIM);
    float sq = 0.f;
#pragma unroll
    for (int i = 0; i < 3; i++) { v[i] -= mean; sq += v[i] * v[i]; }
    float var = blockReduceSum(sq) * (1.f / DIM);
    float r = rsqrtf(var + EPSLN);
    float xv[3];
    float gp0 = 0.f, gp1 = 0.f, gp2 = 0.f, gp3 = 0.f;
#pragma unroll
    for (int i = 0; i < 3; i++) {
        int c = tid + i * 256;
        xv[i] = v[i] * r * g[c] + be[c];
        out[(size_t)t * DIM + c] = xv[i];
        gp0 += xv[i] * Wg[c];
        gp1 += xv[i] * Wg[DIM + c];
        gp2 += xv[i] * Wg[2 * DIM + c];
        gp3 += xv[i] * Wg[3 * DIM + c];
    }
    float s0 = blockReduceSum(gp0);
    float s1 = blockReduceSum(gp1);
    float s2 = blockReduceSum(gp2);
    float s3 = blockReduceSum(gp3);
    if (tid == 0) {
        float s[4] = {s0 + bg[0], s1 + bg[1], s2 + bg[2], s3 + bg[3]};
        float mx = fmaxf(fmaxf(s[0], s[1]), fmaxf(s[2], s[3]));
        float p[4], sum = 0.f;
#pragma unroll
        for (int e = 0; e < 4; e++) { p[e] = expf(s[e] - mx); sum += p[e]; }
        float ri = 1.f / sum;
#pragma unroll
        for (int e = 0; e < 4; e++) p[e] *= ri;
        int i1 = 0;
#pragma unroll
        for (int e = 1; e < 4; e++) if (p[e] > p[i1]) i1 = e;
        int i2 = (i1 == 0) ? 1 : 0;
#pragma unroll
        for (int e = 0; e < 4; e++) if (e != i1 && p[e] > p[i2]) i2 = e;
        int slot = atomicAdd(&g_cnt[i1], 1);
        g_list[i1 * NTOK + slot] = t;
        g_tslot[t] = i1 * NTOK + slot;
        g_tw[t] = p[i1];
        slot = atomicAdd(&g_cnt[i2], 1);
        g_list[i2 * NTOK + slot] = t;
        g_tslot[NTOK + t] = i2 * NTOK + slot;
        g_tw[NTOK + t] = p[i2];
    }
}

// ---------------- LN2 + MoE combine ----------------
__global__ void add_ln2_moe_kernel(const float* __restrict__ x,
                                   const float* __restrict__ g, const float* __restrict__ be,
                                   float* __restrict__ out) {
    int t = blockIdx.x, tid = threadIdx.x;
    int s1 = g_tslot[t], s2 = g_tslot[NTOK + t];
    float w1 = g_tw[t], w2 = g_tw[NTOK + t];
    const float* y1 = g_Y + (size_t)s1 * DIM;
    const float* y2 = g_Y + (size_t)s2 * DIM;
    const float* xr = x + (size_t)t * DIM;
    float v[3];
#pragma unroll
    for (int i = 0; i < 3; i++) {
        int c = tid + i * 256;
        v[i] = xr[c] + w1 * y1[c] + w2 * y2[c];
    }
    float mean = blockReduceSum(v[0] + v[1] + v[2]) * (1.f / DIM);
    float sq = 0.f;
#pragma unroll
    for (int i = 0; i < 3; i++) { v[i] -= mean; sq += v[i] * v[i]; }
    float var = blockReduceSum(sq) * (1.f / DIM);
    float r = rsqrtf(var + EPSLN);
#pragma unroll
    for (int i = 0; i < 3; i++) {
        int c = tid + i * 256;
        out[(size_t)t * DIM + c] = v[i] * r * g[c] + be[c];
    }
}

// ---------------- launch ----------------
extern "C" void kernel_launch(void* const* d_in, const int* in_sizes, int n_in,
                              void* d_out, int out_size) {
    const float* src  = (const float*)d_in[0];
    const float* Wq = (const float*)d_in[2];
    const float* bq = (const float*)d_in[3];
    const float* Wk = (const float*)d_in[4];
    const float* bk = (const float*)d_in[5];
    const float* Wv = (const float*)d_in[6];
    const float* bv = (const float*)d_in[7];
    const float* Wo = (const float*)d_in[8];
    const float* bo = (const float*)d_in[9];
    const float* gamma = (const float*)d_in[10];
    const float* ln1g = (const float*)d_in[11];
    const float* ln1b = (const float*)d_in[12];
    const float* ln2g = (const float*)d_in[13];
    const float* ln2b = (const float*)d_in[14];
    const float* Wg = (const float*)d_in[15];
    const float* bg = (const float*)d_in[16];
    const float* W1 = (const float*)d_in[17];
    const float* b1 = (const float*)d_in[18];
    const float* W2 = (const float*)d_in[19];
    const float* b2 = (const float*)d_in[20];
    float* out = (float*)d_out;

    float *Qp, *Kp, *attnp, *attnop, *xp;
    cudaGetSymbolAddress((void**)&Qp, g_Q);
    cudaGetSymbolAddress((void**)&Kp, g_K);
    cudaGetSymbolAddress((void**)&attnp, g_attn);
    cudaGetSymbolAddress((void**)&attnop, g_attno);
    cudaGetSymbolAddress((void**)&xp, g_x);

    // fused QKV projections (V written transposed) + stats/counter zeroing
    qkv_mma<<<dim3(DIM / 128, NTOK / 128, 3), 256>>>(src, Wq, bq, Wk, bk, Wv, bv);

    // logits = scale * Q K^T  (+ per-row stats, fp16 P store)
    qk_mma<<<dim3(SEQ / 128, SEQ / 128, BHZ), 256>>>(Qp, Kp, 0.125f);

    // fused zscore+softmax+PV (rowc in prologue, fp16 P reads)
    pv2_mma<<<dim3(1, SEQ / 128, BHZ), 256>>>(gamma);

    // O projection (BN=64: 192 CTAs)
    oproj_mma<<<dim3(DIM / 64, NTOK / 128), 256>>>(attnp, Wo, bo, attnop);

    // x = LN1(src + attn_out), fused gating + routing
    add_ln1_gate_kernel<<<NTOK, 256>>>(src, attnop, ln1g, ln1b, Wg, bg, xp);

    // expert FFN (sparse top-2, TN weights; ff2 BN=64)
    ff1_mma<<<dim3(FFD / 128, NTOK / 128, NE), 256>>>(xp, W1, b1);
    ff2_mma<<<dim3(DIM / 64, NTOK / 128, NE), 256>>>(W2, b2);

    // out = LN2(x + combine(Y))
    add_ln2_moe_kernel<<<NTOK, 256>>>(xp, ln2g, ln2b, out);
}

// round 12
// speedup vs baseline: 1.2565x; 1.1874x over previous
#include <cuda_runtime.h>
#include <cuda_fp16.h>
#include <math.h>
#include <stdint.h>

// ---------------- problem constants ----------------
namespace {
constexpr int BATCH = 2;
constexpr int SEQ   = 1024;
constexpr int DIM   = 768;
constexpr int NH    = 12;
constexpr int HD    = 64;
constexpr int FFD   = 3072;
constexpr int NE    = 4;
constexpr int NTOK  = BATCH * SEQ;     // 2048
constexpr int BHZ   = BATCH * NH;      // 24
constexpr int ROWS_TOT = BHZ * SEQ;    // 24576 attention rows
constexpr float EPSZ  = 1e-5f;
constexpr float EPSLN = 1e-5f;
}

// ---------------- scratch (static device memory) ----------------
__device__ __align__(16) float g_Q[NTOK * DIM];
__device__ __align__(16) float g_K[NTOK * DIM];
__device__ __align__(16) float g_Vt[BHZ * HD * SEQ];           // V^T: [b][h][d][t]
__device__ __align__(16) __half g_P[(size_t)BHZ * SEQ * SEQ];  // raw scaled logits (fp16)
__device__ __align__(16) float g_attn[NTOK * DIM];
__device__ __align__(16) float g_attno[NTOK * DIM];
__device__ __align__(16) float g_x[NTOK * DIM];
__device__ __align__(16) __half g_xh[NTOK * DIM];              // x in fp16 (ff1 A operand)
__device__ __align__(16) __half g_H1h[(size_t)NE * NTOK * FFD];// expert hidden (fp16)
__device__ __align__(16) float g_Y[(size_t)NE * NTOK * DIM];
__device__ __align__(16) __half g_W1ht[(size_t)NE * FFD * DIM];// W1^T fp16: [e][ff][d]
__device__ __align__(16) __half g_W2ht[(size_t)NE * DIM * FFD];// W2^T fp16: [e][d][ff]
__device__ float g_rsum[ROWS_TOT];
__device__ float g_rsumsq[ROWS_TOT];
__device__ unsigned g_rmaxe[ROWS_TOT];
__device__ unsigned g_rmine[ROWS_TOT];
__device__ int   g_cnt[NE];
__device__ int   g_list[NE * NTOK];
__device__ int   g_tslot[2 * NTOK];
__device__ float g_tw[2 * NTOK];

// ---------------- primitives ----------------
__device__ __forceinline__ void mma_op(float* d, const uint32_t* a, uint32_t b0, uint32_t b1) {
    asm volatile(
        "mma.sync.aligned.m16n8k8.row.col.f32.tf32.tf32.f32 "
        "{%0,%1,%2,%3},{%4,%5,%6,%7},{%8,%9},{%0,%1,%2,%3};\n"
        : "+f"(d[0]), "+f"(d[1]), "+f"(d[2]), "+f"(d[3])
        : "r"(a[0]), "r"(a[1]), "r"(a[2]), "r"(a[3]), "r"(b0), "r"(b1));
}
__device__ __forceinline__ void mma_h(float* d, const uint32_t* a, uint32_t b0, uint32_t b1) {
    asm volatile(
        "mma.sync.aligned.m16n8k16.row.col.f32.f16.f16.f32 "
        "{%0,%1,%2,%3},{%4,%5,%6,%7},{%8,%9},{%0,%1,%2,%3};\n"
        : "+f"(d[0]), "+f"(d[1]), "+f"(d[2]), "+f"(d[3])
        : "r"(a[0]), "r"(a[1]), "r"(a[2]), "r"(a[3]), "r"(b0), "r"(b1));
}
__device__ __forceinline__ void cp_async16(float* dst, const float* src, int sz) {
    uint32_t s = (uint32_t)__cvta_generic_to_shared(dst);
    asm volatile("cp.async.cg.shared.global [%0], [%1], 16, %2;\n"
                 :: "r"(s), "l"(src), "r"(sz));
}
__device__ __forceinline__ void cp_async16u(uint32_t* dst, const __half* src, int sz) {
    uint32_t s = (uint32_t)__cvta_generic_to_shared(dst);
    asm volatile("cp.async.cg.shared.global [%0], [%1], 16, %2;\n"
                 :: "r"(s), "l"(src), "r"(sz));
}
// fp32 tile swizzle (rows x 16 floats)
__device__ __forceinline__ int swz(int row, int col) {
    return (row << 4) + (((((col >> 2) ^ ((row >> 1) & 3))) << 2) | (col & 3));
}
// fp16 tile: rows x 32 halves = 16 words; chunk-xor swizzle; w = word 0..15
__device__ __forceinline__ int swzh(int row, int w) {
    return (row << 4) + ((((w >> 2) ^ ((row >> 1) & 3)) << 2) | (w & 3));
}
__device__ __forceinline__ int chkoff(int row, int c) {   // 16B chunk word offset
    return (row << 4) + ((c ^ ((row >> 1) & 3)) << 2);
}
// ordered-uint encode for float atomic max/min
__device__ __forceinline__ unsigned fenc(float f) {
    unsigned u = __float_as_uint(f);
    return (u & 0x80000000u) ? ~u : (u | 0x80000000u);
}
__device__ __forceinline__ float fdec(unsigned u) {
    unsigned b = (u & 0x80000000u) ? (u ^ 0x80000000u) : ~u;
    return __uint_as_float(b);
}

// ---------------- cp.async 3-stage pipelined tf32 MMA core (unchanged) ----------------
template<int BN>
__device__ __forceinline__ void mma_core(
    const float* pa1, int sa1, const float* pa2, int sa2,
    const float* pb1, const float* pb2,
    int K, float* smem, float (&acc)[(BN == 128) ? 4 : 2][4][4])
{
    constexpr int MT  = (BN == 128) ? 4 : 2;
    constexpr int WN  = (BN == 128) ? 4 : 2;
    constexpr int ASZ = 128 * 16;
    constexpr int BSZ = BN * 16;
    constexpr int STG = ASZ + BSZ;
    const int tid = threadIdx.x;
    const int lane = tid & 31, wid = tid >> 5;
    const int wm = wid / WN, wn = wid % WN;
    const int gid = lane >> 2, tig = lane & 3;
    const int crow = tid >> 2, cq = tid & 3;
    const int coff  = (crow << 4) + ((cq ^ ((crow >> 1) & 3)) << 2);
    const int coff2 = ((crow + 64) << 4) + ((cq ^ ((crow >> 1) & 3)) << 2);
    const int q4 = 4 * cq;

    auto issue = [&](int i) {
        float* As = smem + (i % 3) * STG;
        float* Bs = As + ASZ;
        const int kt = i << 4;
        cp_async16(As + coff,  pa1 + kt + q4, sa1);
        cp_async16(As + coff2, pa2 + kt + q4, sa2);
        cp_async16(Bs + coff,  pb1 + kt + q4, 16);
        if (BN == 128) cp_async16(Bs + coff2, pb2 + kt + q4, 16);
        asm volatile("cp.async.commit_group;\n" ::: "memory");
    };
    auto compute = [&](int s) {
        const float* As = smem + s * STG;
        const float* Bs = As + ASZ;
#pragma unroll
        for (int c = 0; c < 2; c++) {
            const int k0 = c * 8 + tig;
            uint32_t af[MT][4];
#pragma unroll
            for (int mt = 0; mt < MT; mt++) {
                const int ar = wm * (MT * 16) + mt * 16 + gid;
                af[mt][0] = __float_as_uint(As[swz(ar, k0)]);
                af[mt][1] = __float_as_uint(As[swz(ar + 8, k0)]);
                af[mt][2] = __float_as_uint(As[swz(ar, k0 + 4)]);
                af[mt][3] = __float_as_uint(As[swz(ar + 8, k0 + 4)]);
            }
#pragma unroll
            for (int nt = 0; nt < 4; nt++) {
                const int br = wn * 32 + nt * 8 + gid;
                uint32_t b0 = __float_as_uint(Bs[swz(br, k0)]);
                uint32_t b1 = __float_as_uint(Bs[swz(br, k0 + 4)]);
#pragma unroll
                for (int mt = 0; mt < MT; mt++) mma_op(acc[mt][nt], af[mt], b0, b1);
            }
        }
    };

    const int nk = K >> 4;
    issue(0);
    if (nk > 1) issue(1);
    for (int i = 0; i < nk; i++) {
        if (i + 1 < nk) asm volatile("cp.async.wait_group 1;\n" ::: "memory");
        else            asm volatile("cp.async.wait_group 0;\n" ::: "memory");
        __syncthreads();
        if (i + 2 < nk) issue(i + 2);
        compute(i % 3);
    }
}

// ---------------- fp16 NT MMA core: BM=128, BK=32 halves, 3-stage ----------------
// A rows: per-thread ptr pa (row tid>>1), fp16 K-contiguous. B rows likewise.
template<int BN>
__device__ __forceinline__ void mma_core_h(
    const __half* pa, int sa, const __half* pb,
    int K, uint32_t* smem, float (&acc)[(BN == 128) ? 4 : 2][4][4])
{
    constexpr int MT  = (BN == 128) ? 4 : 2;
    constexpr int WN  = (BN == 128) ? 4 : 2;
    constexpr int ASZ = 128 * 16;            // words
    constexpr int BSZ = BN * 16;
    constexpr int STG = ASZ + BSZ;
    const int tid = threadIdx.x;
    const int lane = tid & 31, wid = tid >> 5;
    const int wm = wid / WN, wn = wid % WN;
    const int gid = lane >> 2, tig = lane & 3;
    const int arow_ld = tid >> 1, ac = (tid & 1) * 2;    // A: 2 chunks/thread
    const int aoff0 = chkoff(arow_ld, ac);
    const int aoff1 = chkoff(arow_ld, ac + 1);
    // B: BN=128 -> same mapping; BN=64 -> 1 chunk/thread
    const int brow_ld = (BN == 128) ? (tid >> 1) : (tid >> 2);
    const int bc = (BN == 128) ? ((tid & 1) * 2) : (tid & 3);
    const int boff0 = chkoff(brow_ld, bc);
    const int boff1 = chkoff(brow_ld, bc + 1);

    auto issue = [&](int i) {
        uint32_t* As = smem + (i % 3) * STG;
        uint32_t* Bs = As + ASZ;
        const int kt = i << 5;               // halves
        cp_async16u(As + aoff0, pa + kt + ac * 8, sa);
        cp_async16u(As + aoff1, pa + kt + ac * 8 + 8, sa);
        cp_async16u(Bs + boff0, pb + kt + bc * 8, 16);
        if (BN == 128) cp_async16u(Bs + boff1, pb + kt + bc * 8 + 8, 16);
        asm volatile("cp.async.commit_group;\n" ::: "memory");
    };
    auto compute = [&](int s) {
        const uint32_t* As = smem + s * STG;
        const uint32_t* Bs = As + ASZ;
#pragma unroll
        for (int ks = 0; ks < 2; ks++) {
            const int w0 = ks * 8 + tig;
            uint32_t af[MT][4];
#pragma unroll
            for (int mt = 0; mt < MT; mt++) {
                const int ar = wm * (MT * 16) + mt * 16 + gid;
                af[mt][0] = As[swzh(ar, w0)];
                af[mt][1] = As[swzh(ar + 8, w0)];
                af[mt][2] = As[swzh(ar, w0 + 4)];
                af[mt][3] = As[swzh(ar + 8, w0 + 4)];
            }
#pragma unroll
            for (int nt = 0; nt < 4; nt++) {
                const int br = wn * 32 + nt * 8 + gid;
                uint32_t b0 = Bs[swzh(br, w0)];
                uint32_t b1 = Bs[swzh(br, w0 + 4)];
#pragma unroll
                for (int mt = 0; mt < MT; mt++) mma_h(acc[mt][nt], af[mt], b0, b1);
            }
        }
    };

    const int nk = K >> 5;
    issue(0);
    if (nk > 1) issue(1);
    for (int i = 0; i < nk; i++) {
        if (i + 1 < nk) asm volatile("cp.async.wait_group 1;\n" ::: "memory");
        else            asm volatile("cp.async.wait_group 0;\n" ::: "memory");
        __syncthreads();
        if (i + 2 < nk) issue(i + 2);
        compute(i % 3);
    }
}

// ---------------- weight transpose + fp32->fp16: out[c][r] = half(in[r][c]) ----------------
__global__ void transpose_cvt(const float* __restrict__ in, __half* __restrict__ out,
                              int R, int C)
{
    __shared__ float t[32][33];
    int e = blockIdx.z;
    in += (size_t)e * R * C;
    out += (size_t)e * R * C;
    int c0 = blockIdx.x * 32, r0 = blockIdx.y * 32;
    int tx = threadIdx.x, ty = threadIdx.y;
#pragma unroll
    for (int i = 0; i < 32; i += 8)
        t[ty + i][tx] = in[(size_t)(r0 + ty + i) * C + c0 + tx];
    __syncthreads();
#pragma unroll
    for (int i = 0; i < 32; i += 8)
        out[(size_t)(c0 + ty + i) * R + r0 + tx] = __float2half(t[tx][ty + i]);
}

// ---------------- fused QKV projection (z: 0=Q,1=K,2=V-transposed) ----------------
__global__ __launch_bounds__(256, 2) void qkv_mma(
    const float* __restrict__ A,
    const float* __restrict__ Wq, const float* __restrict__ bq,
    const float* __restrict__ Wk, const float* __restrict__ bk,
    const float* __restrict__ Wv, const float* __restrict__ bv)
{
    __shared__ float smem[3 * (128 * 16 + 128 * 16)];
    const int tid = threadIdx.x;
    {
        int gbid = (blockIdx.z * gridDim.y + blockIdx.y) * gridDim.x + blockIdx.x;
        int gidx = gbid * 256 + tid;
        if (gidx < ROWS_TOT) {
            g_rsum[gidx] = 0.f;
            g_rsumsq[gidx] = 0.f;
            g_rmaxe[gidx] = fenc(-3e38f);
            g_rmine[gidx] = fenc(3e38f);
        }
        if (gidx < NE) g_cnt[gidx] = 0;
    }
    const int lane = tid & 31, wid = tid >> 5;
    const int wm = wid / 4, wn = wid % 4;
    const int gid = lane >> 2, tig = lane & 3;
    const int crow = tid >> 2;
    float acc[4][4][4] = {};
    const int which = blockIdx.z;
    const float* W = (which == 0) ? Wq : (which == 1) ? Wk : Wv;
    const float* bias = (which == 0) ? bq : (which == 1) ? bk : bv;
    const int m0 = blockIdx.y * 128, n0 = blockIdx.x * 128;
    mma_core<128>(A + (size_t)(m0 + crow) * DIM, 16,
                  A + (size_t)(m0 + crow + 64) * DIM, 16,
                  W + (size_t)(n0 + crow) * DIM,
                  W + (size_t)(n0 + crow + 64) * DIM,
                  DIM, smem, acc);
#pragma unroll
    for (int mt = 0; mt < 4; mt++) {
#pragma unroll
        for (int nt = 0; nt < 4; nt++) {
            int row = m0 + wm * 64 + mt * 16 + gid;
            int col = n0 + wn * 32 + nt * 8 + 2 * tig;
            float c0 = acc[mt][nt][0] + bias[col];
            float c1 = acc[mt][nt][1] + bias[col + 1];
            float c2 = acc[mt][nt][2] + bias[col];
            float c3 = acc[mt][nt][3] + bias[col + 1];
            if (which == 0) {
                *(float2*)(g_Q + (size_t)row * DIM + col) = make_float2(c0, c1);
                *(float2*)(g_Q + (size_t)(row + 8) * DIM + col) = make_float2(c2, c3);
            } else if (which == 1) {
                *(float2*)(g_K + (size_t)row * DIM + col) = make_float2(c0, c1);
                *(float2*)(g_K + (size_t)(row + 8) * DIM + col) = make_float2(c2, c3);
            } else {
                float vals[4] = {c0, c1, c2, c3};
#pragma unroll
                for (int q = 0; q < 4; q++) {
                    int rr = row + (q >> 1) * 8;
                    int cc = col + (q & 1);
                    int bb = rr >> 10, tt = rr & 1023;
                    int h = cc >> 6, d = cc & 63;
                    g_Vt[(((size_t)bb * NH + h) * HD + d) * SEQ + tt] = vals[q];
                }
            }
        }
    }
}

// ---------------- O projection (BN=64) ----------------
__global__ __launch_bounds__(256, 2) void oproj_mma(
    const float* __restrict__ A, const float* __restrict__ W,
    const float* __restrict__ bias, float* __restrict__ C)
{
    __shared__ float smem[3 * (128 * 16 + 64 * 16)];
    const int tid = threadIdx.x;
    const int lane = tid & 31, wid = tid >> 5;
    const int wm = wid / 2, wn = wid % 2;
    const int gid = lane >> 2, tig = lane & 3;
    const int crow = tid >> 2;
    float acc[2][4][4] = {};
    const int m0 = blockIdx.y * 128, n0 = blockIdx.x * 64;
    mma_core<64>(A + (size_t)(m0 + crow) * DIM, 16,
                 A + (size_t)(m0 + crow + 64) * DIM, 16,
                 W + (size_t)(n0 + crow) * DIM, nullptr,
                 DIM, smem, acc);
#pragma unroll
    for (int mt = 0; mt < 2; mt++) {
#pragma unroll
        for (int nt = 0; nt < 4; nt++) {
            int row = m0 + wm * 32 + mt * 16 + gid;
            int col = n0 + wn * 32 + nt * 8 + 2 * tig;
            float b0 = bias[col], b1 = bias[col + 1];
            *(float2*)(C + (size_t)row * DIM + col) =
                make_float2(acc[mt][nt][0] + b0, acc[mt][nt][1] + b1);
            *(float2*)(C + (size_t)(row + 8) * DIM + col) =
                make_float2(acc[mt][nt][2] + b0, acc[mt][nt][3] + b1);
        }
    }
}

// ---------------- QK^T + per-row stats epilogue (fp16 P store) ----------------
__global__ __launch_bounds__(256, 2) void qk_mma(
    const float* __restrict__ Q, const float* __restrict__ Kt, float scale)
{
    __shared__ float smem[3 * (128 * 16 + 128 * 16)];
    const int tid = threadIdx.x;
    const int lane = tid & 31, wid = tid >> 5;
    const int wm = wid / 4, wn = wid % 4;
    const int gid = lane >> 2, tig = lane & 3;
    const int crow = tid >> 2;
    float acc[4][4][4] = {};
    const int z = blockIdx.z, b = z / NH, h = z % NH;
    const int m0 = blockIdx.y * 128, n0 = blockIdx.x * 128;
    const float* Ab = Q + (size_t)b * SEQ * DIM + h * HD;
    const float* Bb = Kt + (size_t)b * SEQ * DIM + h * HD;
    __half* Cb = g_P + (size_t)z * SEQ * SEQ;
    mma_core<128>(Ab + (size_t)(m0 + crow) * DIM, 16,
                  Ab + (size_t)(m0 + crow + 64) * DIM, 16,
                  Bb + (size_t)(n0 + crow) * DIM,
                  Bb + (size_t)(n0 + crow + 64) * DIM,
                  HD, smem, acc);
    const size_t rowbase = (size_t)z * SEQ + m0;
#pragma unroll
    for (int mt = 0; mt < 4; mt++) {
        float s0 = 0.f, q0 = 0.f, s8 = 0.f, q8 = 0.f;
        float mx0 = -3e38f, mn0 = 3e38f, mx8 = -3e38f, mn8 = 3e38f;
#pragma unroll
        for (int nt = 0; nt < 4; nt++) {
            int row = m0 + wm * 64 + mt * 16 + gid;
            int col = n0 + wn * 32 + nt * 8 + 2 * tig;
            float v0 = acc[mt][nt][0] * scale, v1 = acc[mt][nt][1] * scale;
            float v2 = acc[mt][nt][2] * scale, v3 = acc[mt][nt][3] * scale;
            *(__half2*)(Cb + (size_t)row * SEQ + col) = __floats2half2_rn(v0, v1);
            *(__half2*)(Cb + (size_t)(row + 8) * SEQ + col) = __floats2half2_rn(v2, v3);
            s0 += v0 + v1; q0 += v0 * v0 + v1 * v1;
            mx0 = fmaxf(mx0, fmaxf(v0, v1)); mn0 = fminf(mn0, fminf(v0, v1));
            s8 += v2 + v3; q8 += v2 * v2 + v3 * v3;
            mx8 = fmaxf(mx8, fmaxf(v2, v3)); mn8 = fminf(mn8, fminf(v2, v3));
        }
#pragma unroll
        for (int o = 1; o < 4; o <<= 1) {
            s0 += __shfl_xor_sync(~0u, s0, o); q0 += __shfl_xor_sync(~0u, q0, o);
            s8 += __shfl_xor_sync(~0u, s8, o); q8 += __shfl_xor_sync(~0u, q8, o);
            mx0 = fmaxf(mx0, __shfl_xor_sync(~0u, mx0, o));
            mn0 = fminf(mn0, __shfl_xor_sync(~0u, mn0, o));
            mx8 = fmaxf(mx8, __shfl_xor_sync(~0u, mx8, o));
            mn8 = fminf(mn8, __shfl_xor_sync(~0u, mn8, o));
        }
        if (tig == 0) {
            size_t r0 = rowbase + wm * 64 + mt * 16 + gid;
            atomicAdd(&g_rsum[r0], s0);   atomicAdd(&g_rsumsq[r0], q0);
            atomicMax(&g_rmaxe[r0], fenc(mx0)); atomicMin(&g_rmine[r0], fenc(mn0));
            atomicAdd(&g_rsum[r0 + 8], s8); atomicAdd(&g_rsumsq[r0 + 8], q8);
            atomicMax(&g_rmaxe[r0 + 8], fenc(mx8)); atomicMin(&g_rmine[r0 + 8], fenc(mn8));
        }
    }
}

// ---------------- fused zscore-softmax + P@V (BM=128, fp16 P reads) ----------------
__global__ __launch_bounds__(256, 2) void pv2_mma(const float* __restrict__ gamma)
{
    __shared__ float Asm[2][128 * 16];
    __shared__ float Bsm[3][64 * 16];
    __shared__ float denom_s[128];
    __shared__ float2 rowc_s[128];
    const int tid = threadIdx.x;
    const int lane = tid & 31, wid = tid >> 5;
    const int wm = wid / 2, wn = wid % 2;
    const int gid = lane >> 2, tig = lane & 3;
    const int browc = tid >> 2, bq = tid & 3;
    const int bcoff = (browc << 4) + ((bq ^ ((browc >> 1) & 3)) << 2);
    const int arow = tid >> 1, acq = tid & 1;
    const int axor = (arow >> 1) & 3;
    const int asoff0 = (arow << 4) + (((2 * acq)     ^ axor) << 2);
    const int asoff1 = (arow << 4) + (((2 * acq + 1) ^ axor) << 2);
    float acc[2][4][4] = {};
    const int z = blockIdx.z, b = z / NH, h = z % NH;
    const int m0 = blockIdx.y * 128;
    const __half* Arow = g_P + ((size_t)z * SEQ + m0 + arow) * SEQ + 8 * acq;
    const float* Brow = g_Vt + (size_t)z * HD * SEQ + (size_t)browc * SEQ;
    float esum = 0.f;
    constexpr int nk = SEQ / 16;  // 64

    auto issueB = [&](int i) {
        cp_async16(Bsm[i % 3] + bcoff, Brow + (i << 4) + 4 * bq, 16);
        asm volatile("cp.async.commit_group;\n" ::: "memory");
    };
    auto compute = [&](const float* As, const float* Bs) {
#pragma unroll
        for (int c = 0; c < 2; c++) {
            const int k0 = c * 8 + tig;
            uint32_t af[2][4];
#pragma unroll
            for (int mt = 0; mt < 2; mt++) {
                const int ar = wm * 32 + mt * 16 + gid;
                af[mt][0] = __float_as_uint(As[swz(ar, k0)]);
                af[mt][1] = __float_as_uint(As[swz(ar + 8, k0)]);
                af[mt][2] = __float_as_uint(As[swz(ar, k0 + 4)]);
                af[mt][3] = __float_as_uint(As[swz(ar + 8, k0 + 4)]);
            }
#pragma unroll
            for (int nt = 0; nt < 4; nt++) {
                const int br = wn * 32 + nt * 8 + gid;
                uint32_t b0 = __float_as_uint(Bs[swz(br, k0)]);
                uint32_t b1 = __float_as_uint(Bs[swz(br, k0 + 4)]);
#pragma unroll
                for (int mt = 0; mt < 2; mt++) mma_op(acc[mt][nt], af[mt], b0, b1);
            }
        }
    };

    issueB(0);
    issueB(1);
    if (tid < 128) {
        size_t i = (size_t)z * SEQ + m0 + tid;
        float s = g_rsum[i], q = g_rsumsq[i];
        float mean = s * (1.f / SEQ);
        float var = fmaxf((q - s * s * (1.f / SEQ)) * (1.f / (SEQ - 1)), 0.f);
        float c1 = (*gamma) / (sqrtf(var) + EPSZ);
        float mx = fdec(g_rmaxe[i]), mn = fdec(g_rmine[i]);
        float zmax = fmaxf(c1 * (mx - mean), c1 * (mn - mean));
        rowc_s[tid] = make_float2(c1, -mean * c1 - zmax);
    }
    __syncthreads();
    const float2 rc = rowc_s[arow];
    uint4 a0 = *(const uint4*)(Arow);   // 8 halves
    for (int i = 0; i < nk; i++) {
        if (i + 1 < nk) asm volatile("cp.async.wait_group 1;\n" ::: "memory");
        else            asm volatile("cp.async.wait_group 0;\n" ::: "memory");
        __syncthreads();
        if (i + 2 < nk) issueB(i + 2);
        float2 f0 = __half22float2(*(__half2*)&a0.x);
        float2 f1 = __half22float2(*(__half2*)&a0.y);
        float2 f2 = __half22float2(*(__half2*)&a0.z);
        float2 f3 = __half22float2(*(__half2*)&a0.w);
        float4 e0, e1;
        e0.x = __expf(fmaf(f0.x, rc.x, rc.y));
        e0.y = __expf(fmaf(f0.y, rc.x, rc.y));
        e0.z = __expf(fmaf(f1.x, rc.x, rc.y));
        e0.w = __expf(fmaf(f1.y, rc.x, rc.y));
        e1.x = __expf(fmaf(f2.x, rc.x, rc.y));
        e1.y = __expf(fmaf(f2.y, rc.x, rc.y));
        e1.z = __expf(fmaf(f3.x, rc.x, rc.y));
        e1.w = __expf(fmaf(f3.y, rc.x, rc.y));
        esum += e0.x + e0.y + e0.z + e0.w + e1.x + e1.y + e1.z + e1.w;
        *(float4*)(Asm[i & 1] + asoff0) = e0;
        *(float4*)(Asm[i & 1] + asoff1) = e1;
        if (i + 1 < nk) a0 = *(const uint4*)(Arow + ((i + 1) << 4));
        __syncthreads();
        compute(Asm[i & 1], Bsm[i % 3]);
    }
    esum += __shfl_xor_sync(~0u, esum, 1);
    if (acq == 0) denom_s[arow] = esum;
    __syncthreads();
#pragma unroll
    for (int mt = 0; mt < 2; mt++) {
#pragma unroll
        for (int nt = 0; nt < 4; nt++) {
            int ro = wm * 32 + mt * 16 + gid;
            int col = wn * 32 + nt * 8 + 2 * tig;
            float r0 = 1.f / denom_s[ro];
            float r8 = 1.f / denom_s[ro + 8];
            int row = m0 + ro;
            float* c0 = g_attn + ((size_t)(b * SEQ + row)) * DIM + h * HD + col;
            float* c1 = g_attn + ((size_t)(b * SEQ + row + 8)) * DIM + h * HD + col;
            *(float2*)c0 = make_float2(acc[mt][nt][0] * r0, acc[mt][nt][1] * r0);
            *(float2*)c1 = make_float2(acc[mt][nt][2] * r8, acc[mt][nt][3] * r8);
        }
    }
}

// ---------------- FF1 fp16: H1h = relu(xh[list] @ W1ht^T + b1) ----------------
__global__ __launch_bounds__(256, 2) void ff1_mma_h(const float* __restrict__ b1)
{
    const int e = blockIdx.z;
    const int cnt = g_cnt[e];
    const int m0 = blockIdx.y * 128;
    if (m0 >= cnt) return;
    __shared__ uint32_t smem[3 * (128 * 16 + 128 * 16)];
    const int tid = threadIdx.x;
    const int lane = tid & 31, wid = tid >> 5;
    const int wm = wid / 4, wn = wid % 4;
    const int gid = lane >> 2, tig = lane & 3;
    float acc[4][4][4] = {};
    const int n0 = blockIdx.x * 128;
    const int r = m0 + (tid >> 1);
    const __half* pa = g_xh; int sa = 0;
    if (r < cnt) { pa = g_xh + (size_t)g_list[e * NTOK + r] * DIM; sa = 16; }
    const __half* pb = g_W1ht + (size_t)e * FFD * DIM
                     + (size_t)(n0 + ((128 == 128) ? (tid >> 1) : 0)) * DIM;
    const float* bb = b1 + e * FFD;
    __half* Hout = g_H1h + (size_t)e * NTOK * FFD;
    mma_core_h<128>(pa, sa, pb, DIM, smem, acc);
#pragma unroll
    for (int mt = 0; mt < 4; mt++) {
#pragma unroll
        for (int nt = 0; nt < 4; nt++) {
            int lm = m0 + wm * 64 + mt * 16 + gid;
            int col = n0 + wn * 32 + nt * 8 + 2 * tig;
            float b0 = bb[col], b1v = bb[col + 1];
            if (lm < cnt) {
                *(__half2*)(Hout + (size_t)lm * FFD + col) =
                    __floats2half2_rn(fmaxf(acc[mt][nt][0] + b0, 0.f),
                                      fmaxf(acc[mt][nt][1] + b1v, 0.f));
            }
            if (lm + 8 < cnt) {
                *(__half2*)(Hout + (size_t)(lm + 8) * FFD + col) =
                    __floats2half2_rn(fmaxf(acc[mt][nt][2] + b0, 0.f),
                                      fmaxf(acc[mt][nt][3] + b1v, 0.f));
            }
        }
    }
}

// ---------------- FF2 fp16 (BN=64): Y = H1h @ W2ht^T + b2 ----------------
__global__ __launch_bounds__(256, 2) void ff2_mma_h(const float* __restrict__ b2)
{
    const int e = blockIdx.z;
    const int cnt = g_cnt[e];
    const int m0 = blockIdx.y * 128;
    if (m0 >= cnt) return;
    __shared__ uint32_t smem[3 * (128 * 16 + 64 * 16)];
    const int tid = threadIdx.x;
    const int lane = tid & 31, wid = tid >> 5;
    const int wm = wid / 2, wn = wid % 2;
    const int gid = lane >> 2, tig = lane & 3;
    float acc[2][4][4] = {};
    const int n0 = blockIdx.x * 64;
    const __half* Ab = g_H1h + (size_t)e * NTOK * FFD;
    const int r = m0 + (tid >> 1);
    const __half* pa = Ab; int sa = 0;
    if (r < cnt) { pa = Ab + (size_t)r * FFD; sa = 16; }
    const __half* pb = g_W2ht + (size_t)e * DIM * FFD + (size_t)(n0 + (tid >> 2)) * FFD;
    const float* bb = b2 + e * DIM;
    float* Yout = g_Y + (size_t)e * NTOK * DIM;
    mma_core_h<64>(pa, sa, pb, FFD, smem, acc);
#pragma unroll
    for (int mt = 0; mt < 2; mt++) {
#pragma unroll
        for (int nt = 0; nt < 4; nt++) {
            int lm = m0 + wm * 32 + mt * 16 + gid;
            int col = n0 + wn * 32 + nt * 8 + 2 * tig;
            float b0 = bb[col], b1v = bb[col + 1];
            if (lm < cnt) {
                *(float2*)(Yout + (size_t)lm * DIM + col) =
                    make_float2(acc[mt][nt][0] + b0, acc[mt][nt][1] + b1v);
            }
            if (lm + 8 < cnt) {
                *(float2*)(Yout + (size_t)(lm + 8) * DIM + col) =
                    make_float2(acc[mt][nt][2] + b0, acc[mt][nt][3] + b1v);
            }
        }
    }
}

// ---------------- reductions ----------------
__device__ __forceinline__ float blockReduceSum(float v) {
    __shared__ float red[8];
    int lane = threadIdx.x & 31, wid = threadIdx.x >> 5;
#pragma unroll
    for (int o = 16; o > 0; o >>= 1) v += __shfl_xor_sync(0xffffffffu, v, o);
    __syncthreads();
    if (lane == 0) red[wid] = v;
    __syncthreads();
    float r = (lane < 8) ? red[lane] : 0.f;
#pragma unroll
    for (int o = 16; o > 0; o >>= 1) r += __shfl_xor_sync(0xffffffffu, r, o);
    return r;
}

// ---------------- LN1 + fused gating (also emits x fp16) ----------------
__global__ void add_ln1_gate_kernel(const float* __restrict__ a, const float* __restrict__ b,
                                    const float* __restrict__ g, const float* __restrict__ be,
                                    const float* __restrict__ Wg, const float* __restrict__ bg,
                                    float* __restrict__ out) {
    int t = blockIdx.x, tid = threadIdx.x;
    const float* ar = a + (size_t)t * DIM;
    const float* br = b + (size_t)t * DIM;
    float v[3];
#pragma unroll
    for (int i = 0; i < 3; i++) v[i] = ar[tid + i * 256] + br[tid + i * 256];
    float mean = blockReduceSum(v[0] + v[1] + v[2]) * (1.f / DIM);
    float sq = 0.f;
#pragma unroll
    for (int i = 0; i < 3; i++) { v[i] -= mean; sq += v[i] * v[i]; }
    float var = blockReduceSum(sq) * (1.f / DIM);
    float r = rsqrtf(var + EPSLN);
    float xv[3];
    float gp0 = 0.f, gp1 = 0.f, gp2 = 0.f, gp3 = 0.f;
#pragma unroll
    for (int i = 0; i < 3; i++) {
        int c = tid + i * 256;
        xv[i] = v[i] * r * g[c] + be[c];
        out[(size_t)t * DIM + c] = xv[i];
        g_xh[(size_t)t * DIM + c] = __float2half(xv[i]);
        gp0 += xv[i] * Wg[c];
        gp1 += xv[i] * Wg[DIM + c];
        gp2 += xv[i] * Wg[2 * DIM + c];
        gp3 += xv[i] * Wg[3 * DIM + c];
    }
    float s0 = blockReduceSum(gp0);
    float s1 = blockReduceSum(gp1);
    float s2 = blockReduceSum(gp2);
    float s3 = blockReduceSum(gp3);
    if (tid == 0) {
        float s[4] = {s0 + bg[0], s1 + bg[1], s2 + bg[2], s3 + bg[3]};
        float mx = fmaxf(fmaxf(s[0], s[1]), fmaxf(s[2], s[3]));
        float p[4], sum = 0.f;
#pragma unroll
        for (int e = 0; e < 4; e++) { p[e] = expf(s[e] - mx); sum += p[e]; }
        float ri = 1.f / sum;
#pragma unroll
        for (int e = 0; e < 4; e++) p[e] *= ri;
        int i1 = 0;
#pragma unroll
        for (int e = 1; e < 4; e++) if (p[e] > p[i1]) i1 = e;
        int i2 = (i1 == 0) ? 1 : 0;
#pragma unroll
        for (int e = 0; e < 4; e++) if (e != i1 && p[e] > p[i2]) i2 = e;
        int slot = atomicAdd(&g_cnt[i1], 1);
        g_list[i1 * NTOK + slot] = t;
        g_tslot[t] = i1 * NTOK + slot;
        g_tw[t] = p[i1];
        slot = atomicAdd(&g_cnt[i2], 1);
        g_list[i2 * NTOK + slot] = t;
        g_tslot[NTOK + t] = i2 * NTOK + slot;
        g_tw[NTOK + t] = p[i2];
    }
}

// ---------------- LN2 + MoE combine ----------------
__global__ void add_ln2_moe_kernel(const float* __restrict__ x,
                                   const float* __restrict__ g, const float* __restrict__ be,
                                   float* __restrict__ out) {
    int t = blockIdx.x, tid = threadIdx.x;
    int s1 = g_tslot[t], s2 = g_tslot[NTOK + t];
    float w1 = g_tw[t], w2 = g_tw[NTOK + t];
    const float* y1 = g_Y + (size_t)s1 * DIM;
    const float* y2 = g_Y + (size_t)s2 * DIM;
    const float* xr = x + (size_t)t * DIM;
    float v[3];
#pragma unroll
    for (int i = 0; i < 3; i++) {
        int c = tid + i * 256;
        v[i] = xr[c] + w1 * y1[c] + w2 * y2[c];
    }
    float mean = blockReduceSum(v[0] + v[1] + v[2]) * (1.f / DIM);
    float sq = 0.f;
#pragma unroll
    for (int i = 0; i < 3; i++) { v[i] -= mean; sq += v[i] * v[i]; }
    float var = blockReduceSum(sq) * (1.f / DIM);
    float r = rsqrtf(var + EPSLN);
#pragma unroll
    for (int i = 0; i < 3; i++) {
        int c = tid + i * 256;
        out[(size_t)t * DIM + c] = v[i] * r * g[c] + be[c];
    }
}

// ---------------- launch ----------------
extern "C" void kernel_launch(void* const* d_in, const int* in_sizes, int n_in,
                              void* d_out, int out_size) {
    const float* src  = (const float*)d_in[0];
    const float* Wq = (const float*)d_in[2];
    const float* bq = (const float*)d_in[3];
    const float* Wk = (const float*)d_in[4];
    const float* bk = (const float*)d_in[5];
    const float* Wv = (const float*)d_in[6];
    const float* bv = (const float*)d_in[7];
    const float* Wo = (const float*)d_in[8];
    const float* bo = (const float*)d_in[9];
    const float* gamma = (const float*)d_in[10];
    const float* ln1g = (const float*)d_in[11];
    const float* ln1b = (const float*)d_in[12];
    const float* ln2g = (const float*)d_in[13];
    const float* ln2b = (const float*)d_in[14];
    const float* Wg = (const float*)d_in[15];
    const float* bg = (const float*)d_in[16];
    const float* W1 = (const float*)d_in[17];
    const float* b1 = (const float*)d_in[18];
    const float* W2 = (const float*)d_in[19];
    const float* b2 = (const float*)d_in[20];
    float* out = (float*)d_out;

    float *Qp, *Kp, *attnp, *attnop, *xp;
    __half *W1htp, *W2htp;
    cudaGetSymbolAddress((void**)&Qp, g_Q);
    cudaGetSymbolAddress((void**)&Kp, g_K);
    cudaGetSymbolAddress((void**)&attnp, g_attn);
    cudaGetSymbolAddress((void**)&attnop, g_attno);
    cudaGetSymbolAddress((void**)&xp, g_x);
    cudaGetSymbolAddress((void**)&W1htp, g_W1ht);
    cudaGetSymbolAddress((void**)&W2htp, g_W2ht);

    // weight transpose + fp16 convert (NT layout for fp16 FF cores)
    transpose_cvt<<<dim3(FFD / 32, DIM / 32, NE), dim3(32, 8)>>>(W1, W1htp, DIM, FFD);
    transpose_cvt<<<dim3(DIM / 32, FFD / 32, NE), dim3(32, 8)>>>(W2, W2htp, FFD, DIM);

    // fused QKV projections (V written transposed) + stats/counter zeroing
    qkv_mma<<<dim3(DIM / 128, NTOK / 128, 3), 256>>>(src, Wq, bq, Wk, bk, Wv, bv);

    // logits = scale * Q K^T  (+ per-row stats, fp16 P store)
    qk_mma<<<dim3(SEQ / 128, SEQ / 128, BHZ), 256>>>(Qp, Kp, 0.125f);

    // fused zscore+softmax+PV (rowc in prologue, fp16 P reads)
    pv2_mma<<<dim3(1, SEQ / 128, BHZ), 256>>>(gamma);

    // O projection (BN=64)
    oproj_mma<<<dim3(DIM / 64, NTOK / 128), 256>>>(attnp, Wo, bo, attnop);

    // x = LN1(src + attn_out), fused gating + routing (+ fp16 x)
    add_ln1_gate_kernel<<<NTOK, 256>>>(src, attnop, ln1g, ln1b, Wg, bg, xp);

    // expert FFN in fp16 (sparse top-2)
    ff1_mma_h<<<dim3(FFD / 128, NTOK / 128, NE), 256>>>(b1);
    ff2_mma_h<<<dim3(DIM / 64, NTOK / 128, NE), 256>>>(b2);

    // out = LN2(x + combine(Y))
    add_ln2_moe_kernel<<<NTOK, 256>>>(xp, ln2g, ln2b, out);
}

// round 13
// speedup vs baseline: 1.3486x; 1.0733x over previous
#include <cuda_runtime.h>
#include <cuda_fp16.h>
#include <math.h>
#include <stdint.h>

// ---------------- problem constants ----------------
namespace {
constexpr int BATCH = 2;
constexpr int SEQ   = 1024;
constexpr int DIM   = 768;
constexpr int NH    = 12;
constexpr int HD    = 64;
constexpr int FFD   = 3072;
constexpr int NE    = 4;
constexpr int NTOK  = BATCH * SEQ;     // 2048
constexpr int BHZ   = BATCH * NH;      // 24
constexpr int ROWS_TOT = BHZ * SEQ;    // 24576 attention rows
constexpr float EPSZ  = 1e-5f;
constexpr float EPSLN = 1e-5f;
}

// ---------------- scratch (static device memory) ----------------
__device__ __align__(16) __half g_Qh[NTOK * DIM];
__device__ __align__(16) __half g_Kh[NTOK * DIM];
__device__ __align__(16) __half g_Vth[BHZ * HD * SEQ];         // V^T fp16: [b][h][d][t]
__device__ __align__(16) __half g_P[(size_t)BHZ * SEQ * SEQ];  // raw scaled logits (fp16)
__device__ __align__(16) float g_attn[NTOK * DIM];
__device__ __align__(16) float g_attno[NTOK * DIM];
__device__ __align__(16) float g_x[NTOK * DIM];
__device__ __align__(16) __half g_xh[NTOK * DIM];              // x in fp16 (ff1 A operand)
__device__ __align__(16) __half g_H1h[(size_t)NE * NTOK * FFD];// expert hidden (fp16)
__device__ __align__(16) float g_Y[(size_t)NE * NTOK * DIM];
__device__ __align__(16) __half g_W1ht[(size_t)NE * FFD * DIM];// W1^T fp16: [e][ff][d]
__device__ __align__(16) __half g_W2ht[(size_t)NE * DIM * FFD];// W2^T fp16: [e][d][ff]
__device__ float g_rsum[ROWS_TOT];
__device__ float g_rsumsq[ROWS_TOT];
__device__ unsigned g_rmaxe[ROWS_TOT];
__device__ unsigned g_rmine[ROWS_TOT];
__device__ int   g_cnt[NE];
__device__ int   g_list[NE * NTOK];
__device__ int   g_tslot[2 * NTOK];
__device__ float g_tw[2 * NTOK];

// ---------------- primitives ----------------
__device__ __forceinline__ void mma_op(float* d, const uint32_t* a, uint32_t b0, uint32_t b1) {
    asm volatile(
        "mma.sync.aligned.m16n8k8.row.col.f32.tf32.tf32.f32 "
        "{%0,%1,%2,%3},{%4,%5,%6,%7},{%8,%9},{%0,%1,%2,%3};\n"
        : "+f"(d[0]), "+f"(d[1]), "+f"(d[2]), "+f"(d[3])
        : "r"(a[0]), "r"(a[1]), "r"(a[2]), "r"(a[3]), "r"(b0), "r"(b1));
}
__device__ __forceinline__ void mma_h(float* d, const uint32_t* a, uint32_t b0, uint32_t b1) {
    asm volatile(
        "mma.sync.aligned.m16n8k16.row.col.f32.f16.f16.f32 "
        "{%0,%1,%2,%3},{%4,%5,%6,%7},{%8,%9},{%0,%1,%2,%3};\n"
        : "+f"(d[0]), "+f"(d[1]), "+f"(d[2]), "+f"(d[3])
        : "r"(a[0]), "r"(a[1]), "r"(a[2]), "r"(a[3]), "r"(b0), "r"(b1));
}
__device__ __forceinline__ void cp_async16(float* dst, const float* src, int sz) {
    uint32_t s = (uint32_t)__cvta_generic_to_shared(dst);
    asm volatile("cp.async.cg.shared.global [%0], [%1], 16, %2;\n"
                 :: "r"(s), "l"(src), "r"(sz));
}
__device__ __forceinline__ void cp_async16u(uint32_t* dst, const __half* src, int sz) {
    uint32_t s = (uint32_t)__cvta_generic_to_shared(dst);
    asm volatile("cp.async.cg.shared.global [%0], [%1], 16, %2;\n"
                 :: "r"(s), "l"(src), "r"(sz));
}
// fp32 tile swizzle (rows x 16 floats)
__device__ __forceinline__ int swz(int row, int col) {
    return (row << 4) + (((((col >> 2) ^ ((row >> 1) & 3))) << 2) | (col & 3));
}
// fp16 tile: rows x 32 halves = 16 words; chunk-xor swizzle; w = word 0..15
__device__ __forceinline__ int swzh(int row, int w) {
    return (row << 4) + ((((w >> 2) ^ ((row >> 1) & 3)) << 2) | (w & 3));
}
__device__ __forceinline__ int chkoff(int row, int c) {   // 16B chunk word offset
    return (row << 4) + ((c ^ ((row >> 1) & 3)) << 2);
}
// ordered-uint encode for float atomic max/min
__device__ __forceinline__ unsigned fenc(float f) {
    unsigned u = __float_as_uint(f);
    return (u & 0x80000000u) ? ~u : (u | 0x80000000u);
}
__device__ __forceinline__ float fdec(unsigned u) {
    unsigned b = (u & 0x80000000u) ? (u ^ 0x80000000u) : ~u;
    return __uint_as_float(b);
}

// ---------------- cp.async 3-stage pipelined tf32 MMA core ----------------
template<int BN>
__device__ __forceinline__ void mma_core(
    const float* pa1, int sa1, const float* pa2, int sa2,
    const float* pb1, const float* pb2,
    int K, float* smem, float (&acc)[(BN == 128) ? 4 : 2][4][4])
{
    constexpr int MT  = (BN == 128) ? 4 : 2;
    constexpr int WN  = (BN == 128) ? 4 : 2;
    constexpr int ASZ = 128 * 16;
    constexpr int BSZ = BN * 16;
    constexpr int STG = ASZ + BSZ;
    const int tid = threadIdx.x;
    const int lane = tid & 31, wid = tid >> 5;
    const int wm = wid / WN, wn = wid % WN;
    const int gid = lane >> 2, tig = lane & 3;
    const int crow = tid >> 2, cq = tid & 3;
    const int coff  = (crow << 4) + ((cq ^ ((crow >> 1) & 3)) << 2);
    const int coff2 = ((crow + 64) << 4) + ((cq ^ ((crow >> 1) & 3)) << 2);
    const int q4 = 4 * cq;

    auto issue = [&](int i) {
        float* As = smem + (i % 3) * STG;
        float* Bs = As + ASZ;
        const int kt = i << 4;
        cp_async16(As + coff,  pa1 + kt + q4, sa1);
        cp_async16(As + coff2, pa2 + kt + q4, sa2);
        cp_async16(Bs + coff,  pb1 + kt + q4, 16);
        if (BN == 128) cp_async16(Bs + coff2, pb2 + kt + q4, 16);
        asm volatile("cp.async.commit_group;\n" ::: "memory");
    };
    auto compute = [&](int s) {
        const float* As = smem + s * STG;
        const float* Bs = As + ASZ;
#pragma unroll
        for (int c = 0; c < 2; c++) {
            const int k0 = c * 8 + tig;
            uint32_t af[MT][4];
#pragma unroll
            for (int mt = 0; mt < MT; mt++) {
                const int ar = wm * (MT * 16) + mt * 16 + gid;
                af[mt][0] = __float_as_uint(As[swz(ar, k0)]);
                af[mt][1] = __float_as_uint(As[swz(ar + 8, k0)]);
                af[mt][2] = __float_as_uint(As[swz(ar, k0 + 4)]);
                af[mt][3] = __float_as_uint(As[swz(ar + 8, k0 + 4)]);
            }
#pragma unroll
            for (int nt = 0; nt < 4; nt++) {
                const int br = wn * 32 + nt * 8 + gid;
                uint32_t b0 = __float_as_uint(Bs[swz(br, k0)]);
                uint32_t b1 = __float_as_uint(Bs[swz(br, k0 + 4)]);
#pragma unroll
                for (int mt = 0; mt < MT; mt++) mma_op(acc[mt][nt], af[mt], b0, b1);
            }
        }
    };

    const int nk = K >> 4;
    issue(0);
    if (nk > 1) issue(1);
    for (int i = 0; i < nk; i++) {
        if (i + 1 < nk) asm volatile("cp.async.wait_group 1;\n" ::: "memory");
        else            asm volatile("cp.async.wait_group 0;\n" ::: "memory");
        __syncthreads();
        if (i + 2 < nk) issue(i + 2);
        compute(i % 3);
    }
}

// ---------------- fp16 NT MMA core: BM=128, BK=32 halves, 3-stage ----------------
template<int BN>
__device__ __forceinline__ void mma_core_h(
    const __half* pa, int sa, const __half* pb,
    int K, uint32_t* smem, float (&acc)[(BN == 128) ? 4 : 2][4][4])
{
    constexpr int MT  = (BN == 128) ? 4 : 2;
    constexpr int WN  = (BN == 128) ? 4 : 2;
    constexpr int ASZ = 128 * 16;            // words
    constexpr int BSZ = BN * 16;
    constexpr int STG = ASZ + BSZ;
    const int tid = threadIdx.x;
    const int lane = tid & 31, wid = tid >> 5;
    const int wm = wid / WN, wn = wid % WN;
    const int gid = lane >> 2, tig = lane & 3;
    const int arow_ld = tid >> 1, ac = (tid & 1) * 2;
    const int aoff0 = chkoff(arow_ld, ac);
    const int aoff1 = chkoff(arow_ld, ac + 1);
    const int brow_ld = (BN == 128) ? (tid >> 1) : (tid >> 2);
    const int bc = (BN == 128) ? ((tid & 1) * 2) : (tid & 3);
    const int boff0 = chkoff(brow_ld, bc);
    const int boff1 = chkoff(brow_ld, bc + 1);

    auto issue = [&](int i) {
        uint32_t* As = smem + (i % 3) * STG;
        uint32_t* Bs = As + ASZ;
        const int kt = i << 5;
        cp_async16u(As + aoff0, pa + kt + ac * 8, sa);
        cp_async16u(As + aoff1, pa + kt + ac * 8 + 8, sa);
        cp_async16u(Bs + boff0, pb + kt + bc * 8, 16);
        if (BN == 128) cp_async16u(Bs + boff1, pb + kt + bc * 8 + 8, 16);
        asm volatile("cp.async.commit_group;\n" ::: "memory");
    };
    auto compute = [&](int s) {
        const uint32_t* As = smem + s * STG;
        const uint32_t* Bs = As + ASZ;
#pragma unroll
        for (int ks = 0; ks < 2; ks++) {
            const int w0 = ks * 8 + tig;
            uint32_t af[MT][4];
#pragma unroll
            for (int mt = 0; mt < MT; mt++) {
                const int ar = wm * (MT * 16) + mt * 16 + gid;
                af[mt][0] = As[swzh(ar, w0)];
                af[mt][1] = As[swzh(ar + 8, w0)];
                af[mt][2] = As[swzh(ar, w0 + 4)];
                af[mt][3] = As[swzh(ar + 8, w0 + 4)];
            }
#pragma unroll
            for (int nt = 0; nt < 4; nt++) {
                const int br = wn * 32 + nt * 8 + gid;
                uint32_t b0 = Bs[swzh(br, w0)];
                uint32_t b1 = Bs[swzh(br, w0 + 4)];
#pragma unroll
                for (int mt = 0; mt < MT; mt++) mma_h(acc[mt][nt], af[mt], b0, b1);
            }
        }
    };

    const int nk = K >> 5;
    issue(0);
    if (nk > 1) issue(1);
    for (int i = 0; i < nk; i++) {
        if (i + 1 < nk) asm volatile("cp.async.wait_group 1;\n" ::: "memory");
        else            asm volatile("cp.async.wait_group 0;\n" ::: "memory");
        __syncthreads();
        if (i + 2 < nk) issue(i + 2);
        compute(i % 3);
    }
}

// ---------------- weight transpose + fp32->fp16 ----------------
__global__ void transpose_cvt(const float* __restrict__ in, __half* __restrict__ out,
                              int R, int C)
{
    __shared__ float t[32][33];
    int e = blockIdx.z;
    in += (size_t)e * R * C;
    out += (size_t)e * R * C;
    int c0 = blockIdx.x * 32, r0 = blockIdx.y * 32;
    int tx = threadIdx.x, ty = threadIdx.y;
#pragma unroll
    for (int i = 0; i < 32; i += 8)
        t[ty + i][tx] = in[(size_t)(r0 + ty + i) * C + c0 + tx];
    __syncthreads();
#pragma unroll
    for (int i = 0; i < 32; i += 8)
        out[(size_t)(c0 + ty + i) * R + r0 + tx] = __float2half(t[tx][ty + i]);
}

// ---------------- fused QKV projection: tf32 compute, fp16 outputs ----------------
__global__ __launch_bounds__(256, 2) void qkv_mma(
    const float* __restrict__ A,
    const float* __restrict__ Wq, const float* __restrict__ bq,
    const float* __restrict__ Wk, const float* __restrict__ bk,
    const float* __restrict__ Wv, const float* __restrict__ bv)
{
    __shared__ float smem[3 * (128 * 16 + 128 * 16)];
    const int tid = threadIdx.x;
    {
        int gbid = (blockIdx.z * gridDim.y + blockIdx.y) * gridDim.x + blockIdx.x;
        int gidx = gbid * 256 + tid;
        if (gidx < ROWS_TOT) {
            g_rsum[gidx] = 0.f;
            g_rsumsq[gidx] = 0.f;
            g_rmaxe[gidx] = fenc(-3e38f);
            g_rmine[gidx] = fenc(3e38f);
        }
        if (gidx < NE) g_cnt[gidx] = 0;
    }
    const int lane = tid & 31, wid = tid >> 5;
    const int wm = wid / 4, wn = wid % 4;
    const int gid = lane >> 2, tig = lane & 3;
    const int crow = tid >> 2;
    float acc[4][4][4] = {};
    const int which = blockIdx.z;
    const float* W = (which == 0) ? Wq : (which == 1) ? Wk : Wv;
    const float* bias = (which == 0) ? bq : (which == 1) ? bk : bv;
    const int m0 = blockIdx.y * 128, n0 = blockIdx.x * 128;
    mma_core<128>(A + (size_t)(m0 + crow) * DIM, 16,
                  A + (size_t)(m0 + crow + 64) * DIM, 16,
                  W + (size_t)(n0 + crow) * DIM,
                  W + (size_t)(n0 + crow + 64) * DIM,
                  DIM, smem, acc);
#pragma unroll
    for (int mt = 0; mt < 4; mt++) {
#pragma unroll
        for (int nt = 0; nt < 4; nt++) {
            int row = m0 + wm * 64 + mt * 16 + gid;
            int col = n0 + wn * 32 + nt * 8 + 2 * tig;
            float c0 = acc[mt][nt][0] + bias[col];
            float c1 = acc[mt][nt][1] + bias[col + 1];
            float c2 = acc[mt][nt][2] + bias[col];
            float c3 = acc[mt][nt][3] + bias[col + 1];
            if (which == 0) {
                *(__half2*)(g_Qh + (size_t)row * DIM + col) = __floats2half2_rn(c0, c1);
                *(__half2*)(g_Qh + (size_t)(row + 8) * DIM + col) = __floats2half2_rn(c2, c3);
            } else if (which == 1) {
                *(__half2*)(g_Kh + (size_t)row * DIM + col) = __floats2half2_rn(c0, c1);
                *(__half2*)(g_Kh + (size_t)(row + 8) * DIM + col) = __floats2half2_rn(c2, c3);
            } else {
                float vals[4] = {c0, c1, c2, c3};
#pragma unroll
                for (int q = 0; q < 4; q++) {
                    int rr = row + (q >> 1) * 8;
                    int cc = col + (q & 1);
                    int bb = rr >> 10, tt = rr & 1023;
                    int h = cc >> 6, d = cc & 63;
                    g_Vth[(((size_t)bb * NH + h) * HD + d) * SEQ + tt] = __float2half(vals[q]);
                }
            }
        }
    }
}

// ---------------- O projection (BN=64, tf32) ----------------
__global__ __launch_bounds__(256, 2) void oproj_mma(
    const float* __restrict__ A, const float* __restrict__ W,
    const float* __restrict__ bias, float* __restrict__ C)
{
    __shared__ float smem[3 * (128 * 16 + 64 * 16)];
    const int tid = threadIdx.x;
    const int lane = tid & 31, wid = tid >> 5;
    const int wm = wid / 2, wn = wid % 2;
    const int gid = lane >> 2, tig = lane & 3;
    const int crow = tid >> 2;
    float acc[2][4][4] = {};
    const int m0 = blockIdx.y * 128, n0 = blockIdx.x * 64;
    mma_core<64>(A + (size_t)(m0 + crow) * DIM, 16,
                 A + (size_t)(m0 + crow + 64) * DIM, 16,
                 W + (size_t)(n0 + crow) * DIM, nullptr,
                 DIM, smem, acc);
#pragma unroll
    for (int mt = 0; mt < 2; mt++) {
#pragma unroll
        for (int nt = 0; nt < 4; nt++) {
            int row = m0 + wm * 32 + mt * 16 + gid;
            int col = n0 + wn * 32 + nt * 8 + 2 * tig;
            float b0 = bias[col], b1 = bias[col + 1];
            *(float2*)(C + (size_t)row * DIM + col) =
                make_float2(acc[mt][nt][0] + b0, acc[mt][nt][1] + b1);
            *(float2*)(C + (size_t)(row + 8) * DIM + col) =
                make_float2(acc[mt][nt][2] + b0, acc[mt][nt][3] + b1);
        }
    }
}

// ---------------- QK^T in fp16 + per-row stats epilogue (fp16 P store) ----------------
__global__ __launch_bounds__(256, 2) void qk_mma_h(float scale)
{
    __shared__ uint32_t smem[3 * (128 * 16 + 128 * 16)];
    const int tid = threadIdx.x;
    const int lane = tid & 31, wid = tid >> 5;
    const int wm = wid / 4, wn = wid % 4;
    const int gid = lane >> 2, tig = lane & 3;
    float acc[4][4][4] = {};
    const int z = blockIdx.z, b = z / NH, h = z % NH;
    const int m0 = blockIdx.y * 128, n0 = blockIdx.x * 128;
    const __half* pa = g_Qh + ((size_t)(b * SEQ + m0 + (tid >> 1))) * DIM + h * HD;
    const __half* pb = g_Kh + ((size_t)(b * SEQ + n0 + (tid >> 1))) * DIM + h * HD;
    __half* Cb = g_P + (size_t)z * SEQ * SEQ;
    mma_core_h<128>(pa, 16, pb, HD, smem, acc);
    const size_t rowbase = (size_t)z * SEQ + m0;
#pragma unroll
    for (int mt = 0; mt < 4; mt++) {
        float s0 = 0.f, q0 = 0.f, s8 = 0.f, q8 = 0.f;
        float mx0 = -3e38f, mn0 = 3e38f, mx8 = -3e38f, mn8 = 3e38f;
#pragma unroll
        for (int nt = 0; nt < 4; nt++) {
            int row = m0 + wm * 64 + mt * 16 + gid;
            int col = n0 + wn * 32 + nt * 8 + 2 * tig;
            float v0 = acc[mt][nt][0] * scale, v1 = acc[mt][nt][1] * scale;
            float v2 = acc[mt][nt][2] * scale, v3 = acc[mt][nt][3] * scale;
            *(__half2*)(Cb + (size_t)row * SEQ + col) = __floats2half2_rn(v0, v1);
            *(__half2*)(Cb + (size_t)(row + 8) * SEQ + col) = __floats2half2_rn(v2, v3);
            s0 += v0 + v1; q0 += v0 * v0 + v1 * v1;
            mx0 = fmaxf(mx0, fmaxf(v0, v1)); mn0 = fminf(mn0, fminf(v0, v1));
            s8 += v2 + v3; q8 += v2 * v2 + v3 * v3;
            mx8 = fmaxf(mx8, fmaxf(v2, v3)); mn8 = fminf(mn8, fminf(v2, v3));
        }
#pragma unroll
        for (int o = 1; o < 4; o <<= 1) {
            s0 += __shfl_xor_sync(~0u, s0, o); q0 += __shfl_xor_sync(~0u, q0, o);
            s8 += __shfl_xor_sync(~0u, s8, o); q8 += __shfl_xor_sync(~0u, q8, o);
            mx0 = fmaxf(mx0, __shfl_xor_sync(~0u, mx0, o));
            mn0 = fminf(mn0, __shfl_xor_sync(~0u, mn0, o));
            mx8 = fmaxf(mx8, __shfl_xor_sync(~0u, mx8, o));
            mn8 = fminf(mn8, __shfl_xor_sync(~0u, mn8, o));
        }
        if (tig == 0) {
            size_t r0 = rowbase + wm * 64 + mt * 16 + gid;
            atomicAdd(&g_rsum[r0], s0);   atomicAdd(&g_rsumsq[r0], q0);
            atomicMax(&g_rmaxe[r0], fenc(mx0)); atomicMin(&g_rmine[r0], fenc(mn0));
            atomicAdd(&g_rsum[r0 + 8], s8); atomicAdd(&g_rsumsq[r0 + 8], q8);
            atomicMax(&g_rmaxe[r0 + 8], fenc(mx8)); atomicMin(&g_rmine[r0 + 8], fenc(mn8));
        }
    }
}

// ---------------- fused zscore-softmax + P@V, all-fp16 operands (BK=32) ----------------
__global__ __launch_bounds__(256, 2) void pv2_mma(const float* __restrict__ gamma)
{
    __shared__ uint32_t Asm[2][128 * 16];
    __shared__ uint32_t Bsm[3][64 * 16];
    __shared__ float denom_s[128];
    __shared__ float2 rowc_s[128];
    const int tid = threadIdx.x;
    const int lane = tid & 31, wid = tid >> 5;
    const int wm = wid / 2, wn = wid % 2;
    const int gid = lane >> 2, tig = lane & 3;
    // B: 64 rows x 4 chunks (32 halves/row/iter)
    const int brow = tid >> 2, bc = tid & 3;
    const int boff = chkoff(brow, bc);
    // A: 128 rows x 2 threads; each handles 2 chunks (16 halves)
    const int arow = tid >> 1, acq = tid & 1;
    const int aoff0 = chkoff(arow, 2 * acq);
    const int aoff1 = chkoff(arow, 2 * acq + 1);
    float acc[2][4][4] = {};
    const int z = blockIdx.z, b = z / NH, h = z % NH;
    const int m0 = blockIdx.y * 128;
    const __half* Arow = g_P + ((size_t)z * SEQ + m0 + arow) * SEQ + 16 * acq;
    const __half* Brow = g_Vth + (size_t)z * HD * SEQ + (size_t)brow * SEQ;
    float esum = 0.f;
    constexpr int nk = SEQ / 32;  // 32

    auto issueB = [&](int i) {
        cp_async16u(Bsm[i % 3] + boff, Brow + (i << 5) + bc * 8, 16);
        asm volatile("cp.async.commit_group;\n" ::: "memory");
    };
    auto compute = [&](const uint32_t* As, const uint32_t* Bs) {
#pragma unroll
        for (int ks = 0; ks < 2; ks++) {
            const int w0 = ks * 8 + tig;
            uint32_t af[2][4];
#pragma unroll
            for (int mt = 0; mt < 2; mt++) {
                const int ar = wm * 32 + mt * 16 + gid;
                af[mt][0] = As[swzh(ar, w0)];
                af[mt][1] = As[swzh(ar + 8, w0)];
                af[mt][2] = As[swzh(ar, w0 + 4)];
                af[mt][3] = As[swzh(ar + 8, w0 + 4)];
            }
#pragma unroll
            for (int nt = 0; nt < 4; nt++) {
                const int br = wn * 32 + nt * 8 + gid;
                uint32_t b0 = Bs[swzh(br, w0)];
                uint32_t b1 = Bs[swzh(br, w0 + 4)];
#pragma unroll
                for (int mt = 0; mt < 2; mt++) mma_h(acc[mt][nt], af[mt], b0, b1);
            }
        }
    };

    issueB(0);
    issueB(1);
    // per-row zscore coefficients (rows m0..m0+127)
    if (tid < 128) {
        size_t i = (size_t)z * SEQ + m0 + tid;
        float s = g_rsum[i], q = g_rsumsq[i];
        float mean = s * (1.f / SEQ);
        float var = fmaxf((q - s * s * (1.f / SEQ)) * (1.f / (SEQ - 1)), 0.f);
        float c1 = (*gamma) / (sqrtf(var) + EPSZ);
        float mx = fdec(g_rmaxe[i]), mn = fdec(g_rmine[i]);
        float zmax = fmaxf(c1 * (mx - mean), c1 * (mn - mean));
        rowc_s[tid] = make_float2(c1, -mean * c1 - zmax);
    }
    __syncthreads();
    const float2 rc = rowc_s[arow];
    uint4 a0 = *(const uint4*)(Arow);        // halves 0..7
    uint4 a1 = *(const uint4*)(Arow + 8);    // halves 8..15
    for (int i = 0; i < nk; i++) {
        if (i + 1 < nk) asm volatile("cp.async.wait_group 1;\n" ::: "memory");
        else            asm volatile("cp.async.wait_group 0;\n" ::: "memory");
        __syncthreads();                     // B(i) visible; compute(i-1) done
        if (i + 2 < nk) issueB(i + 2);
        // exp-transform 16 halves -> 16 fp32 -> 8 half2 words
        uint4 o0, o1;
        {
            const uint32_t* aw = &a0.x;
            uint32_t* ow = &o0.x;
#pragma unroll
            for (int w = 0; w < 4; w++) {
                float2 f = __half22float2(*(const __half2*)&aw[w]);
                float ex = __expf(fmaf(f.x, rc.x, rc.y));
                float ey = __expf(fmaf(f.y, rc.x, rc.y));
                esum += ex + ey;
                *(__half2*)&ow[w] = __floats2half2_rn(ex, ey);
            }
            const uint32_t* aw1 = &a1.x;
            uint32_t* ow1 = &o1.x;
#pragma unroll
            for (int w = 0; w < 4; w++) {
                float2 f = __half22float2(*(const __half2*)&aw1[w]);
                float ex = __expf(fmaf(f.x, rc.x, rc.y));
                float ey = __expf(fmaf(f.y, rc.x, rc.y));
                esum += ex + ey;
                *(__half2*)&ow1[w] = __floats2half2_rn(ex, ey);
            }
        }
        *(uint4*)(Asm[i & 1] + aoff0) = o0;
        *(uint4*)(Asm[i & 1] + aoff1) = o1;
        if (i + 1 < nk) {
            a0 = *(const uint4*)(Arow + ((i + 1) << 5));
            a1 = *(const uint4*)(Arow + ((i + 1) << 5) + 8);
        }
        __syncthreads();                     // A STS visible
        compute(Asm[i & 1], Bsm[i % 3]);
    }
    // row exp-sums -> denominators (2 threads/row)
    esum += __shfl_xor_sync(~0u, esum, 1);
    if (acq == 0) denom_s[arow] = esum;
    __syncthreads();
#pragma unroll
    for (int mt = 0; mt < 2; mt++) {
#pragma unroll
        for (int nt = 0; nt < 4; nt++) {
            int ro = wm * 32 + mt * 16 + gid;
            int col = wn * 32 + nt * 8 + 2 * tig;
            float r0 = 1.f / denom_s[ro];
            float r8 = 1.f / denom_s[ro + 8];
            int row = m0 + ro;
            float* c0 = g_attn + ((size_t)(b * SEQ + row)) * DIM + h * HD + col;
            float* c1 = g_attn + ((size_t)(b * SEQ + row + 8)) * DIM + h * HD + col;
            *(float2*)c0 = make_float2(acc[mt][nt][0] * r0, acc[mt][nt][1] * r0);
            *(float2*)c1 = make_float2(acc[mt][nt][2] * r8, acc[mt][nt][3] * r8);
        }
    }
}

// ---------------- FF1 fp16: H1h = relu(xh[list] @ W1ht^T + b1) ----------------
__global__ __launch_bounds__(256, 2) void ff1_mma_h(const float* __restrict__ b1)
{
    const int e = blockIdx.z;
    const int cnt = g_cnt[e];
    const int m0 = blockIdx.y * 128;
    if (m0 >= cnt) return;
    __shared__ uint32_t smem[3 * (128 * 16 + 128 * 16)];
    const int tid = threadIdx.x;
    const int lane = tid & 31, wid = tid >> 5;
    const int wm = wid / 4, wn = wid % 4;
    const int gid = lane >> 2, tig = lane & 3;
    float acc[4][4][4] = {};
    const int n0 = blockIdx.x * 128;
    const int r = m0 + (tid >> 1);
    const __half* pa = g_xh; int sa = 0;
    if (r < cnt) { pa = g_xh + (size_t)g_list[e * NTOK + r] * DIM; sa = 16; }
    const __half* pb = g_W1ht + (size_t)e * FFD * DIM + (size_t)(n0 + (tid >> 1)) * DIM;
    const float* bb = b1 + e * FFD;
    __half* Hout = g_H1h + (size_t)e * NTOK * FFD;
    mma_core_h<128>(pa, sa, pb, DIM, smem, acc);
#pragma unroll
    for (int mt = 0; mt < 4; mt++) {
#pragma unroll
        for (int nt = 0; nt < 4; nt++) {
            int lm = m0 + wm * 64 + mt * 16 + gid;
            int col = n0 + wn * 32 + nt * 8 + 2 * tig;
            float b0 = bb[col], b1v = bb[col + 1];
            if (lm < cnt) {
                *(__half2*)(Hout + (size_t)lm * FFD + col) =
                    __floats2half2_rn(fmaxf(acc[mt][nt][0] + b0, 0.f),
                                      fmaxf(acc[mt][nt][1] + b1v, 0.f));
            }
            if (lm + 8 < cnt) {
                *(__half2*)(Hout + (size_t)(lm + 8) * FFD + col) =
                    __floats2half2_rn(fmaxf(acc[mt][nt][2] + b0, 0.f),
                                      fmaxf(acc[mt][nt][3] + b1v, 0.f));
            }
        }
    }
}

// ---------------- FF2 fp16 (BN=64): Y = H1h @ W2ht^T + b2 ----------------
__global__ __launch_bounds__(256, 2) void ff2_mma_h(const float* __restrict__ b2)
{
    const int e = blockIdx.z;
    const int cnt = g_cnt[e];
    const int m0 = blockIdx.y * 128;
    if (m0 >= cnt) return;
    __shared__ uint32_t smem[3 * (128 * 16 + 64 * 16)];
    const int tid = threadIdx.x;
    const int lane = tid & 31, wid = tid >> 5;
    const int wm = wid / 2, wn = wid % 2;
    const int gid = lane >> 2, tig = lane & 3;
    float acc[2][4][4] = {};
    const int n0 = blockIdx.x * 64;
    const __half* Ab = g_H1h + (size_t)e * NTOK * FFD;
    const int r = m0 + (tid >> 1);
    const __half* pa = Ab; int sa = 0;
    if (r < cnt) { pa = Ab + (size_t)r * FFD; sa = 16; }
    const __half* pb = g_W2ht + (size_t)e * DIM * FFD + (size_t)(n0 + (tid >> 2)) * FFD;
    const float* bb = b2 + e * DIM;
    float* Yout = g_Y + (size_t)e * NTOK * DIM;
    mma_core_h<64>(pa, sa, pb, FFD, smem, acc);
#pragma unroll
    for (int mt = 0; mt < 2; mt++) {
#pragma unroll
        for (int nt = 0; nt < 4; nt++) {
            int lm = m0 + wm * 32 + mt * 16 + gid;
            int col = n0 + wn * 32 + nt * 8 + 2 * tig;
            float b0 = bb[col], b1v = bb[col + 1];
            if (lm < cnt) {
                *(float2*)(Yout + (size_t)lm * DIM + col) =
                    make_float2(acc[mt][nt][0] + b0, acc[mt][nt][1] + b1v);
            }
            if (lm + 8 < cnt) {
                *(float2*)(Yout + (size_t)(lm + 8) * DIM + col) =
                    make_float2(acc[mt][nt][2] + b0, acc[mt][nt][3] + b1v);
            }
        }
    }
}

// ---------------- reductions ----------------
__device__ __forceinline__ float blockReduceSum(float v) {
    __shared__ float red[8];
    int lane = threadIdx.x & 31, wid = threadIdx.x >> 5;
#pragma unroll
    for (int o = 16; o > 0; o >>= 1) v += __shfl_xor_sync(0xffffffffu, v, o);
    __syncthreads();
    if (lane == 0) red[wid] = v;
    __syncthreads();
    float r = (lane < 8) ? red[lane] : 0.f;
#pragma unroll
    for (int o = 16; o > 0; o >>= 1) r += __shfl_xor_sync(0xffffffffu, r, o);
    return r;
}

// ---------------- LN1 + fused gating (also emits x fp16) ----------------
__global__ void add_ln1_gate_kernel(const float* __restrict__ a, const float* __restrict__ b,
                                    const float* __restrict__ g, const float* __restrict__ be,
                                    const float* __restrict__ Wg, const float* __restrict__ bg,
                                    float* __restrict__ out) {
    int t = blockIdx.x, tid = threadIdx.x;
    const float* ar = a + (size_t)t * DIM;
    const float* br = b + (size_t)t * DIM;
    float v[3];
#pragma unroll
    for (int i = 0; i < 3; i++) v[i] = ar[tid + i * 256] + br[tid + i * 256];
    float mean = blockReduceSum(v[0] + v[1] + v[2]) * (1.f / DIM);
    float sq = 0.f;
#pragma unroll
    for (int i = 0; i < 3; i++) { v[i] -= mean; sq += v[i] * v[i]; }
    float var = blockReduceSum(sq) * (1.f / DIM);
    float r = rsqrtf(var + EPSLN);
    float xv[3];
    float gp0 = 0.f, gp1 = 0.f, gp2 = 0.f, gp3 = 0.f;
#pragma unroll
    for (int i = 0; i < 3; i++) {
        int c = tid + i * 256;
        xv[i] = v[i] * r * g[c] + be[c];
        out[(size_t)t * DIM + c] = xv[i];
        g_xh[(size_t)t * DIM + c] = __float2half(xv[i]);
        gp0 += xv[i] * Wg[c];
        gp1 += xv[i] * Wg[DIM + c];
        gp2 += xv[i] * Wg[2 * DIM + c];
        gp3 += xv[i] * Wg[3 * DIM + c];
    }
    float s0 = blockReduceSum(gp0);
    float s1 = blockReduceSum(gp1);
    float s2 = blockReduceSum(gp2);
    float s3 = blockReduceSum(gp3);
    if (tid == 0) {
        float s[4] = {s0 + bg[0], s1 + bg[1], s2 + bg[2], s3 + bg[3]};
        float mx = fmaxf(fmaxf(s[0], s[1]), fmaxf(s[2], s[3]));
        float p[4], sum = 0.f;
#pragma unroll
        for (int e = 0; e < 4; e++) { p[e] = expf(s[e] - mx); sum += p[e]; }
        float ri = 1.f / sum;
#pragma unroll
        for (int e = 0; e < 4; e++) p[e] *= ri;
        int i1 = 0;
#pragma unroll
        for (int e = 1; e < 4; e++) if (p[e] > p[i1]) i1 = e;
        int i2 = (i1 == 0) ? 1 : 0;
#pragma unroll
        for (int e = 0; e < 4; e++) if (e != i1 && p[e] > p[i2]) i2 = e;
        int slot = atomicAdd(&g_cnt[i1], 1);
        g_list[i1 * NTOK + slot] = t;
        g_tslot[t] = i1 * NTOK + slot;
        g_tw[t] = p[i1];
        slot = atomicAdd(&g_cnt[i2], 1);
        g_list[i2 * NTOK + slot] = t;
        g_tslot[NTOK + t] = i2 * NTOK + slot;
        g_tw[NTOK + t] = p[i2];
    }
}

// ---------------- LN2 + MoE combine ----------------
__global__ void add_ln2_moe_kernel(const float* __restrict__ x,
                                   const float* __restrict__ g, const float* __restrict__ be,
                                   float* __restrict__ out) {
    int t = blockIdx.x, tid = threadIdx.x;
    int s1 = g_tslot[t], s2 = g_tslot[NTOK + t];
    float w1 = g_tw[t], w2 = g_tw[NTOK + t];
    const float* y1 = g_Y + (size_t)s1 * DIM;
    const float* y2 = g_Y + (size_t)s2 * DIM;
    const float* xr = x + (size_t)t * DIM;
    float v[3];
#pragma unroll
    for (int i = 0; i < 3; i++) {
        int c = tid + i * 256;
        v[i] = xr[c] + w1 * y1[c] + w2 * y2[c];
    }
    float mean = blockReduceSum(v[0] + v[1] + v[2]) * (1.f / DIM);
    float sq = 0.f;
#pragma unroll
    for (int i = 0; i < 3; i++) { v[i] -= mean; sq += v[i] * v[i]; }
    float var = blockReduceSum(sq) * (1.f / DIM);
    float r = rsqrtf(var + EPSLN);
#pragma unroll
    for (int i = 0; i < 3; i++) {
        int c = tid + i * 256;
        out[(size_t)t * DIM + c] = v[i] * r * g[c] + be[c];
    }
}

// ---------------- launch ----------------
extern "C" void kernel_launch(void* const* d_in, const int* in_sizes, int n_in,
                              void* d_out, int out_size) {
    const float* src  = (const float*)d_in[0];
    const float* Wq = (const float*)d_in[2];
    const float* bq = (const float*)d_in[3];
    const float* Wk = (const float*)d_in[4];
    const float* bk = (const float*)d_in[5];
    const float* Wv = (const float*)d_in[6];
    const float* bv = (const float*)d_in[7];
    const float* Wo = (const float*)d_in[8];
    const float* bo = (const float*)d_in[9];
    const float* gamma = (const float*)d_in[10];
    const float* ln1g = (const float*)d_in[11];
    const float* ln1b = (const float*)d_in[12];
    const float* ln2g = (const float*)d_in[13];
    const float* ln2b = (const float*)d_in[14];
    const float* Wg = (const float*)d_in[15];
    const float* bg = (const float*)d_in[16];
    const float* W1 = (const float*)d_in[17];
    const float* b1 = (const float*)d_in[18];
    const float* W2 = (const float*)d_in[19];
    const float* b2 = (const float*)d_in[20];
    float* out = (float*)d_out;

    float *attnp, *attnop, *xp;
    __half *W1htp, *W2htp;
    cudaGetSymbolAddress((void**)&attnp, g_attn);
    cudaGetSymbolAddress((void**)&attnop, g_attno);
    cudaGetSymbolAddress((void**)&xp, g_x);
    cudaGetSymbolAddress((void**)&W1htp, g_W1ht);
    cudaGetSymbolAddress((void**)&W2htp, g_W2ht);

    // weight transpose + fp16 convert (NT layout for fp16 FF cores)
    transpose_cvt<<<dim3(FFD / 32, DIM / 32, NE), dim3(32, 8)>>>(W1, W1htp, DIM, FFD);
    transpose_cvt<<<dim3(DIM / 32, FFD / 32, NE), dim3(32, 8)>>>(W2, W2htp, FFD, DIM);

    // fused QKV projections (fp16 outputs, V transposed) + stats/counter zeroing
    qkv_mma<<<dim3(DIM / 128, NTOK / 128, 3), 256>>>(src, Wq, bq, Wk, bk, Wv, bv);

    // logits = scale * Q K^T  (fp16 operands; per-row stats; fp16 P store)
    qk_mma_h<<<dim3(SEQ / 128, SEQ / 128, BHZ), 256>>>(0.125f);

    // fused zscore+softmax+PV (fp16 operands, BK=32 -> 32 iters)
    pv2_mma<<<dim3(1, SEQ / 128, BHZ), 256>>>(gamma);

    // O projection (BN=64)
    oproj_mma<<<dim3(DIM / 64, NTOK / 128), 256>>>(attnp, Wo, bo, attnop);

    // x = LN1(src + attn_out), fused gating + routing (+ fp16 x)
    add_ln1_gate_kernel<<<NTOK, 256>>>(src, attnop, ln1g, ln1b, Wg, bg, xp);

    // expert FFN in fp16 (sparse top-2)
    ff1_mma_h<<<dim3(FFD / 128, NTOK / 128, NE), 256>>>(b1);
    ff2_mma_h<<<dim3(DIM / 64, NTOK / 128, NE), 256>>>(b2);

    // out = LN2(x + combine(Y))
    add_ln2_moe_kernel<<<NTOK, 256>>>(xp, ln2g, ln2b, out);
}

// round 14
// speedup vs baseline: 1.4111x; 1.0463x over previous
#include <cuda_runtime.h>
#include <cuda_fp16.h>
#include <math.h>
#include <stdint.h>

// ---------------- problem constants ----------------
namespace {
constexpr int BATCH = 2;
constexpr int SEQ   = 1024;
constexpr int DIM   = 768;
constexpr int NH    = 12;
constexpr int HD    = 64;
constexpr int FFD   = 3072;
constexpr int NE    = 4;
constexpr int NTOK  = BATCH * SEQ;     // 2048
constexpr int BHZ   = BATCH * NH;      // 24
constexpr int ROWS_TOT = BHZ * SEQ;    // 24576 attention rows
constexpr float EPSZ  = 1e-5f;
constexpr float EPSLN = 1e-5f;
constexpr int WELEM = DIM * DIM;       // 589824
constexpr int CVT_TOT = NTOK * DIM + 4 * WELEM;
}

// ---------------- scratch (static device memory) ----------------
__device__ __align__(16) __half g_srch[NTOK * DIM];
__device__ __align__(16) __half g_Wqh[WELEM];
__device__ __align__(16) __half g_Wkh[WELEM];
__device__ __align__(16) __half g_Wvh[WELEM];
__device__ __align__(16) __half g_Woh[WELEM];
__device__ __align__(16) __half g_Qh[NTOK * DIM];
__device__ __align__(16) __half g_Kh[NTOK * DIM];
__device__ __align__(16) __half g_Vth[BHZ * HD * SEQ];         // V^T fp16: [b][h][d][t]
__device__ __align__(16) __half g_P[(size_t)BHZ * SEQ * SEQ];  // raw scaled logits (fp16)
__device__ __align__(16) __half g_attnh[NTOK * DIM];
__device__ __align__(16) float g_attno[NTOK * DIM];
__device__ __align__(16) float g_x[NTOK * DIM];
__device__ __align__(16) __half g_xh[NTOK * DIM];
__device__ __align__(16) __half g_H1h[(size_t)NE * NTOK * FFD];
__device__ __align__(16) float g_Y[(size_t)NE * NTOK * DIM];
__device__ __align__(16) __half g_W1ht[(size_t)NE * FFD * DIM];
__device__ __align__(16) __half g_W2ht[(size_t)NE * DIM * FFD];
__device__ float g_rsum[ROWS_TOT];
__device__ float g_rsumsq[ROWS_TOT];
__device__ unsigned g_rmaxe[ROWS_TOT];
__device__ unsigned g_rmine[ROWS_TOT];
__device__ int   g_cnt[NE];
__device__ int   g_list[NE * NTOK];
__device__ int   g_tslot[2 * NTOK];
__device__ float g_tw[2 * NTOK];

// ---------------- primitives ----------------
__device__ __forceinline__ void mma_h(float* d, const uint32_t* a, uint32_t b0, uint32_t b1) {
    asm volatile(
        "mma.sync.aligned.m16n8k16.row.col.f32.f16.f16.f32 "
        "{%0,%1,%2,%3},{%4,%5,%6,%7},{%8,%9},{%0,%1,%2,%3};\n"
        : "+f"(d[0]), "+f"(d[1]), "+f"(d[2]), "+f"(d[3])
        : "r"(a[0]), "r"(a[1]), "r"(a[2]), "r"(a[3]), "r"(b0), "r"(b1));
}
__device__ __forceinline__ void cp_async16u(uint32_t* dst, const __half* src, int sz) {
    uint32_t s = (uint32_t)__cvta_generic_to_shared(dst);
    asm volatile("cp.async.cg.shared.global [%0], [%1], 16, %2;\n"
                 :: "r"(s), "l"(src), "r"(sz));
}
// fp16 tile: rows x 32 halves = 16 words; chunk-xor swizzle; w = word 0..15
__device__ __forceinline__ int swzh(int row, int w) {
    return (row << 4) + ((((w >> 2) ^ ((row >> 1) & 3)) << 2) | (w & 3));
}
__device__ __forceinline__ int chkoff(int row, int c) {   // 16B chunk word offset
    return (row << 4) + ((c ^ ((row >> 1) & 3)) << 2);
}
// ordered-uint encode for float atomic max/min
__device__ __forceinline__ unsigned fenc(float f) {
    unsigned u = __float_as_uint(f);
    return (u & 0x80000000u) ? ~u : (u | 0x80000000u);
}
__device__ __forceinline__ float fdec(unsigned u) {
    unsigned b = (u & 0x80000000u) ? (u ^ 0x80000000u) : ~u;
    return __uint_as_float(b);
}

// ---------------- fp16 NT MMA core: BM=128, BK=32 halves, 3-stage ----------------
template<int BN>
__device__ __forceinline__ void mma_core_h(
    const __half* pa, int sa, const __half* pb,
    int K, uint32_t* smem, float (&acc)[(BN == 128) ? 4 : 2][4][4])
{
    constexpr int MT  = (BN == 128) ? 4 : 2;
    constexpr int WN  = (BN == 128) ? 4 : 2;
    constexpr int ASZ = 128 * 16;            // words
    constexpr int BSZ = BN * 16;
    constexpr int STG = ASZ + BSZ;
    const int tid = threadIdx.x;
    const int lane = tid & 31, wid = tid >> 5;
    const int wm = wid / WN, wn = wid % WN;
    const int gid = lane >> 2, tig = lane & 3;
    const int arow_ld = tid >> 1, ac = (tid & 1) * 2;
    const int aoff0 = chkoff(arow_ld, ac);
    const int aoff1 = chkoff(arow_ld, ac + 1);
    const int brow_ld = (BN == 128) ? (tid >> 1) : (tid >> 2);
    const int bc = (BN == 128) ? ((tid & 1) * 2) : (tid & 3);
    const int boff0 = chkoff(brow_ld, bc);
    const int boff1 = chkoff(brow_ld, bc + 1);

    auto issue = [&](int i) {
        uint32_t* As = smem + (i % 3) * STG;
        uint32_t* Bs = As + ASZ;
        const int kt = i << 5;
        cp_async16u(As + aoff0, pa + kt + ac * 8, sa);
        cp_async16u(As + aoff1, pa + kt + ac * 8 + 8, sa);
        cp_async16u(Bs + boff0, pb + kt + bc * 8, 16);
        if (BN == 128) cp_async16u(Bs + boff1, pb + kt + bc * 8 + 8, 16);
        asm volatile("cp.async.commit_group;\n" ::: "memory");
    };
    auto compute = [&](int s) {
        const uint32_t* As = smem + s * STG;
        const uint32_t* Bs = As + ASZ;
#pragma unroll
        for (int ks = 0; ks < 2; ks++) {
            const int w0 = ks * 8 + tig;
            uint32_t af[MT][4];
#pragma unroll
            for (int mt = 0; mt < MT; mt++) {
                const int ar = wm * (MT * 16) + mt * 16 + gid;
                af[mt][0] = As[swzh(ar, w0)];
                af[mt][1] = As[swzh(ar + 8, w0)];
                af[mt][2] = As[swzh(ar, w0 + 4)];
                af[mt][3] = As[swzh(ar + 8, w0 + 4)];
            }
#pragma unroll
            for (int nt = 0; nt < 4; nt++) {
                const int br = wn * 32 + nt * 8 + gid;
                uint32_t b0 = Bs[swzh(br, w0)];
                uint32_t b1 = Bs[swzh(br, w0 + 4)];
#pragma unroll
                for (int mt = 0; mt < MT; mt++) mma_h(acc[mt][nt], af[mt], b0, b1);
            }
        }
    };

    const int nk = K >> 5;
    issue(0);
    if (nk > 1) issue(1);
    for (int i = 0; i < nk; i++) {
        if (i + 1 < nk) asm volatile("cp.async.wait_group 1;\n" ::: "memory");
        else            asm volatile("cp.async.wait_group 0;\n" ::: "memory");
        __syncthreads();
        if (i + 2 < nk) issue(i + 2);
        compute(i % 3);
    }
}

// ---------------- fp32 -> fp16 convert: src + 4 attention weights ----------------
__global__ void cvt_inputs(const float* __restrict__ src,
                           const float* __restrict__ Wq, const float* __restrict__ Wk,
                           const float* __restrict__ Wv, const float* __restrict__ Wo)
{
    int i = blockIdx.x * 256 + threadIdx.x;
    if (i >= CVT_TOT) return;
    if (i < NTOK * DIM) { g_srch[i] = __float2half(src[i]); return; }
    int j = i - NTOK * DIM;
    int w = j / WELEM, k = j % WELEM;
    if (w == 0) g_Wqh[k] = __float2half(Wq[k]);
    else if (w == 1) g_Wkh[k] = __float2half(Wk[k]);
    else if (w == 2) g_Wvh[k] = __float2half(Wv[k]);
    else g_Woh[k] = __float2half(Wo[k]);
}

// ---------------- weight transpose + fp32->fp16 (W1/W2) ----------------
__global__ void transpose_cvt(const float* __restrict__ in, __half* __restrict__ out,
                              int R, int C)
{
    __shared__ float t[32][33];
    int e = blockIdx.z;
    in += (size_t)e * R * C;
    out += (size_t)e * R * C;
    int c0 = blockIdx.x * 32, r0 = blockIdx.y * 32;
    int tx = threadIdx.x, ty = threadIdx.y;
#pragma unroll
    for (int i = 0; i < 32; i += 8)
        t[ty + i][tx] = in[(size_t)(r0 + ty + i) * C + c0 + tx];
    __syncthreads();
#pragma unroll
    for (int i = 0; i < 32; i += 8)
        out[(size_t)(c0 + ty + i) * R + r0 + tx] = __float2half(t[tx][ty + i]);
}

// ---------------- fused QKV projection, fp16 (z: 0=Q,1=K,2=V-transposed) ----------------
__global__ __launch_bounds__(256, 2) void qkv_mma_h(
    const float* __restrict__ bq, const float* __restrict__ bk,
    const float* __restrict__ bv)
{
    __shared__ uint32_t smem[3 * (128 * 16 + 128 * 16)];
    const int tid = threadIdx.x;
    {   // fold zero_stats: 288 CTAs x 256 threads cover ROWS_TOT
        int gbid = (blockIdx.z * gridDim.y + blockIdx.y) * gridDim.x + blockIdx.x;
        int gidx = gbid * 256 + tid;
        if (gidx < ROWS_TOT) {
            g_rsum[gidx] = 0.f;
            g_rsumsq[gidx] = 0.f;
            g_rmaxe[gidx] = fenc(-3e38f);
            g_rmine[gidx] = fenc(3e38f);
        }
        if (gidx < NE) g_cnt[gidx] = 0;
    }
    const int lane = tid & 31, wid = tid >> 5;
    const int wm = wid / 4, wn = wid % 4;
    const int gid = lane >> 2, tig = lane & 3;
    float acc[4][4][4] = {};
    const int which = blockIdx.z;
    const __half* W = (which == 0) ? g_Wqh : (which == 1) ? g_Wkh : g_Wvh;
    const float* bias = (which == 0) ? bq : (which == 1) ? bk : bv;
    const int m0 = blockIdx.y * 128, n0 = blockIdx.x * 128;
    const __half* pa = g_srch + (size_t)(m0 + (tid >> 1)) * DIM;
    const __half* pb = W + (size_t)(n0 + (tid >> 1)) * DIM;
    mma_core_h<128>(pa, 16, pb, DIM, smem, acc);
#pragma unroll
    for (int mt = 0; mt < 4; mt++) {
#pragma unroll
        for (int nt = 0; nt < 4; nt++) {
            int row = m0 + wm * 64 + mt * 16 + gid;
            int col = n0 + wn * 32 + nt * 8 + 2 * tig;
            float c0 = acc[mt][nt][0] + bias[col];
            float c1 = acc[mt][nt][1] + bias[col + 1];
            float c2 = acc[mt][nt][2] + bias[col];
            float c3 = acc[mt][nt][3] + bias[col + 1];
            if (which == 0) {
                *(__half2*)(g_Qh + (size_t)row * DIM + col) = __floats2half2_rn(c0, c1);
                *(__half2*)(g_Qh + (size_t)(row + 8) * DIM + col) = __floats2half2_rn(c2, c3);
            } else if (which == 1) {
                *(__half2*)(g_Kh + (size_t)row * DIM + col) = __floats2half2_rn(c0, c1);
                *(__half2*)(g_Kh + (size_t)(row + 8) * DIM + col) = __floats2half2_rn(c2, c3);
            } else {
                float vals[4] = {c0, c1, c2, c3};
#pragma unroll
                for (int q = 0; q < 4; q++) {
                    int rr = row + (q >> 1) * 8;
                    int cc = col + (q & 1);
                    int bb = rr >> 10, tt = rr & 1023;
                    int h = cc >> 6, d = cc & 63;
                    g_Vth[(((size_t)bb * NH + h) * HD + d) * SEQ + tt] = __float2half(vals[q]);
                }
            }
        }
    }
}

// ---------------- O projection fp16 (BN=64) ----------------
__global__ __launch_bounds__(256, 2) void oproj_mma_h(
    const float* __restrict__ bias, float* __restrict__ C)
{
    __shared__ uint32_t smem[3 * (128 * 16 + 64 * 16)];
    const int tid = threadIdx.x;
    const int lane = tid & 31, wid = tid >> 5;
    const int wm = wid / 2, wn = wid % 2;
    const int gid = lane >> 2, tig = lane & 3;
    float acc[2][4][4] = {};
    const int m0 = blockIdx.y * 128, n0 = blockIdx.x * 64;
    const __half* pa = g_attnh + (size_t)(m0 + (tid >> 1)) * DIM;
    const __half* pb = g_Woh + (size_t)(n0 + (tid >> 2)) * DIM;
    mma_core_h<64>(pa, 16, pb, DIM, smem, acc);
#pragma unroll
    for (int mt = 0; mt < 2; mt++) {
#pragma unroll
        for (int nt = 0; nt < 4; nt++) {
            int row = m0 + wm * 32 + mt * 16 + gid;
            int col = n0 + wn * 32 + nt * 8 + 2 * tig;
            float b0 = bias[col], b1 = bias[col + 1];
            *(float2*)(C + (size_t)row * DIM + col) =
                make_float2(acc[mt][nt][0] + b0, acc[mt][nt][1] + b1);
            *(float2*)(C + (size_t)(row + 8) * DIM + col) =
                make_float2(acc[mt][nt][2] + b0, acc[mt][nt][3] + b1);
        }
    }
}

// ---------------- QK^T in fp16 + per-row stats epilogue (fp16 P store) ----------------
__global__ __launch_bounds__(256, 2) void qk_mma_h(float scale)
{
    __shared__ uint32_t smem[3 * (128 * 16 + 128 * 16)];
    const int tid = threadIdx.x;
    const int lane = tid & 31, wid = tid >> 5;
    const int wm = wid / 4, wn = wid % 4;
    const int gid = lane >> 2, tig = lane & 3;
    float acc[4][4][4] = {};
    const int z = blockIdx.z, b = z / NH, h = z % NH;
    const int m0 = blockIdx.y * 128, n0 = blockIdx.x * 128;
    const __half* pa = g_Qh + ((size_t)(b * SEQ + m0 + (tid >> 1))) * DIM + h * HD;
    const __half* pb = g_Kh + ((size_t)(b * SEQ + n0 + (tid >> 1))) * DIM + h * HD;
    __half* Cb = g_P + (size_t)z * SEQ * SEQ;
    mma_core_h<128>(pa, 16, pb, HD, smem, acc);
    const size_t rowbase = (size_t)z * SEQ + m0;
#pragma unroll
    for (int mt = 0; mt < 4; mt++) {
        float s0 = 0.f, q0 = 0.f, s8 = 0.f, q8 = 0.f;
        float mx0 = -3e38f, mn0 = 3e38f, mx8 = -3e38f, mn8 = 3e38f;
#pragma unroll
        for (int nt = 0; nt < 4; nt++) {
            int row = m0 + wm * 64 + mt * 16 + gid;
            int col = n0 + wn * 32 + nt * 8 + 2 * tig;
            float v0 = acc[mt][nt][0] * scale, v1 = acc[mt][nt][1] * scale;
            float v2 = acc[mt][nt][2] * scale, v3 = acc[mt][nt][3] * scale;
            *(__half2*)(Cb + (size_t)row * SEQ + col) = __floats2half2_rn(v0, v1);
            *(__half2*)(Cb + (size_t)(row + 8) * SEQ + col) = __floats2half2_rn(v2, v3);
            s0 += v0 + v1; q0 += v0 * v0 + v1 * v1;
            mx0 = fmaxf(mx0, fmaxf(v0, v1)); mn0 = fminf(mn0, fminf(v0, v1));
            s8 += v2 + v3; q8 += v2 * v2 + v3 * v3;
            mx8 = fmaxf(mx8, fmaxf(v2, v3)); mn8 = fminf(mn8, fminf(v2, v3));
        }
#pragma unroll
        for (int o = 1; o < 4; o <<= 1) {
            s0 += __shfl_xor_sync(~0u, s0, o); q0 += __shfl_xor_sync(~0u, q0, o);
            s8 += __shfl_xor_sync(~0u, s8, o); q8 += __shfl_xor_sync(~0u, q8, o);
            mx0 = fmaxf(mx0, __shfl_xor_sync(~0u, mx0, o));
            mn0 = fminf(mn0, __shfl_xor_sync(~0u, mn0, o));
            mx8 = fmaxf(mx8, __shfl_xor_sync(~0u, mx8, o));
            mn8 = fminf(mn8, __shfl_xor_sync(~0u, mn8, o));
        }
        if (tig == 0) {
            size_t r0 = rowbase + wm * 64 + mt * 16 + gid;
            atomicAdd(&g_rsum[r0], s0);   atomicAdd(&g_rsumsq[r0], q0);
            atomicMax(&g_rmaxe[r0], fenc(mx0)); atomicMin(&g_rmine[r0], fenc(mn0));
            atomicAdd(&g_rsum[r0 + 8], s8); atomicAdd(&g_rsumsq[r0 + 8], q8);
            atomicMax(&g_rmaxe[r0 + 8], fenc(mx8)); atomicMin(&g_rmine[r0 + 8], fenc(mn8));
        }
    }
}

// ---------------- fused zscore-softmax + P@V, all-fp16 operands (BK=32) ----------------
__global__ __launch_bounds__(256, 2) void pv2_mma(const float* __restrict__ gamma)
{
    __shared__ uint32_t Asm[2][128 * 16];
    __shared__ uint32_t Bsm[3][64 * 16];
    __shared__ float denom_s[128];
    __shared__ float2 rowc_s[128];
    const int tid = threadIdx.x;
    const int lane = tid & 31, wid = tid >> 5;
    const int wm = wid / 2, wn = wid % 2;
    const int gid = lane >> 2, tig = lane & 3;
    const int brow = tid >> 2, bc = tid & 3;
    const int boff = chkoff(brow, bc);
    const int arow = tid >> 1, acq = tid & 1;
    const int aoff0 = chkoff(arow, 2 * acq);
    const int aoff1 = chkoff(arow, 2 * acq + 1);
    float acc[2][4][4] = {};
    const int z = blockIdx.z, b = z / NH, h = z % NH;
    const int m0 = blockIdx.y * 128;
    const __half* Arow = g_P + ((size_t)z * SEQ + m0 + arow) * SEQ + 16 * acq;
    const __half* Brow = g_Vth + (size_t)z * HD * SEQ + (size_t)brow * SEQ;
    float esum = 0.f;
    constexpr int nk = SEQ / 32;  // 32

    auto issueB = [&](int i) {
        cp_async16u(Bsm[i % 3] + boff, Brow + (i << 5) + bc * 8, 16);
        asm volatile("cp.async.commit_group;\n" ::: "memory");
    };
    auto compute = [&](const uint32_t* As, const uint32_t* Bs) {
#pragma unroll
        for (int ks = 0; ks < 2; ks++) {
            const int w0 = ks * 8 + tig;
            uint32_t af[2][4];
#pragma unroll
            for (int mt = 0; mt < 2; mt++) {
                const int ar = wm * 32 + mt * 16 + gid;
                af[mt][0] = As[swzh(ar, w0)];
                af[mt][1] = As[swzh(ar + 8, w0)];
                af[mt][2] = As[swzh(ar, w0 + 4)];
                af[mt][3] = As[swzh(ar + 8, w0 + 4)];
            }
#pragma unroll
            for (int nt = 0; nt < 4; nt++) {
                const int br = wn * 32 + nt * 8 + gid;
                uint32_t b0 = Bs[swzh(br, w0)];
                uint32_t b1 = Bs[swzh(br, w0 + 4)];
#pragma unroll
                for (int mt = 0; mt < 2; mt++) mma_h(acc[mt][nt], af[mt], b0, b1);
            }
        }
    };

    issueB(0);
    issueB(1);
    if (tid < 128) {
        size_t i = (size_t)z * SEQ + m0 + tid;
        float s = g_rsum[i], q = g_rsumsq[i];
        float mean = s * (1.f / SEQ);
        float var = fmaxf((q - s * s * (1.f / SEQ)) * (1.f / (SEQ - 1)), 0.f);
        float c1 = (*gamma) / (sqrtf(var) + EPSZ);
        float mx = fdec(g_rmaxe[i]), mn = fdec(g_rmine[i]);
        float zmax = fmaxf(c1 * (mx - mean), c1 * (mn - mean));
        rowc_s[tid] = make_float2(c1, -mean * c1 - zmax);
    }
    __syncthreads();
    const float2 rc = rowc_s[arow];
    uint4 a0 = *(const uint4*)(Arow);
    uint4 a1 = *(const uint4*)(Arow + 8);
    for (int i = 0; i < nk; i++) {
        if (i + 1 < nk) asm volatile("cp.async.wait_group 1;\n" ::: "memory");
        else            asm volatile("cp.async.wait_group 0;\n" ::: "memory");
        __syncthreads();
        if (i + 2 < nk) issueB(i + 2);
        uint4 o0, o1;
        {
            const uint32_t* aw = &a0.x;
            uint32_t* ow = &o0.x;
#pragma unroll
            for (int w = 0; w < 4; w++) {
                float2 f = __half22float2(*(const __half2*)&aw[w]);
                float ex = __expf(fmaf(f.x, rc.x, rc.y));
                float ey = __expf(fmaf(f.y, rc.x, rc.y));
                esum += ex + ey;
                *(__half2*)&ow[w] = __floats2half2_rn(ex, ey);
            }
            const uint32_t* aw1 = &a1.x;
            uint32_t* ow1 = &o1.x;
#pragma unroll
            for (int w = 0; w < 4; w++) {
                float2 f = __half22float2(*(const __half2*)&aw1[w]);
                float ex = __expf(fmaf(f.x, rc.x, rc.y));
                float ey = __expf(fmaf(f.y, rc.x, rc.y));
                esum += ex + ey;
                *(__half2*)&ow1[w] = __floats2half2_rn(ex, ey);
            }
        }
        *(uint4*)(Asm[i & 1] + aoff0) = o0;
        *(uint4*)(Asm[i & 1] + aoff1) = o1;
        if (i + 1 < nk) {
            a0 = *(const uint4*)(Arow + ((i + 1) << 5));
            a1 = *(const uint4*)(Arow + ((i + 1) << 5) + 8);
        }
        __syncthreads();
        compute(Asm[i & 1], Bsm[i % 3]);
    }
    esum += __shfl_xor_sync(~0u, esum, 1);
    if (acq == 0) denom_s[arow] = esum;
    __syncthreads();
#pragma unroll
    for (int mt = 0; mt < 2; mt++) {
#pragma unroll
        for (int nt = 0; nt < 4; nt++) {
            int ro = wm * 32 + mt * 16 + gid;
            int col = wn * 32 + nt * 8 + 2 * tig;
            float r0 = 1.f / denom_s[ro];
            float r8 = 1.f / denom_s[ro + 8];
            int row = m0 + ro;
            __half* c0 = g_attnh + ((size_t)(b * SEQ + row)) * DIM + h * HD + col;
            __half* c1 = g_attnh + ((size_t)(b * SEQ + row + 8)) * DIM + h * HD + col;
            *(__half2*)c0 = __floats2half2_rn(acc[mt][nt][0] * r0, acc[mt][nt][1] * r0);
            *(__half2*)c1 = __floats2half2_rn(acc[mt][nt][2] * r8, acc[mt][nt][3] * r8);
        }
    }
}

// ---------------- FF1 fp16: H1h = relu(xh[list] @ W1ht^T + b1) ----------------
__global__ __launch_bounds__(256, 2) void ff1_mma_h(const float* __restrict__ b1)
{
    const int e = blockIdx.z;
    const int cnt = g_cnt[e];
    const int m0 = blockIdx.y * 128;
    if (m0 >= cnt) return;
    __shared__ uint32_t smem[3 * (128 * 16 + 128 * 16)];
    const int tid = threadIdx.x;
    const int lane = tid & 31, wid = tid >> 5;
    const int wm = wid / 4, wn = wid % 4;
    const int gid = lane >> 2, tig = lane & 3;
    float acc[4][4][4] = {};
    const int n0 = blockIdx.x * 128;
    const int r = m0 + (tid >> 1);
    const __half* pa = g_xh; int sa = 0;
    if (r < cnt) { pa = g_xh + (size_t)g_list[e * NTOK + r] * DIM; sa = 16; }
    const __half* pb = g_W1ht + (size_t)e * FFD * DIM + (size_t)(n0 + (tid >> 1)) * DIM;
    const float* bb = b1 + e * FFD;
    __half* Hout = g_H1h + (size_t)e * NTOK * FFD;
    mma_core_h<128>(pa, sa, pb, DIM, smem, acc);
#pragma unroll
    for (int mt = 0; mt < 4; mt++) {
#pragma unroll
        for (int nt = 0; nt < 4; nt++) {
            int lm = m0 + wm * 64 + mt * 16 + gid;
            int col = n0 + wn * 32 + nt * 8 + 2 * tig;
            float b0 = bb[col], b1v = bb[col + 1];
            if (lm < cnt) {
                *(__half2*)(Hout + (size_t)lm * FFD + col) =
                    __floats2half2_rn(fmaxf(acc[mt][nt][0] + b0, 0.f),
                                      fmaxf(acc[mt][nt][1] + b1v, 0.f));
            }
            if (lm + 8 < cnt) {
                *(__half2*)(Hout + (size_t)(lm + 8) * FFD + col) =
                    __floats2half2_rn(fmaxf(acc[mt][nt][2] + b0, 0.f),
                                      fmaxf(acc[mt][nt][3] + b1v, 0.f));
            }
        }
    }
}

// ---------------- FF2 fp16 (BN=64): Y = H1h @ W2ht^T + b2 ----------------
__global__ __launch_bounds__(256, 2) void ff2_mma_h(const float* __restrict__ b2)
{
    const int e = blockIdx.z;
    const int cnt = g_cnt[e];
    const int m0 = blockIdx.y * 128;
    if (m0 >= cnt) return;
    __shared__ uint32_t smem[3 * (128 * 16 + 64 * 16)];
    const int tid = threadIdx.x;
    const int lane = tid & 31, wid = tid >> 5;
    const int wm = wid / 2, wn = wid % 2;
    const int gid = lane >> 2, tig = lane & 3;
    float acc[2][4][4] = {};
    const int n0 = blockIdx.x * 64;
    const __half* Ab = g_H1h + (size_t)e * NTOK * FFD;
    const int r = m0 + (tid >> 1);
    const __half* pa = Ab; int sa = 0;
    if (r < cnt) { pa = Ab + (size_t)r * FFD; sa = 16; }
    const __half* pb = g_W2ht + (size_t)e * DIM * FFD + (size_t)(n0 + (tid >> 2)) * FFD;
    const float* bb = b2 + e * DIM;
    float* Yout = g_Y + (size_t)e * NTOK * DIM;
    mma_core_h<64>(pa, sa, pb, FFD, smem, acc);
#pragma unroll
    for (int mt = 0; mt < 2; mt++) {
#pragma unroll
        for (int nt = 0; nt < 4; nt++) {
            int lm = m0 + wm * 32 + mt * 16 + gid;
            int col = n0 + wn * 32 + nt * 8 + 2 * tig;
            float b0 = bb[col], b1v = bb[col + 1];
            if (lm < cnt) {
                *(float2*)(Yout + (size_t)lm * DIM + col) =
                    make_float2(acc[mt][nt][0] + b0, acc[mt][nt][1] + b1v);
            }
            if (lm + 8 < cnt) {
                *(float2*)(Yout + (size_t)(lm + 8) * DIM + col) =
                    make_float2(acc[mt][nt][2] + b0, acc[mt][nt][3] + b1v);
            }
        }
    }
}

// ---------------- reductions ----------------
__device__ __forceinline__ float blockReduceSum(float v) {
    __shared__ float red[8];
    int lane = threadIdx.x & 31, wid = threadIdx.x >> 5;
#pragma unroll
    for (int o = 16; o > 0; o >>= 1) v += __shfl_xor_sync(0xffffffffu, v, o);
    __syncthreads();
    if (lane == 0) red[wid] = v;
    __syncthreads();
    float r = (lane < 8) ? red[lane] : 0.f;
#pragma unroll
    for (int o = 16; o > 0; o >>= 1) r += __shfl_xor_sync(0xffffffffu, r, o);
    return r;
}

// ---------------- LN1 + fused gating (also emits x fp16) ----------------
__global__ void add_ln1_gate_kernel(const float* __restrict__ a, const float* __restrict__ b,
                                    const float* __restrict__ g, const float* __restrict__ be,
                                    const float* __restrict__ Wg, const float* __restrict__ bg,
                                    float* __restrict__ out) {
    int t = blockIdx.x, tid = threadIdx.x;
    const float* ar = a + (size_t)t * DIM;
    const float* br = b + (size_t)t * DIM;
    float v[3];
#pragma unroll
    for (int i = 0; i < 3; i++) v[i] = ar[tid + i * 256] + br[tid + i * 256];
    float mean = blockReduceSum(v[0] + v[1] + v[2]) * (1.f / DIM);
    float sq = 0.f;
#pragma unroll
    for (int i = 0; i < 3; i++) { v[i] -= mean; sq += v[i] * v[i]; }
    float var = blockReduceSum(sq) * (1.f / DIM);
    float r = rsqrtf(var + EPSLN);
    float xv[3];
    float gp0 = 0.f, gp1 = 0.f, gp2 = 0.f, gp3 = 0.f;
#pragma unroll
    for (int i = 0; i < 3; i++) {
        int c = tid + i * 256;
        xv[i] = v[i] * r * g[c] + be[c];
        out[(size_t)t * DIM + c] = xv[i];
        g_xh[(size_t)t * DIM + c] = __float2half(xv[i]);
        gp0 += xv[i] * Wg[c];
        gp1 += xv[i] * Wg[DIM + c];
        gp2 += xv[i] * Wg[2 * DIM + c];
        gp3 += xv[i] * Wg[3 * DIM + c];
    }
    float s0 = blockReduceSum(gp0);
    float s1 = blockReduceSum(gp1);
    float s2 = blockReduceSum(gp2);
    float s3 = blockReduceSum(gp3);
    if (tid == 0) {
        float s[4] = {s0 + bg[0], s1 + bg[1], s2 + bg[2], s3 + bg[3]};
        float mx = fmaxf(fmaxf(s[0], s[1]), fmaxf(s[2], s[3]));
        float p[4], sum = 0.f;
#pragma unroll
        for (int e = 0; e < 4; e++) { p[e] = expf(s[e] - mx); sum += p[e]; }
        float ri = 1.f / sum;
#pragma unroll
        for (int e = 0; e < 4; e++) p[e] *= ri;
        int i1 = 0;
#pragma unroll
        for (int e = 1; e < 4; e++) if (p[e] > p[i1]) i1 = e;
        int i2 = (i1 == 0) ? 1 : 0;
#pragma unroll
        for (int e = 0; e < 4; e++) if (e != i1 && p[e] > p[i2]) i2 = e;
        int slot = atomicAdd(&g_cnt[i1], 1);
        g_list[i1 * NTOK + slot] = t;
        g_tslot[t] = i1 * NTOK + slot;
        g_tw[t] = p[i1];
        slot = atomicAdd(&g_cnt[i2], 1);
        g_list[i2 * NTOK + slot] = t;
        g_tslot[NTOK + t] = i2 * NTOK + slot;
        g_tw[NTOK + t] = p[i2];
    }
}

// ---------------- LN2 + MoE combine ----------------
__global__ void add_ln2_moe_kernel(const float* __restrict__ x,
                                   const float* __restrict__ g, const float* __restrict__ be,
                                   float* __restrict__ out) {
    int t = blockIdx.x, tid = threadIdx.x;
    int s1 = g_tslot[t], s2 = g_tslot[NTOK + t];
    float w1 = g_tw[t], w2 = g_tw[NTOK + t];
    const float* y1 = g_Y + (size_t)s1 * DIM;
    const float* y2 = g_Y + (size_t)s2 * DIM;
    const float* xr = x + (size_t)t * DIM;
    float v[3];
#pragma unroll
    for (int i = 0; i < 3; i++) {
        int c = tid + i * 256;
        v[i] = xr[c] + w1 * y1[c] + w2 * y2[c];
    }
    float mean = blockReduceSum(v[0] + v[1] + v[2]) * (1.f / DIM);
    float sq = 0.f;
#pragma unroll
    for (int i = 0; i < 3; i++) { v[i] -= mean; sq += v[i] * v[i]; }
    float var = blockReduceSum(sq) * (1.f / DIM);
    float r = rsqrtf(var + EPSLN);
#pragma unroll
    for (int i = 0; i < 3; i++) {
        int c = tid + i * 256;
        out[(size_t)t * DIM + c] = v[i] * r * g[c] + be[c];
    }
}

// ---------------- launch ----------------
extern "C" void kernel_launch(void* const* d_in, const int* in_sizes, int n_in,
                              void* d_out, int out_size) {
    const float* src  = (const float*)d_in[0];
    const float* Wq = (const float*)d_in[2];
    const float* bq = (const float*)d_in[3];
    const float* Wk = (const float*)d_in[4];
    const float* bk = (const float*)d_in[5];
    const float* Wv = (const float*)d_in[6];
    const float* bv = (const float*)d_in[7];
    const float* Wo = (const float*)d_in[8];
    const float* bo = (const float*)d_in[9];
    const float* gamma = (const float*)d_in[10];
    const float* ln1g = (const float*)d_in[11];
    const float* ln1b = (const float*)d_in[12];
    const float* ln2g = (const float*)d_in[13];
    const float* ln2b = (const float*)d_in[14];
    const float* Wg = (const float*)d_in[15];
    const float* bg = (const float*)d_in[16];
    const float* W1 = (const float*)d_in[17];
    const float* b1 = (const float*)d_in[18];
    const float* W2 = (const float*)d_in[19];
    const float* b2 = (const float*)d_in[20];
    float* out = (float*)d_out;

    float *attnop, *xp;
    __half *W1htp, *W2htp;
    cudaGetSymbolAddress((void**)&attnop, g_attno);
    cudaGetSymbolAddress((void**)&xp, g_x);
    cudaGetSymbolAddress((void**)&W1htp, g_W1ht);
    cudaGetSymbolAddress((void**)&W2htp, g_W2ht);

    // fp32->fp16 converts: src + attention weights; W1/W2 transpose+convert
    cvt_inputs<<<(CVT_TOT + 255) / 256, 256>>>(src, Wq, Wk, Wv, Wo);
    transpose_cvt<<<dim3(FFD / 32, DIM / 32, NE), dim3(32, 8)>>>(W1, W1htp, DIM, FFD);
    transpose_cvt<<<dim3(DIM / 32, FFD / 32, NE), dim3(32, 8)>>>(W2, W2htp, FFD, DIM);

    // fused QKV projections fp16 (V transposed) + stats/counter zeroing
    qkv_mma_h<<<dim3(DIM / 128, NTOK / 128, 3), 256>>>(bq, bk, bv);

    // logits = scale * Q K^T  (fp16 operands; per-row stats; fp16 P store)
    qk_mma_h<<<dim3(SEQ / 128, SEQ / 128, BHZ), 256>>>(0.125f);

    // fused zscore+softmax+PV (fp16; attn stored fp16)
    pv2_mma<<<dim3(1, SEQ / 128, BHZ), 256>>>(gamma);

    // O projection fp16 (BN=64)
    oproj_mma_h<<<dim3(DIM / 64, NTOK / 128), 256>>>(bo, attnop);

    // x = LN1(src + attn_out), fused gating + routing (+ fp16 x)
    add_ln1_gate_kernel<<<NTOK, 256>>>(src, attnop, ln1g, ln1b, Wg, bg, xp);

    // expert FFN in fp16 (sparse top-2)
    ff1_mma_h<<<dim3(FFD / 128, NTOK / 128, NE), 256>>>(b1);
    ff2_mma_h<<<dim3(DIM / 64, NTOK / 128, NE), 256>>>(b2);

    // out = LN2(x + combine(Y))
    add_ln2_moe_kernel<<<NTOK, 256>>>(xp, ln2g, ln2b, out);
}

// round 15
// speedup vs baseline: 1.6643x; 1.1794x over previous
#include <cuda_runtime.h>
#include <cuda_fp16.h>
#include <math.h>
#include <stdint.h>

// ---------------- problem constants ----------------
namespace {
constexpr int BATCH = 2;
constexpr int SEQ   = 1024;
constexpr int DIM   = 768;
constexpr int NH    = 12;
constexpr int HD    = 64;
constexpr int FFD   = 3072;
constexpr int NE    = 4;
constexpr int NTOK  = BATCH * SEQ;     // 2048
constexpr int BHZ   = BATCH * NH;      // 24
constexpr int ROWS_TOT = BHZ * SEQ;    // 24576 attention rows
constexpr float EPSZ  = 1e-5f;
constexpr float EPSLN = 1e-5f;
constexpr int WELEM = DIM * DIM;       // 589824
constexpr int CVT_TOT = NTOK * DIM + 4 * WELEM;
}

// ---------------- scratch (static device memory) ----------------
__device__ __align__(16) __half g_srch[NTOK * DIM];
__device__ __align__(16) __half g_Wqh[WELEM];
__device__ __align__(16) __half g_Wkh[WELEM];
__device__ __align__(16) __half g_Wvh[WELEM];
__device__ __align__(16) __half g_Woh[WELEM];
__device__ __align__(16) __half g_Qh[NTOK * DIM];
__device__ __align__(16) __half g_Kh[NTOK * DIM];
__device__ __align__(16) __half g_Vth[BHZ * HD * SEQ];         // V^T fp16: [b][h][d][t]
__device__ __align__(16) __half g_P[(size_t)BHZ * SEQ * SEQ];  // raw scaled logits (fp16)
__device__ __align__(16) __half g_attnh[NTOK * DIM];
__device__ __align__(16) float g_attno[NTOK * DIM];
__device__ __align__(16) float g_x[NTOK * DIM];
__device__ __align__(16) __half g_xh[NTOK * DIM];
__device__ __align__(16) __half g_H1h[(size_t)NE * NTOK * FFD];
__device__ __align__(16) float g_Y[(size_t)NE * NTOK * DIM];
__device__ __align__(16) __half g_W1ht[(size_t)NE * FFD * DIM];
__device__ __align__(16) __half g_W2ht[(size_t)NE * DIM * FFD];
__device__ float g_rsum[ROWS_TOT];
__device__ float g_rsumsq[ROWS_TOT];
__device__ unsigned g_rmaxe[ROWS_TOT];
__device__ unsigned g_rmine[ROWS_TOT];
__device__ int   g_cnt[NE];
__device__ int   g_list[NE * NTOK];
__device__ int   g_tslot[2 * NTOK];
__device__ float g_tw[2 * NTOK];

// ---------------- primitives ----------------
__device__ __forceinline__ void mma_h(float* d, const uint32_t* a, uint32_t b0, uint32_t b1) {
    asm volatile(
        "mma.sync.aligned.m16n8k16.row.col.f32.f16.f16.f32 "
        "{%0,%1,%2,%3},{%4,%5,%6,%7},{%8,%9},{%0,%1,%2,%3};\n"
        : "+f"(d[0]), "+f"(d[1]), "+f"(d[2]), "+f"(d[3])
        : "r"(a[0]), "r"(a[1]), "r"(a[2]), "r"(a[3]), "r"(b0), "r"(b1));
}
__device__ __forceinline__ void cp_async16u(uint32_t* dst, const __half* src, int sz) {
    uint32_t s = (uint32_t)__cvta_generic_to_shared(dst);
    asm volatile("cp.async.cg.shared.global [%0], [%1], 16, %2;\n"
                 :: "r"(s), "l"(src), "r"(sz));
}
__device__ __forceinline__ void ldmx4(uint32_t* r, uint32_t saddr) {
    asm volatile("ldmatrix.sync.aligned.m8n8.x4.shared.b16 {%0,%1,%2,%3}, [%4];\n"
                 : "=r"(r[0]), "=r"(r[1]), "=r"(r[2]), "=r"(r[3]) : "r"(saddr));
}
// fp16 tile: rows x 32 halves = 16 words; chunk-xor swizzle; w = word 0..15
__device__ __forceinline__ int swzh(int row, int w) {
    return (row << 4) + ((((w >> 2) ^ ((row >> 1) & 3)) << 2) | (w & 3));
}
__device__ __forceinline__ int chkoff(int row, int c) {   // 16B chunk word offset
    return (row << 4) + ((c ^ ((row >> 1) & 3)) << 2);
}
// ordered-uint encode for float atomic max/min
__device__ __forceinline__ unsigned fenc(float f) {
    unsigned u = __float_as_uint(f);
    return (u & 0x80000000u) ? ~u : (u | 0x80000000u);
}
__device__ __forceinline__ float fdec(unsigned u) {
    unsigned b = (u & 0x80000000u) ? (u ^ 0x80000000u) : ~u;
    return __uint_as_float(b);
}

// ---------------- fp16 NT MMA core: BM=128, BK=32 halves, 3-stage, ldmatrix ----------------
template<int BN>
__device__ __forceinline__ void mma_core_h(
    const __half* pa, int sa, const __half* pb,
    int K, uint32_t* smem, float (&acc)[(BN == 128) ? 4 : 2][4][4])
{
    constexpr int MT  = (BN == 128) ? 4 : 2;
    constexpr int WN  = (BN == 128) ? 4 : 2;
    constexpr int ASZ = 128 * 16;            // words
    constexpr int BSZ = BN * 16;
    constexpr int STG = ASZ + BSZ;
    const int tid = threadIdx.x;
    const int lane = tid & 31, wid = tid >> 5;
    const int wm = wid / WN, wn = wid % WN;
    const int arow_ld = tid >> 1, ac = (tid & 1) * 2;
    const int aoff0 = chkoff(arow_ld, ac);
    const int aoff1 = chkoff(arow_ld, ac + 1);
    const int brow_ld = (BN == 128) ? (tid >> 1) : (tid >> 2);
    const int bc = (BN == 128) ? ((tid & 1) * 2) : (tid & 3);
    const int boff0 = chkoff(brow_ld, bc);
    const int boff1 = chkoff(brow_ld, bc + 1);
    // ldmatrix lane rows
    const uint32_t sbase = (uint32_t)__cvta_generic_to_shared(smem);
    int arow_lm[MT];
#pragma unroll
    for (int mt = 0; mt < MT; mt++)
        arow_lm[mt] = wm * (MT * 16) + mt * 16 + ((lane >> 3) & 1) * 8 + (lane & 7);
    const int cA = lane >> 4;               // 0/1: chunk offset within k-pair
    int brow_lm[2];
    brow_lm[0] = wn * 32 + ((lane >> 4) & 1) * 8 + (lane & 7);
    brow_lm[1] = brow_lm[0] + 16;
    const int cB = (lane >> 3) & 1;

    auto issue = [&](int i) {
        uint32_t* As = smem + (i % 3) * STG;
        uint32_t* Bs = As + ASZ;
        const int kt = i << 5;
        cp_async16u(As + aoff0, pa + kt + ac * 8, sa);
        cp_async16u(As + aoff1, pa + kt + ac * 8 + 8, sa);
        cp_async16u(Bs + boff0, pb + kt + bc * 8, 16);
        if (BN == 128) cp_async16u(Bs + boff1, pb + kt + bc * 8 + 8, 16);
        asm volatile("cp.async.commit_group;\n" ::: "memory");
    };
    auto compute = [&](int s) {
        const uint32_t aBase = sbase + (uint32_t)(s * STG) * 4;
        const uint32_t bBase = aBase + ASZ * 4;
#pragma unroll
        for (int ks = 0; ks < 2; ks++) {
            uint32_t af[MT][4];
#pragma unroll
            for (int mt = 0; mt < MT; mt++) {
                int r = arow_lm[mt];
                int w = (r << 4) + (((2 * ks + cA) ^ ((r >> 1) & 3)) << 2);
                ldmx4(af[mt], aBase + 4 * w);
            }
            uint32_t bf[2][4];
#pragma unroll
            for (int p = 0; p < 2; p++) {
                int r = brow_lm[p];
                int w = (r << 4) + (((2 * ks + cB) ^ ((r >> 1) & 3)) << 2);
                ldmx4(bf[p], bBase + 4 * w);
            }
#pragma unroll
            for (int nt = 0; nt < 4; nt++) {
                uint32_t b0 = bf[nt >> 1][(nt & 1) * 2];
                uint32_t b1 = bf[nt >> 1][(nt & 1) * 2 + 1];
#pragma unroll
                for (int mt = 0; mt < MT; mt++) mma_h(acc[mt][nt], af[mt], b0, b1);
            }
        }
    };

    const int nk = K >> 5;
    issue(0);
    if (nk > 1) issue(1);
    for (int i = 0; i < nk; i++) {
        if (i + 1 < nk) asm volatile("cp.async.wait_group 1;\n" ::: "memory");
        else            asm volatile("cp.async.wait_group 0;\n" ::: "memory");
        __syncthreads();
        if (i + 2 < nk) issue(i + 2);
        compute(i % 3);
    }
}

// ---------------- fp32 -> fp16 convert: src + 4 attention weights ----------------
__global__ void cvt_inputs(const float* __restrict__ src,
                           const float* __restrict__ Wq, const float* __restrict__ Wk,
                           const float* __restrict__ Wv, const float* __restrict__ Wo)
{
    int i = blockIdx.x * 256 + threadIdx.x;
    if (i >= CVT_TOT) return;
    if (i < NTOK * DIM) { g_srch[i] = __float2half(src[i]); return; }
    int j = i - NTOK * DIM;
    int w = j / WELEM, k = j % WELEM;
    if (w == 0) g_Wqh[k] = __float2half(Wq[k]);
    else if (w == 1) g_Wkh[k] = __float2half(Wk[k]);
    else if (w == 2) g_Wvh[k] = __float2half(Wv[k]);
    else g_Woh[k] = __float2half(Wo[k]);
}

// ---------------- weight transpose + fp32->fp16 (W1/W2) ----------------
__global__ void transpose_cvt(const float* __restrict__ in, __half* __restrict__ out,
                              int R, int C)
{
    __shared__ float t[32][33];
    int e = blockIdx.z;
    in += (size_t)e * R * C;
    out += (size_t)e * R * C;
    int c0 = blockIdx.x * 32, r0 = blockIdx.y * 32;
    int tx = threadIdx.x, ty = threadIdx.y;
#pragma unroll
    for (int i = 0; i < 32; i += 8)
        t[ty + i][tx] = in[(size_t)(r0 + ty + i) * C + c0 + tx];
    __syncthreads();
#pragma unroll
    for (int i = 0; i < 32; i += 8)
        out[(size_t)(c0 + ty + i) * R + r0 + tx] = __float2half(t[tx][ty + i]);
}

// ---------------- fused QKV projection, fp16 (z: 0=Q,1=K,2=V-transposed) ----------------
__global__ __launch_bounds__(256, 2) void qkv_mma_h(
    const float* __restrict__ bq, const float* __restrict__ bk,
    const float* __restrict__ bv)
{
    __shared__ uint32_t smem[3 * (128 * 16 + 128 * 16)];
    const int tid = threadIdx.x;
    {   // fold zero_stats: 288 CTAs x 256 threads cover ROWS_TOT
        int gbid = (blockIdx.z * gridDim.y + blockIdx.y) * gridDim.x + blockIdx.x;
        int gidx = gbid * 256 + tid;
        if (gidx < ROWS_TOT) {
            g_rsum[gidx] = 0.f;
            g_rsumsq[gidx] = 0.f;
            g_rmaxe[gidx] = fenc(-3e38f);
            g_rmine[gidx] = fenc(3e38f);
        }
        if (gidx < NE) g_cnt[gidx] = 0;
    }
    const int lane = tid & 31, wid = tid >> 5;
    const int wm = wid / 4, wn = wid % 4;
    const int gid = lane >> 2, tig = lane & 3;
    float acc[4][4][4] = {};
    const int which = blockIdx.z;
    const __half* W = (which == 0) ? g_Wqh : (which == 1) ? g_Wkh : g_Wvh;
    const float* bias = (which == 0) ? bq : (which == 1) ? bk : bv;
    const int m0 = blockIdx.y * 128, n0 = blockIdx.x * 128;
    const __half* pa = g_srch + (size_t)(m0 + (tid >> 1)) * DIM;
    const __half* pb = W + (size_t)(n0 + (tid >> 1)) * DIM;
    mma_core_h<128>(pa, 16, pb, DIM, smem, acc);
#pragma unroll
    for (int mt = 0; mt < 4; mt++) {
#pragma unroll
        for (int nt = 0; nt < 4; nt++) {
            int row = m0 + wm * 64 + mt * 16 + gid;
            int col = n0 + wn * 32 + nt * 8 + 2 * tig;
            float c0 = acc[mt][nt][0] + bias[col];
            float c1 = acc[mt][nt][1] + bias[col + 1];
            float c2 = acc[mt][nt][2] + bias[col];
            float c3 = acc[mt][nt][3] + bias[col + 1];
            if (which == 0) {
                *(__half2*)(g_Qh + (size_t)row * DIM + col) = __floats2half2_rn(c0, c1);
                *(__half2*)(g_Qh + (size_t)(row + 8) * DIM + col) = __floats2half2_rn(c2, c3);
            } else if (which == 1) {
                *(__half2*)(g_Kh + (size_t)row * DIM + col) = __floats2half2_rn(c0, c1);
                *(__half2*)(g_Kh + (size_t)(row + 8) * DIM + col) = __floats2half2_rn(c2, c3);
            } else {
                float vals[4] = {c0, c1, c2, c3};
#pragma unroll
                for (int q = 0; q < 4; q++) {
                    int rr = row + (q >> 1) * 8;
                    int cc = col + (q & 1);
                    int bb = rr >> 10, tt = rr & 1023;
                    int h = cc >> 6, d = cc & 63;
                    g_Vth[(((size_t)bb * NH + h) * HD + d) * SEQ + tt] = __float2half(vals[q]);
                }
            }
        }
    }
}

// ---------------- O projection fp16 (BN=64) ----------------
__global__ __launch_bounds__(256, 2) void oproj_mma_h(
    const float* __restrict__ bias, float* __restrict__ C)
{
    __shared__ uint32_t smem[3 * (128 * 16 + 64 * 16)];
    const int tid = threadIdx.x;
    const int lane = tid & 31, wid = tid >> 5;
    const int wm = wid / 2, wn = wid % 2;
    const int gid = lane >> 2, tig = lane & 3;
    float acc[2][4][4] = {};
    const int m0 = blockIdx.y * 128, n0 = blockIdx.x * 64;
    const __half* pa = g_attnh + (size_t)(m0 + (tid >> 1)) * DIM;
    const __half* pb = g_Woh + (size_t)(n0 + (tid >> 2)) * DIM;
    mma_core_h<64>(pa, 16, pb, DIM, smem, acc);
#pragma unroll
    for (int mt = 0; mt < 2; mt++) {
#pragma unroll
        for (int nt = 0; nt < 4; nt++) {
            int row = m0 + wm * 32 + mt * 16 + gid;
            int col = n0 + wn * 32 + nt * 8 + 2 * tig;
            float b0 = bias[col], b1 = bias[col + 1];
            *(float2*)(C + (size_t)row * DIM + col) =
                make_float2(acc[mt][nt][0] + b0, acc[mt][nt][1] + b1);
            *(float2*)(C + (size_t)(row + 8) * DIM + col) =
                make_float2(acc[mt][nt][2] + b0, acc[mt][nt][3] + b1);
        }
    }
}

// ---------------- QK^T in fp16 + per-row stats epilogue (fp16 P store) ----------------
__global__ __launch_bounds__(256, 2) void qk_mma_h(float scale)
{
    __shared__ uint32_t smem[3 * (128 * 16 + 128 * 16)];
    const int tid = threadIdx.x;
    const int lane = tid & 31, wid = tid >> 5;
    const int wm = wid / 4, wn = wid % 4;
    const int gid = lane >> 2, tig = lane & 3;
    float acc[4][4][4] = {};
    const int z = blockIdx.z, b = z / NH, h = z % NH;
    const int m0 = blockIdx.y * 128, n0 = blockIdx.x * 128;
    const __half* pa = g_Qh + ((size_t)(b * SEQ + m0 + (tid >> 1))) * DIM + h * HD;
    const __half* pb = g_Kh + ((size_t)(b * SEQ + n0 + (tid >> 1))) * DIM + h * HD;
    __half* Cb = g_P + (size_t)z * SEQ * SEQ;
    mma_core_h<128>(pa, 16, pb, HD, smem, acc);
    const size_t rowbase = (size_t)z * SEQ + m0;
#pragma unroll
    for (int mt = 0; mt < 4; mt++) {
        float s0 = 0.f, q0 = 0.f, s8 = 0.f, q8 = 0.f;
        float mx0 = -3e38f, mn0 = 3e38f, mx8 = -3e38f, mn8 = 3e38f;
#pragma unroll
        for (int nt = 0; nt < 4; nt++) {
            int row = m0 + wm * 64 + mt * 16 + gid;
            int col = n0 + wn * 32 + nt * 8 + 2 * tig;
            float v0 = acc[mt][nt][0] * scale, v1 = acc[mt][nt][1] * scale;
            float v2 = acc[mt][nt][2] * scale, v3 = acc[mt][nt][3] * scale;
            *(__half2*)(Cb + (size_t)row * SEQ + col) = __floats2half2_rn(v0, v1);
            *(__half2*)(Cb + (size_t)(row + 8) * SEQ + col) = __floats2half2_rn(v2, v3);
            s0 += v0 + v1; q0 += v0 * v0 + v1 * v1;
            mx0 = fmaxf(mx0, fmaxf(v0, v1)); mn0 = fminf(mn0, fminf(v0, v1));
            s8 += v2 + v3; q8 += v2 * v2 + v3 * v3;
            mx8 = fmaxf(mx8, fmaxf(v2, v3)); mn8 = fminf(mn8, fminf(v2, v3));
        }
#pragma unroll
        for (int o = 1; o < 4; o <<= 1) {
            s0 += __shfl_xor_sync(~0u, s0, o); q0 += __shfl_xor_sync(~0u, q0, o);
            s8 += __shfl_xor_sync(~0u, s8, o); q8 += __shfl_xor_sync(~0u, q8, o);
            mx0 = fmaxf(mx0, __shfl_xor_sync(~0u, mx0, o));
            mn0 = fminf(mn0, __shfl_xor_sync(~0u, mn0, o));
            mx8 = fmaxf(mx8, __shfl_xor_sync(~0u, mx8, o));
            mn8 = fminf(mn8, __shfl_xor_sync(~0u, mn8, o));
        }
        if (tig == 0) {
            size_t r0 = rowbase + wm * 64 + mt * 16 + gid;
            atomicAdd(&g_rsum[r0], s0);   atomicAdd(&g_rsumsq[r0], q0);
            atomicMax(&g_rmaxe[r0], fenc(mx0)); atomicMin(&g_rmine[r0], fenc(mn0));
            atomicAdd(&g_rsum[r0 + 8], s8); atomicAdd(&g_rsumsq[r0 + 8], q8);
            atomicMax(&g_rmaxe[r0 + 8], fenc(mx8)); atomicMin(&g_rmine[r0 + 8], fenc(mn8));
        }
    }
}

// ---------------- fused zscore-softmax + P@V, all-fp16 operands (BK=32) ----------------
__global__ __launch_bounds__(256, 2) void pv2_mma(const float* __restrict__ gamma)
{
    __shared__ uint32_t Asm[2][128 * 16];
    __shared__ uint32_t Bsm[3][64 * 16];
    __shared__ float denom_s[128];
    __shared__ float2 rowc_s[128];
    const int tid = threadIdx.x;
    const int lane = tid & 31, wid = tid >> 5;
    const int wm = wid / 2, wn = wid % 2;
    const int gid = lane >> 2, tig = lane & 3;
    const int brow = tid >> 2, bc = tid & 3;
    const int boff = chkoff(brow, bc);
    const int arow = tid >> 1, acq = tid & 1;
    const int aoff0 = chkoff(arow, 2 * acq);
    const int aoff1 = chkoff(arow, 2 * acq + 1);
    float acc[2][4][4] = {};
    const int z = blockIdx.z, b = z / NH, h = z % NH;
    const int m0 = blockIdx.y * 128;
    const __half* Arow = g_P + ((size_t)z * SEQ + m0 + arow) * SEQ + 16 * acq;
    const __half* Brow = g_Vth + (size_t)z * HD * SEQ + (size_t)brow * SEQ;
    float esum = 0.f;
    constexpr int nk = SEQ / 32;  // 32
    // ldmatrix lane rows
    const uint32_t aS0 = (uint32_t)__cvta_generic_to_shared(Asm[0]);
    const uint32_t aS1 = (uint32_t)__cvta_generic_to_shared(Asm[1]);
    const uint32_t bS0 = (uint32_t)__cvta_generic_to_shared(Bsm[0]);
    int arow_lm[2];
#pragma unroll
    for (int mt = 0; mt < 2; mt++)
        arow_lm[mt] = wm * 32 + mt * 16 + ((lane >> 3) & 1) * 8 + (lane & 7);
    const int cA = lane >> 4;
    int brow_lm[2];
    brow_lm[0] = wn * 32 + ((lane >> 4) & 1) * 8 + (lane & 7);
    brow_lm[1] = brow_lm[0] + 16;
    const int cB = (lane >> 3) & 1;

    auto issueB = [&](int i) {
        cp_async16u(Bsm[i % 3] + boff, Brow + (i << 5) + bc * 8, 16);
        asm volatile("cp.async.commit_group;\n" ::: "memory");
    };
    auto compute = [&](uint32_t aBase, uint32_t bBase) {
#pragma unroll
        for (int ks = 0; ks < 2; ks++) {
            uint32_t af[2][4];
#pragma unroll
            for (int mt = 0; mt < 2; mt++) {
                int r = arow_lm[mt];
                int w = (r << 4) + (((2 * ks + cA) ^ ((r >> 1) & 3)) << 2);
                ldmx4(af[mt], aBase + 4 * w);
            }
            uint32_t bf[2][4];
#pragma unroll
            for (int p = 0; p < 2; p++) {
                int r = brow_lm[p];
                int w = (r << 4) + (((2 * ks + cB) ^ ((r >> 1) & 3)) << 2);
                ldmx4(bf[p], bBase + 4 * w);
            }
#pragma unroll
            for (int nt = 0; nt < 4; nt++) {
                uint32_t b0 = bf[nt >> 1][(nt & 1) * 2];
                uint32_t b1 = bf[nt >> 1][(nt & 1) * 2 + 1];
#pragma unroll
                for (int mt = 0; mt < 2; mt++) mma_h(acc[mt][nt], af[mt], b0, b1);
            }
        }
    };

    issueB(0);
    issueB(1);
    if (tid < 128) {
        size_t i = (size_t)z * SEQ + m0 + tid;
        float s = g_rsum[i], q = g_rsumsq[i];
        float mean = s * (1.f / SEQ);
        float var = fmaxf((q - s * s * (1.f / SEQ)) * (1.f / (SEQ - 1)), 0.f);
        float c1 = (*gamma) / (sqrtf(var) + EPSZ);
        float mx = fdec(g_rmaxe[i]), mn = fdec(g_rmine[i]);
        float zmax = fmaxf(c1 * (mx - mean), c1 * (mn - mean));
        rowc_s[tid] = make_float2(c1, -mean * c1 - zmax);
    }
    __syncthreads();
    const float2 rc = rowc_s[arow];
    uint4 a0 = *(const uint4*)(Arow);
    uint4 a1 = *(const uint4*)(Arow + 8);
    for (int i = 0; i < nk; i++) {
        if (i + 1 < nk) asm volatile("cp.async.wait_group 1;\n" ::: "memory");
        else            asm volatile("cp.async.wait_group 0;\n" ::: "memory");
        __syncthreads();
        if (i + 2 < nk) issueB(i + 2);
        uint4 o0, o1;
        {
            const uint32_t* aw = &a0.x;
            uint32_t* ow = &o0.x;
#pragma unroll
            for (int w = 0; w < 4; w++) {
                float2 f = __half22float2(*(const __half2*)&aw[w]);
                float ex = __expf(fmaf(f.x, rc.x, rc.y));
                float ey = __expf(fmaf(f.y, rc.x, rc.y));
                esum += ex + ey;
                *(__half2*)&ow[w] = __floats2half2_rn(ex, ey);
            }
            const uint32_t* aw1 = &a1.x;
            uint32_t* ow1 = &o1.x;
#pragma unroll
            for (int w = 0; w < 4; w++) {
                float2 f = __half22float2(*(const __half2*)&aw1[w]);
                float ex = __expf(fmaf(f.x, rc.x, rc.y));
                float ey = __expf(fmaf(f.y, rc.x, rc.y));
                esum += ex + ey;
                *(__half2*)&ow1[w] = __floats2half2_rn(ex, ey);
            }
        }
        *(uint4*)(Asm[i & 1] + aoff0) = o0;
        *(uint4*)(Asm[i & 1] + aoff1) = o1;
        if (i + 1 < nk) {
            a0 = *(const uint4*)(Arow + ((i + 1) << 5));
            a1 = *(const uint4*)(Arow + ((i + 1) << 5) + 8);
        }
        __syncthreads();
        compute((i & 1) ? aS1 : aS0, bS0 + (uint32_t)((i % 3) * 64 * 16) * 4);
    }
    esum += __shfl_xor_sync(~0u, esum, 1);
    if (acq == 0) denom_s[arow] = esum;
    __syncthreads();
#pragma unroll
    for (int mt = 0; mt < 2; mt++) {
#pragma unroll
        for (int nt = 0; nt < 4; nt++) {
            int ro = wm * 32 + mt * 16 + gid;
            int col = wn * 32 + nt * 8 + 2 * tig;
            float r0 = 1.f / denom_s[ro];
            float r8 = 1.f / denom_s[ro + 8];
            int row = m0 + ro;
            __half* c0 = g_attnh + ((size_t)(b * SEQ + row)) * DIM + h * HD + col;
            __half* c1 = g_attnh + ((size_t)(b * SEQ + row + 8)) * DIM + h * HD + col;
            *(__half2*)c0 = __floats2half2_rn(acc[mt][nt][0] * r0, acc[mt][nt][1] * r0);
            *(__half2*)c1 = __floats2half2_rn(acc[mt][nt][2] * r8, acc[mt][nt][3] * r8);
        }
    }
}

// ---------------- FF1 fp16: H1h = relu(xh[list] @ W1ht^T + b1) ----------------
__global__ __launch_bounds__(256, 2) void ff1_mma_h(const float* __restrict__ b1)
{
    const int e = blockIdx.z;
    const int cnt = g_cnt[e];
    const int m0 = blockIdx.y * 128;
    if (m0 >= cnt) return;
    __shared__ uint32_t smem[3 * (128 * 16 + 128 * 16)];
    const int tid = threadIdx.x;
    const int lane = tid & 31, wid = tid >> 5;
    const int wm = wid / 4, wn = wid % 4;
    const int gid = lane >> 2, tig = lane & 3;
    float acc[4][4][4] = {};
    const int n0 = blockIdx.x * 128;
    const int r = m0 + (tid >> 1);
    const __half* pa = g_xh; int sa = 0;
    if (r < cnt) { pa = g_xh + (size_t)g_list[e * NTOK + r] * DIM; sa = 16; }
    const __half* pb = g_W1ht + (size_t)e * FFD * DIM + (size_t)(n0 + (tid >> 1)) * DIM;
    const float* bb = b1 + e * FFD;
    __half* Hout = g_H1h + (size_t)e * NTOK * FFD;
    mma_core_h<128>(pa, sa, pb, DIM, smem, acc);
#pragma unroll
    for (int mt = 0; mt < 4; mt++) {
#pragma unroll
        for (int nt = 0; nt < 4; nt++) {
            int lm = m0 + wm * 64 + mt * 16 + gid;
            int col = n0 + wn * 32 + nt * 8 + 2 * tig;
            float b0 = bb[col], b1v = bb[col + 1];
            if (lm < cnt) {
                *(__half2*)(Hout + (size_t)lm * FFD + col) =
                    __floats2half2_rn(fmaxf(acc[mt][nt][0] + b0, 0.f),
                                      fmaxf(acc[mt][nt][1] + b1v, 0.f));
            }
            if (lm + 8 < cnt) {
                *(__half2*)(Hout + (size_t)(lm + 8) * FFD + col) =
                    __floats2half2_rn(fmaxf(acc[mt][nt][2] + b0, 0.f),
                                      fmaxf(acc[mt][nt][3] + b1v, 0.f));
            }
        }
    }
}

// ---------------- FF2 fp16 (BN=64): Y = H1h @ W2ht^T + b2 ----------------
__global__ __launch_bounds__(256, 2) void ff2_mma_h(const float* __restrict__ b2)
{
    const int e = blockIdx.z;
    const int cnt = g_cnt[e];
    const int m0 = blockIdx.y * 128;
    if (m0 >= cnt) return;
    __shared__ uint32_t smem[3 * (128 * 16 + 64 * 16)];
    const int tid = threadIdx.x;
    const int lane = tid & 31, wid = tid >> 5;
    const int wm = wid / 2, wn = wid % 2;
    const int gid = lane >> 2, tig = lane & 3;
    float acc[2][4][4] = {};
    const int n0 = blockIdx.x * 64;
    const __half* Ab = g_H1h + (size_t)e * NTOK * FFD;
    const int r = m0 + (tid >> 1);
    const __half* pa = Ab; int sa = 0;
    if (r < cnt) { pa = Ab + (size_t)r * FFD; sa = 16; }
    const __half* pb = g_W2ht + (size_t)e * DIM * FFD + (size_t)(n0 + (tid >> 2)) * FFD;
    const float* bb = b2 + e * DIM;
    float* Yout = g_Y + (size_t)e * NTOK * DIM;
    mma_core_h<64>(pa, sa, pb, FFD, smem, acc);
#pragma unroll
    for (int mt = 0; mt < 2; mt++) {
#pragma unroll
        for (int nt = 0; nt < 4; nt++) {
            int lm = m0 + wm * 32 + mt * 16 + gid;
            int col = n0 + wn * 32 + nt * 8 + 2 * tig;
            float b0 = bb[col], b1v = bb[col + 1];
            if (lm < cnt) {
                *(float2*)(Yout + (size_t)lm * DIM + col) =
                    make_float2(acc[mt][nt][0] + b0, acc[mt][nt][1] + b1v);
            }
            if (lm + 8 < cnt) {
                *(float2*)(Yout + (size_t)(lm + 8) * DIM + col) =
                    make_float2(acc[mt][nt][2] + b0, acc[mt][nt][3] + b1v);
            }
        }
    }
}

// ---------------- reductions ----------------
__device__ __forceinline__ float blockReduceSum(float v) {
    __shared__ float red[8];
    int lane = threadIdx.x & 31, wid = threadIdx.x >> 5;
#pragma unroll
    for (int o = 16; o > 0; o >>= 1) v += __shfl_xor_sync(0xffffffffu, v, o);
    __syncthreads();
    if (lane == 0) red[wid] = v;
    __syncthreads();
    float r = (lane < 8) ? red[lane] : 0.f;
#pragma unroll
    for (int o = 16; o > 0; o >>= 1) r += __shfl_xor_sync(0xffffffffu, r, o);
    return r;
}

// ---------------- LN1 + fused gating (also emits x fp16) ----------------
__global__ void add_ln1_gate_kernel(const float* __restrict__ a, const float* __restrict__ b,
                                    const float* __restrict__ g, const float* __restrict__ be,
                                    const float* __restrict__ Wg, const float* __restrict__ bg,
                                    float* __restrict__ out) {
    int t = blockIdx.x, tid = threadIdx.x;
    const float* ar = a + (size_t)t * DIM;
    const float* br = b + (size_t)t * DIM;
    float v[3];
#pragma unroll
    for (int i = 0; i < 3; i++) v[i] = ar[tid + i * 256] + br[tid + i * 256];
    float mean = blockReduceSum(v[0] + v[1] + v[2]) * (1.f / DIM);
    float sq = 0.f;
#pragma unroll
    for (int i = 0; i < 3; i++) { v[i] -= mean; sq += v[i] * v[i]; }
    float var = blockReduceSum(sq) * (1.f / DIM);
    float r = rsqrtf(var + EPSLN);
    float xv[3];
    float gp0 = 0.f, gp1 = 0.f, gp2 = 0.f, gp3 = 0.f;
#pragma unroll
    for (int i = 0; i < 3; i++) {
        int c = tid + i * 256;
        xv[i] = v[i] * r * g[c] + be[c];
        out[(size_t)t * DIM + c] = xv[i];
        g_xh[(size_t)t * DIM + c] = __float2half(xv[i]);
        gp0 += xv[i] * Wg[c];
        gp1 += xv[i] * Wg[DIM + c];
        gp2 += xv[i] * Wg[2 * DIM + c];
        gp3 += xv[i] * Wg[3 * DIM + c];
    }
    float s0 = blockReduceSum(gp0);
    float s1 = blockReduceSum(gp1);
    float s2 = blockReduceSum(gp2);
    float s3 = blockReduceSum(gp3);
    if (tid == 0) {
        float s[4] = {s0 + bg[0], s1 + bg[1], s2 + bg[2], s3 + bg[3]};
        float mx = fmaxf(fmaxf(s[0], s[1]), fmaxf(s[2], s[3]));
        float p[4], sum = 0.f;
#pragma unroll
        for (int e = 0; e < 4; e++) { p[e] = expf(s[e] - mx); sum += p[e]; }
        float ri = 1.f / sum;
#pragma unroll
        for (int e = 0; e < 4; e++) p[e] *= ri;
        int i1 = 0;
#pragma unroll
        for (int e = 1; e < 4; e++) if (p[e] > p[i1]) i1 = e;
        int i2 = (i1 == 0) ? 1 : 0;
#pragma unroll
        for (int e = 0; e < 4; e++) if (e != i1 && p[e] > p[i2]) i2 = e;
        int slot = atomicAdd(&g_cnt[i1], 1);
        g_list[i1 * NTOK + slot] = t;
        g_tslot[t] = i1 * NTOK + slot;
        g_tw[t] = p[i1];
        slot = atomicAdd(&g_cnt[i2], 1);
        g_list[i2 * NTOK + slot] = t;
        g_tslot[NTOK + t] = i2 * NTOK + slot;
        g_tw[NTOK + t] = p[i2];
    }
}

// ---------------- LN2 + MoE combine ----------------
__global__ void add_ln2_moe_kernel(const float* __restrict__ x,
                                   const float* __restrict__ g, const float* __restrict__ be,
                                   float* __restrict__ out) {
    int t = blockIdx.x, tid = threadIdx.x;
    int s1 = g_tslot[t], s2 = g_tslot[NTOK + t];
    float w1 = g_tw[t], w2 = g_tw[NTOK + t];
    const float* y1 = g_Y + (size_t)s1 * DIM;
    const float* y2 = g_Y + (size_t)s2 * DIM;
    const float* xr = x + (size_t)t * DIM;
    float v[3];
#pragma unroll
    for (int i = 0; i < 3; i++) {
        int c = tid + i * 256;
        v[i] = xr[c] + w1 * y1[c] + w2 * y2[c];
    }
    float mean = blockReduceSum(v[0] + v[1] + v[2]) * (1.f / DIM);
    float sq = 0.f;
#pragma unroll
    for (int i = 0; i < 3; i++) { v[i] -= mean; sq += v[i] * v[i]; }
    float var = blockReduceSum(sq) * (1.f / DIM);
    float r = rsqrtf(var + EPSLN);
#pragma unroll
    for (int i = 0; i < 3; i++) {
        int c = tid + i * 256;
        out[(size_t)t * DIM + c] = v[i] * r * g[c] + be[c];
    }
}

// ---------------- launch ----------------
extern "C" void kernel_launch(void* const* d_in, const int* in_sizes, int n_in,
                              void* d_out, int out_size) {
    const float* src  = (const float*)d_in[0];
    const float* Wq = (const float*)d_in[2];
    const float* bq = (const float*)d_in[3];
    const float* Wk = (const float*)d_in[4];
    const float* bk = (const float*)d_in[5];
    const float* Wv = (const float*)d_in[6];
    const float* bv = (const float*)d_in[7];
    const float* Wo = (const float*)d_in[8];
    const float* bo = (const float*)d_in[9];
    const float* gamma = (const float*)d_in[10];
    const float* ln1g = (const float*)d_in[11];
    const float* ln1b = (const float*)d_in[12];
    const float* ln2g = (const float*)d_in[13];
    const float* ln2b = (const float*)d_in[14];
    const float* Wg = (const float*)d_in[15];
    const float* bg = (const float*)d_in[16];
    const float* W1 = (const float*)d_in[17];
    const float* b1 = (const float*)d_in[18];
    const float* W2 = (const float*)d_in[19];
    const float* b2 = (const float*)d_in[20];
    float* out = (float*)d_out;

    float *attnop, *xp;
    __half *W1htp, *W2htp;
    cudaGetSymbolAddress((void**)&attnop, g_attno);
    cudaGetSymbolAddress((void**)&xp, g_x);
    cudaGetSymbolAddress((void**)&W1htp, g_W1ht);
    cudaGetSymbolAddress((void**)&W2htp, g_W2ht);

    // fp32->fp16 converts: src + attention weights; W1/W2 transpose+convert
    cvt_inputs<<<(CVT_TOT + 255) / 256, 256>>>(src, Wq, Wk, Wv, Wo);
    transpose_cvt<<<dim3(FFD / 32, DIM / 32, NE), dim3(32, 8)>>>(W1, W1htp, DIM, FFD);
    transpose_cvt<<<dim3(DIM / 32, FFD / 32, NE), dim3(32, 8)>>>(W2, W2htp, FFD, DIM);

    // fused QKV projections fp16 (V transposed) + stats/counter zeroing
    qkv_mma_h<<<dim3(DIM / 128, NTOK / 128, 3), 256>>>(bq, bk, bv);

    // logits = scale * Q K^T  (fp16 operands; per-row stats; fp16 P store)
    qk_mma_h<<<dim3(SEQ / 128, SEQ / 128, BHZ), 256>>>(0.125f);

    // fused zscore+softmax+PV (fp16; attn stored fp16)
    pv2_mma<<<dim3(1, SEQ / 128, BHZ), 256>>>(gamma);

    // O projection fp16 (BN=64)
    oproj_mma_h<<<dim3(DIM / 64, NTOK / 128), 256>>>(bo, attnop);

    // x = LN1(src + attn_out), fused gating + routing (+ fp16 x)
    add_ln1_gate_kernel<<<NTOK, 256>>>(src, attnop, ln1g, ln1b, Wg, bg, xp);

    // expert FFN in fp16 (sparse top-2)
    ff1_mma_h<<<dim3(FFD / 128, NTOK / 128, NE), 256>>>(b1);
    ff2_mma_h<<<dim3(DIM / 64, NTOK / 128, NE), 256>>>(b2);

    // out = LN2(x + combine(Y))
    add_ln2_moe_kernel<<<NTOK, 256>>>(xp, ln2g, ln2b, out);
}